// round 11
// baseline (speedup 1.0000x reference)
#include <cuda_runtime.h>
#include <cuda_fp16.h>

typedef unsigned long long u64;
typedef unsigned int u32;

// ===========================================================================
// PTX helpers — family-portable only (.target sm_103): mma.sync fp16 (HMMA),
// ldmatrix, cp.async. No tcgen05/TMEM (rejected by compute_103 virtual arch).
// ===========================================================================
__device__ __forceinline__ u64 ffma2(u64 a, u64 b, u64 c) {
    asm("fma.rn.f32x2 %0, %1, %2, %0;" : "+l"(c) : "l"(a), "l"(b));
    return c;
}
__device__ __forceinline__ u64 dup2(float x) {
    u64 r; unsigned xi = __float_as_uint(x);
    asm("mov.b64 %0, {%1, %1};" : "=l"(r) : "r"(xi));
    return r;
}
__device__ __forceinline__ float2 unpk(u64 v) {
    unsigned lo, hi;
    asm("mov.b64 {%0, %1}, %2;" : "=r"(lo), "=r"(hi) : "l"(v));
    return make_float2(__uint_as_float(lo), __uint_as_float(hi));
}
__device__ __forceinline__ u32 smem_u32(const void* p) {
    u32 a;
    asm("{ .reg .u64 t; cvta.to.shared.u64 t, %1; cvt.u32.u64 %0, t; }" : "=r"(a) : "l"(p));
    return a;
}
__device__ __forceinline__ void ldsm4(u32 addr, u32 r[4]) {
    asm volatile("ldmatrix.sync.aligned.m8n8.x4.shared.b16 {%0,%1,%2,%3}, [%4];"
                 : "=r"(r[0]), "=r"(r[1]), "=r"(r[2]), "=r"(r[3]) : "r"(addr));
}
__device__ __forceinline__ void mma16816h(float d[4], const u32 a[4], u32 b0, u32 b1) {
    asm volatile(
        "mma.sync.aligned.m16n8k16.row.col.f32.f16.f16.f32 "
        "{%0,%1,%2,%3}, {%4,%5,%6,%7}, {%8,%9}, {%0,%1,%2,%3};"
        : "+f"(d[0]), "+f"(d[1]), "+f"(d[2]), "+f"(d[3])
        : "r"(a[0]), "r"(a[1]), "r"(a[2]), "r"(a[3]), "r"(b0), "r"(b1));
}
#define CPASYNC(s, g) \
    asm volatile("cp.async.ca.shared.global [%0], [%1], 16;" :: "r"(s), "l"(g))
#define CPCOMMIT() asm volatile("cp.async.commit_group;" ::: "memory")
#define CPWAIT(n)  asm volatile("cp.async.wait_group %0;" :: "n"(n) : "memory")

// ===========================================================================
// Scratch (__device__ globals) — all low-precision planes are fp16
// ===========================================================================
__device__ float g_xg[268435456ULL];              // [65536][4096] fp32
__device__ float g_h [67108864ULL];               // [65536][1024] fp32 (exact h)
__device__ float g_c [131072];                    // [128][1024]
__device__ __half g_whh0_hi[4194304];             // permuted W_hh0 hi [4096][1024]
__device__ __half g_whh0_lo[4194304];
__device__ __half g_whh1_hi[4194304];
__device__ __half g_whh1_lo[4194304];
__device__ __half g_wih0_hi[4194304];             // W_ih0 [4096][64]
__device__ __half g_wih0_lo[4194304];
__device__ __half g_wih1_hi[4194304];             // W_ih1 [4096][1024]
__device__ __half g_wih1_lo[4194304];
__device__ __half g_in_hi[4194304];               // input planes [65536][64]
__device__ __half g_in_lo[4194304];
__device__ __half g_h16 [67108864ULL];            // h quantized fp16 (recurrence B)
__device__ __half g_hlo16[67108864ULL];           // h residual (for xg1 3-pass)

__device__ unsigned g_bar_count = 0;
__device__ volatile unsigned g_bar_gen = 0;

__device__ __forceinline__ void grid_barrier(int nblocks) {
    __syncthreads();
    if (threadIdx.x == 0) {
        __threadfence();
        unsigned my_gen = g_bar_gen;
        if (atomicAdd(&g_bar_count, 1) == (unsigned)(nblocks - 1)) {
            g_bar_count = 0;
            __threadfence();
            g_bar_gen = my_gen + 1;
        } else {
            while (g_bar_gen == my_gen) { }
            __threadfence();
        }
    }
    __syncthreads();
}

// ===========================================================================
// split_all: ONE prep launch.
//   blocks [0,4096)      : input split       (65536*64 elems)
//   blocks [4096,4352)   : W_ih0 split       (4096*64)
//   blocks [4352,8448)   : W_hh0 split+permute
//   blocks [8448,12544)  : W_hh1 split+permute
// ===========================================================================
__device__ __forceinline__ void plane_body(const float* __restrict__ src,
                                           __half* __restrict__ hi,
                                           __half* __restrict__ lo, size_t blk)
{
    size_t i4 = blk * 256 + threadIdx.x;
    float4 v = ((const float4*)src)[i4];
    float xs[4] = {v.x, v.y, v.z, v.w};
    __half h[4], l[4];
#pragma unroll
    for (int e = 0; e < 4; e++) {
        h[e] = __float2half_rn(xs[e]);
        l[e] = __float2half_rn(xs[e] - __half2float(h[e]));
    }
    __half2* hp = (__half2*)(hi + i4 * 4);
    __half2* lp = (__half2*)(lo + i4 * 4);
    hp[0] = __halves2half2(h[0], h[1]); hp[1] = __halves2half2(h[2], h[3]);
    lp[0] = __halves2half2(l[0], l[1]); lp[1] = __halves2half2(l[2], l[3]);
}

__device__ __forceinline__ void splitw_body(const float* __restrict__ W,
                                            __half* __restrict__ hi,
                                            __half* __restrict__ lo, int orow)
{
    int cta = orow >> 5, cc = orow & 31;
    int q = cc >> 3, r = cc & 7;
    int wrow = cta * 8 + r + q * 1024;
    float4 v = ((const float4*)(W + (size_t)wrow * 1024))[threadIdx.x];
    size_t o = (size_t)orow * 1024 + threadIdx.x * 4;
    float xs[4] = {v.x, v.y, v.z, v.w};
#pragma unroll
    for (int e = 0; e < 4; e++) {
        __half h = __float2half_rn(xs[e]);
        hi[o + e] = h;
        lo[o + e] = __float2half_rn(xs[e] - __half2float(h));
    }
}

__global__ void __launch_bounds__(256)
split_all(const float* __restrict__ input, const float* __restrict__ W_ih0,
          const float* __restrict__ W_hh0, const float* __restrict__ W_hh1,
          __half* inhi, __half* inlo, __half* wih0hi, __half* wih0lo,
          __half* whh0hi, __half* whh0lo, __half* whh1hi, __half* whh1lo)
{
    int b = blockIdx.x;
    if (b < 4096)       plane_body(input, inhi, inlo, (size_t)b);
    else if (b < 4352)  plane_body(W_ih0, wih0hi, wih0lo, (size_t)(b - 4096));
    else if (b < 8448)  splitw_body(W_hh0, whh0hi, whh0lo, b - 4352);
    else                splitw_body(W_hh1, whh1hi, whh1lo, b - 8448);
}

__global__ void __launch_bounds__(256)
split_plane_h(const float* __restrict__ src, __half* __restrict__ hi,
              __half* __restrict__ lo)
{
    plane_body(src, hi, lo, (size_t)blockIdx.x);
}

// ===========================================================================
// SIMT f32x2 GEMM (small FC only): C[M,N] = A[M,K]@W[N,K]^T + b1(+b2)
// ===========================================================================
__global__ void __launch_bounds__(256)
gemm_bias(const float* __restrict__ A, const float* __restrict__ W,
          const float* __restrict__ b1, const float* __restrict__ b2,
          float* __restrict__ C, int N, int K)
{
    __shared__ float As[16 * 128];
    __shared__ float Ws[16 * 64];

    const int tid = threadIdx.x;
    const size_t m0 = (size_t)blockIdx.y * 128;
    const int n0 = blockIdx.x * 64;
    const int tm0 = (tid >> 4) * 8;
    const int tn0 = (tid & 15) * 4;

    u64 acc[4][4];
#pragma unroll
    for (int i = 0; i < 4; i++)
#pragma unroll
        for (int j = 0; j < 4; j++) acc[i][j] = 0ULL;

    const int lm  = tid >> 2;
    const int lkq = (tid & 3) * 4;

    for (int k0 = 0; k0 < K; k0 += 16) {
#pragma unroll
        for (int p = 0; p < 2; p++) {
            int m = lm + p * 64;
            float4 v = *(const float4*)(A + (m0 + m) * (size_t)K + k0 + lkq);
            As[(lkq + 0) * 128 + m] = v.x;
            As[(lkq + 1) * 128 + m] = v.y;
            As[(lkq + 2) * 128 + m] = v.z;
            As[(lkq + 3) * 128 + m] = v.w;
        }
        {
            float4 v = *(const float4*)(W + (size_t)(n0 + lm) * K + k0 + lkq);
            Ws[(lkq + 0) * 64 + lm] = v.x;
            Ws[(lkq + 1) * 64 + lm] = v.y;
            Ws[(lkq + 2) * 64 + lm] = v.z;
            Ws[(lkq + 3) * 64 + lm] = v.w;
        }
        __syncthreads();

#pragma unroll
        for (int k = 0; k < 16; k++) {
            u64 a0 = *(const u64*)(As + k * 128 + tm0 + 0);
            u64 a1 = *(const u64*)(As + k * 128 + tm0 + 2);
            u64 a2 = *(const u64*)(As + k * 128 + tm0 + 4);
            u64 a3 = *(const u64*)(As + k * 128 + tm0 + 6);
            float4 w = *(const float4*)(Ws + k * 64 + tn0);
            u64 w0 = dup2(w.x), w1 = dup2(w.y), w2 = dup2(w.z), w3 = dup2(w.w);
            acc[0][0] = ffma2(a0, w0, acc[0][0]); acc[0][1] = ffma2(a0, w1, acc[0][1]);
            acc[0][2] = ffma2(a0, w2, acc[0][2]); acc[0][3] = ffma2(a0, w3, acc[0][3]);
            acc[1][0] = ffma2(a1, w0, acc[1][0]); acc[1][1] = ffma2(a1, w1, acc[1][1]);
            acc[1][2] = ffma2(a1, w2, acc[1][2]); acc[1][3] = ffma2(a1, w3, acc[1][3]);
            acc[2][0] = ffma2(a2, w0, acc[2][0]); acc[2][1] = ffma2(a2, w1, acc[2][1]);
            acc[2][2] = ffma2(a2, w2, acc[2][2]); acc[2][3] = ffma2(a2, w3, acc[2][3]);
            acc[3][0] = ffma2(a3, w0, acc[3][0]); acc[3][1] = ffma2(a3, w1, acc[3][1]);
            acc[3][2] = ffma2(a3, w2, acc[3][2]); acc[3][3] = ffma2(a3, w3, acc[3][3]);
        }
        __syncthreads();
    }

#pragma unroll
    for (int j = 0; j < 4; j++) {
        int col = n0 + tn0 + j;
        float bias = b1[col] + (b2 ? b2[col] : 0.0f);
#pragma unroll
        for (int i = 0; i < 4; i++) {
            float2 v = unpk(acc[i][j]);
            size_t r = m0 + tm0 + 2 * i;
            C[r * (size_t)N + col]       = v.x + bias;
            C[(r + 1) * (size_t)N + col] = v.y + bias;
        }
    }
}

// ===========================================================================
// gemm_tc: C[M,N] = A[M,K]@W[N,K]^T + b1 + b2, fp16 hi/lo 3-pass via mma.sync
// ===========================================================================
#define GT_PITCH 144
#define GT_PL    (128 * GT_PITCH)
#define GT_BUF   (4 * GT_PL)
#define GT_SMEM  (2 * GT_BUF)

__device__ __forceinline__ void gt_fill(u32 sb, const __half* Ahi,
                                        const __half* Alo,
                                        const __half* Whi,
                                        const __half* Wlo,
                                        size_t m0, int n0, int K, int k0, int tid)
{
#pragma unroll
    for (int i = 0; i < 8; i++) {
        int idx = tid + i * 256;
        int pl = idx >> 10, r2 = idx & 1023;
        int rr = r2 >> 3, ks = r2 & 7;
        const __half* src = (pl ? Alo : Ahi) + (m0 + rr) * (size_t)K + k0 + ks * 8;
        CPASYNC(sb + pl * GT_PL + rr * GT_PITCH + ks * 16, src);
    }
#pragma unroll
    for (int i = 0; i < 8; i++) {
        int idx = tid + i * 256;
        int pl = idx >> 10, r2 = idx & 1023;
        int rr = r2 >> 3, ks = r2 & 7;
        const __half* src = (pl ? Wlo : Whi) + (size_t)(n0 + rr) * K + k0 + ks * 8;
        CPASYNC(sb + 2 * GT_PL + pl * GT_PL + rr * GT_PITCH + ks * 16, src);
    }
}

__global__ void __launch_bounds__(256, 1)
gemm_tc(const __half* __restrict__ Ahi, const __half* __restrict__ Alo,
        const __half* __restrict__ Whi, const __half* __restrict__ Wlo,
        const float* __restrict__ b1, const float* __restrict__ b2,
        float* __restrict__ C, int N, int K)
{
    extern __shared__ char smem[];
    const u32 sbase = smem_u32(smem);
    const int tid = threadIdx.x;
    const int wid = tid >> 5, lane = tid & 31;
    const int wr = wid >> 2, wc = wid & 3;
    const size_t m0 = (size_t)blockIdx.y * 128;
    const int n0 = blockIdx.x * 128;
    const int NC = K / 64;

    float acc[4][4][4];
#pragma unroll
    for (int a = 0; a < 4; a++)
#pragma unroll
        for (int b = 0; b < 4; b++)
#pragma unroll
            for (int e = 0; e < 4; e++) acc[a][b][e] = 0.0f;

    const u32 a_r  = (u32)(lane & 15);
    const u32 a_c8 = (u32)((lane >> 4) << 3);
    const u32 b_r  = (u32)(((lane >> 4) << 3) + (lane & 7));
    const u32 b_c8 = (u32)(((lane >> 3) & 1) << 3);

    gt_fill(sbase, Ahi, Alo, Whi, Wlo, m0, n0, K, 0, tid);
    CPCOMMIT();

    for (int c = 0; c < NC; c++) {
        if (c + 1 < NC) {
            gt_fill(sbase + ((c + 1) & 1) * GT_BUF, Ahi, Alo, Whi, Wlo,
                    m0, n0, K, (c + 1) * 64, tid);
            CPCOMMIT();
            CPWAIT(1);
        } else {
            CPWAIT(0);
        }
        __syncthreads();

        const u32 ab = sbase + (c & 1) * GT_BUF;
#pragma unroll
        for (int kk = 0; kk < 4; kk++) {
            const u32 kc = (u32)(kk * 16);
            u32 baddr = ab + 2 * GT_PL + (wc * 32 + b_r) * GT_PITCH + (kc + b_c8) * 2;
            u32 bh0[4], bh1[4], bl0[4], bl1[4];
            ldsm4(baddr, bh0);
            ldsm4(baddr + 16 * GT_PITCH, bh1);
            ldsm4(baddr + GT_PL, bl0);
            ldsm4(baddr + GT_PL + 16 * GT_PITCH, bl1);
#pragma unroll
            for (int mb = 0; mb < 4; mb++) {
                u32 aaddr = ab + (wr * 64 + mb * 16 + a_r) * GT_PITCH + (kc + a_c8) * 2;
                u32 ah[4], al[4];
                ldsm4(aaddr, ah);
                ldsm4(aaddr + GT_PL, al);
                mma16816h(acc[mb][0], ah, bh0[0], bh0[1]);
                mma16816h(acc[mb][1], ah, bh0[2], bh0[3]);
                mma16816h(acc[mb][2], ah, bh1[0], bh1[1]);
                mma16816h(acc[mb][3], ah, bh1[2], bh1[3]);
                mma16816h(acc[mb][0], ah, bl0[0], bl0[1]);
                mma16816h(acc[mb][1], ah, bl0[2], bl0[3]);
                mma16816h(acc[mb][2], ah, bl1[0], bl1[1]);
                mma16816h(acc[mb][3], ah, bl1[2], bl1[3]);
                mma16816h(acc[mb][0], al, bh0[0], bh0[1]);
                mma16816h(acc[mb][1], al, bh0[2], bh0[3]);
                mma16816h(acc[mb][2], al, bh1[0], bh1[1]);
                mma16816h(acc[mb][3], al, bh1[2], bh1[3]);
            }
        }
        __syncthreads();
    }

#pragma unroll
    for (int nb = 0; nb < 4; nb++) {
        int col = n0 + wc * 32 + nb * 8 + (lane & 3) * 2;
        float bs0 = b1[col]     + b2[col];
        float bs1 = b1[col + 1] + b2[col + 1];
#pragma unroll
        for (int mb = 0; mb < 4; mb++) {
            size_t row = m0 + wr * 64 + mb * 16 + (lane >> 2);
            float2 v0 = make_float2(acc[mb][nb][0] + bs0, acc[mb][nb][1] + bs1);
            float2 v1 = make_float2(acc[mb][nb][2] + bs0, acc[mb][nb][3] + bs1);
            *(float2*)(C + row * (size_t)N + col)       = v0;
            *(float2*)(C + (row + 8) * (size_t)N + col) = v1;
        }
    }
}

// ===========================================================================
// Persistent recurrence — 2-pass fp16, BATCH-SPLIT for 2 CTAs/SM:
// grid 256 = (m 0..127 unit groups) x (bh 0..1 batch halves).
// CTA: M=32 permuted gate rows, N=64 batch, K=1024 in 16 chunks of 64.
// 8 warps = 2 (M) x 4 (N=16 each). smem 44.5KB -> 2 resident CTAs/SM.
// ===========================================================================
#define LS_PITCH 144
#define LS_APL   (32 * LS_PITCH)              // 4608
#define LS_BPL   (64 * LS_PITCH)              // 9216
#define LS_BUF   (2 * LS_APL + LS_BPL)        // 18432
#define LS_GS    (2 * LS_BUF)                 // 36864
#define GS_PITCH 68
#define LS_SMEM  (LS_GS + 32 * GS_PITCH * 4)  // 45568
#define LSTM_NBLK 256

__device__ __forceinline__ void ls_fill(u32 sb, const __half* Whi,
                                        const __half* Wlo,
                                        const __half* h16,
                                        int m, int bh, int tp, int k0, int tid)
{
#pragma unroll
    for (int i = 0; i < 2; i++) {        // A (Wperm slice): 2 planes x 32 x 8
        int idx = tid + i * 256;
        int pl = idx >> 8, r2 = idx & 255;
        int rr = r2 >> 3, ks = r2 & 7;
        const __half* src = (pl ? Wlo : Whi) +
            (size_t)(m * 32 + rr) * 1024 + k0 + ks * 8;
        CPASYNC(sb + pl * LS_APL + rr * LS_PITCH + ks * 16, src);
    }
#pragma unroll
    for (int i = 0; i < 2; i++) {        // B (h16): 64 batch x 8 segs
        int idx = tid + i * 256;
        int rb = idx >> 3, ks = idx & 7;
        const __half* src = h16 +
            ((size_t)(bh * 64 + rb) * 512 + tp) * 1024 + k0 + ks * 8;
        CPASYNC(sb + 2 * LS_APL + rb * LS_PITCH + ks * 16, src);
    }
}

__global__ void __launch_bounds__(256, 2)
lstm_mma(const float* __restrict__ xg,          // [65536][4096]
         float* __restrict__ hseq,              // [65536][1024] fp32 exact
         float* __restrict__ cst,               // [128][1024]
         const __half* __restrict__ Whi,        // permuted [4096][1024]
         const __half* __restrict__ Wlo,
         __half* __restrict__ h16,              // [65536][1024]
         __half* __restrict__ hlo16)            // residual (for xg1)
{
    extern __shared__ char smem[];
    const u32 sbase = smem_u32(smem);
    float* Gs = (float*)(smem + LS_GS);
    const int tid = threadIdx.x;
    const int lane = tid & 31;
    const int wid = tid >> 5;
    const int wr = wid >> 2, wc = wid & 3;   // M half / N quarter(16)
    const int m  = blockIdx.x >> 1;          // unit group 0..127
    const int bh = blockIdx.x & 1;           // batch half
    const int j0 = m * 8;

    const u32 a_r  = (u32)(lane & 15);
    const u32 a_c8 = (u32)((lane >> 4) << 3);
    const u32 b_r  = (u32)(((lane >> 4) << 3) + (lane & 7));
    const u32 b_c8 = (u32)(((lane >> 3) & 1) << 3);

    const int bl = tid >> 2;             // gate-pass local batch 0..63
    const int up = tid & 3;              // unit pair (2 units)

    for (int t = 0; t < 512; t++) {
        if (t > 0) {
            float acc[2][4];
#pragma unroll
            for (int b = 0; b < 2; b++)
#pragma unroll
                for (int e = 0; e < 4; e++) acc[b][e] = 0.0f;

            ls_fill(sbase, Whi, Wlo, h16, m, bh, t - 1, 0, tid);
            CPCOMMIT();

            for (int c = 0; c < 16; c++) {
                if (c < 15) {
                    ls_fill(sbase + ((c + 1) & 1) * LS_BUF, Whi, Wlo, h16,
                            m, bh, t - 1, (c + 1) * 64, tid);
                    CPCOMMIT();
                    CPWAIT(1);
                } else {
                    CPWAIT(0);
                }
                __syncthreads();

                const u32 ab = sbase + (c & 1) * LS_BUF;
#pragma unroll
                for (int kk = 0; kk < 4; kk++) {
                    const u32 kc = (u32)(kk * 16);
                    u32 aaddr = ab + (wr * 16 + a_r) * LS_PITCH + (kc + a_c8) * 2;
                    u32 ah[4], al[4];
                    ldsm4(aaddr, ah);
                    ldsm4(aaddr + LS_APL, al);
                    u32 baddr = ab + 2 * LS_APL + (wc * 16 + b_r) * LS_PITCH + (kc + b_c8) * 2;
                    u32 bh0[4];
                    ldsm4(baddr, bh0);
                    mma16816h(acc[0], ah, bh0[0], bh0[1]);
                    mma16816h(acc[1], ah, bh0[2], bh0[3]);
                    mma16816h(acc[0], al, bh0[0], bh0[1]);
                    mma16816h(acc[1], al, bh0[2], bh0[3]);
                }
                __syncthreads();
            }

            // spill accum to Gs[32 gate rows][64 batch] (pitch 68)
#pragma unroll
            for (int nb = 0; nb < 2; nb++) {
                int n = wc * 16 + nb * 8 + (lane & 3) * 2;
                int mm = wr * 16 + (lane >> 2);
                Gs[mm * GS_PITCH + n]           = acc[nb][0];
                Gs[mm * GS_PITCH + n + 1]       = acc[nb][1];
                Gs[(mm + 8) * GS_PITCH + n]     = acc[nb][2];
                Gs[(mm + 8) * GS_PITCH + n + 1] = acc[nb][3];
            }
            __syncthreads();
        }

        // fused gate pass: thread = (local batch bl, unit pair up)
        {
            int b = bh * 64 + bl;
            size_t row = (size_t)b * 512 + t;
            const float* xr = xg + row * 4096 + j0 + up * 2;
            float2 xi = *(const float2*)(xr);
            float2 xf = *(const float2*)(xr + 1024);
            float2 xq = *(const float2*)(xr + 2048);
            float2 xo = *(const float2*)(xr + 3072);
            float xia[2] = {xi.x, xi.y};
            float xfa[2] = {xf.x, xf.y};
            float xqa[2] = {xq.x, xq.y};
            float xoa[2] = {xo.x, xo.y};
            float cpa[2] = {0.f, 0.f};
            float ria[2] = {0.f, 0.f}, rfa[2] = {0.f, 0.f};
            float rqa[2] = {0.f, 0.f}, roa[2] = {0.f, 0.f};
            if (t > 0) {
                float2 cv = *(const float2*)(cst + b * 1024 + j0 + up * 2);
                cpa[0] = cv.x; cpa[1] = cv.y;
#pragma unroll
                for (int r = 0; r < 2; r++) {
                    int u = up * 2 + r;
                    ria[r] = Gs[(0  + u) * GS_PITCH + bl];
                    rfa[r] = Gs[(8  + u) * GS_PITCH + bl];
                    rqa[r] = Gs[(16 + u) * GS_PITCH + bl];
                    roa[r] = Gs[(24 + u) * GS_PITCH + bl];
                }
            }
            float hva[2], cna[2];
#pragma unroll
            for (int r = 0; r < 2; r++) {
                float ig = 1.0f / (1.0f + expf(-(ria[r] + xia[r])));
                float fg = 1.0f / (1.0f + expf(-(rfa[r] + xfa[r])));
                float gv = tanhf(rqa[r] + xqa[r]);
                float og = 1.0f / (1.0f + expf(-(roa[r] + xoa[r])));
                cna[r] = fg * cpa[r] + ig * gv;
                hva[r] = og * tanhf(cna[r]);
            }
            *(float2*)(cst + b * 1024 + j0 + up * 2) = make_float2(cna[0], cna[1]);
            *(float2*)(hseq + row * 1024 + j0 + up * 2) = make_float2(hva[0], hva[1]);
            __half hb0 = __float2half_rn(hva[0]);
            __half hb1 = __float2half_rn(hva[1]);
            *(__half2*)(h16 + row * 1024 + j0 + up * 2) = __halves2half2(hb0, hb1);
            *(__half2*)(hlo16 + row * 1024 + j0 + up * 2) = __halves2half2(
                __float2half_rn(hva[0] - __half2float(hb0)),
                __float2half_rn(hva[1] - __half2float(hb1)));
        }

        grid_barrier(LSTM_NBLK);
    }
}

// ===========================================================================
// Launch sequence (7 launches), graph-capturable, allocation-free.
// ===========================================================================
extern "C" void kernel_launch(void* const* d_in, const int* in_sizes, int n_in,
                              void* d_out, int out_size)
{
    const float* input = (const float*)d_in[0];
    const float* W_ih0 = (const float*)d_in[1];
    const float* W_hh0 = (const float*)d_in[2];
    const float* b_ih0 = (const float*)d_in[3];
    const float* b_hh0 = (const float*)d_in[4];
    const float* W_ih1 = (const float*)d_in[5];
    const float* W_hh1 = (const float*)d_in[6];
    const float* b_ih1 = (const float*)d_in[7];
    const float* b_hh1 = (const float*)d_in[8];
    const float* W_fc  = (const float*)d_in[9];
    const float* b_fc  = (const float*)d_in[10];
    float* out = (float*)d_out;

    float *xg, *h, *c;
    __half *whh0hi, *whh0lo, *whh1hi, *whh1lo;
    __half *wih0hi, *wih0lo, *wih1hi, *wih1lo, *inhi, *inlo, *h16, *hlo16;
    cudaGetSymbolAddress((void**)&xg,     g_xg);
    cudaGetSymbolAddress((void**)&h,      g_h);
    cudaGetSymbolAddress((void**)&c,      g_c);
    cudaGetSymbolAddress((void**)&whh0hi, g_whh0_hi);
    cudaGetSymbolAddress((void**)&whh0lo, g_whh0_lo);
    cudaGetSymbolAddress((void**)&whh1hi, g_whh1_hi);
    cudaGetSymbolAddress((void**)&whh1lo, g_whh1_lo);
    cudaGetSymbolAddress((void**)&wih0hi, g_wih0_hi);
    cudaGetSymbolAddress((void**)&wih0lo, g_wih0_lo);
    cudaGetSymbolAddress((void**)&wih1hi, g_wih1_hi);
    cudaGetSymbolAddress((void**)&wih1lo, g_wih1_lo);
    cudaGetSymbolAddress((void**)&inhi,   g_in_hi);
    cudaGetSymbolAddress((void**)&inlo,   g_in_lo);
    cudaGetSymbolAddress((void**)&h16,    g_h16);
    cudaGetSymbolAddress((void**)&hlo16,  g_hlo16);

    cudaFuncSetAttribute(gemm_tc,  cudaFuncAttributeMaxDynamicSharedMemorySize, GT_SMEM);
    cudaFuncSetAttribute(lstm_mma, cudaFuncAttributeMaxDynamicSharedMemorySize, LS_SMEM);

    // #1: all prep splits fused
    split_all<<<12544, 256>>>(input, W_ih0, W_hh0, W_hh1,
                              inhi, inlo, wih0hi, wih0lo,
                              whh0hi, whh0lo, whh1hi, whh1lo);
    // #2: xg0 = x @ W_ih0^T + biases (K=64)
    {
        dim3 g(4096 / 128, 65536 / 128);
        gemm_tc<<<g, 256, GT_SMEM>>>(inhi, inlo, wih0hi, wih0lo,
                                     b_ih0, b_hh0, xg, 4096, 64);
    }
    // #3: W_ih1 split
    split_plane_h<<<4096, 256>>>(W_ih1, wih1hi, wih1lo);
    // #4: layer-0 recurrence (absolute launch #6 -> ncu window)
    lstm_mma<<<LSTM_NBLK, 256, LS_SMEM>>>(xg, h, c, whh0hi, whh0lo, h16, hlo16);
    // #5: xg1 = h1 @ W_ih1^T + biases (K=1024, 3-pass fp16)
    {
        dim3 g(4096 / 128, 65536 / 128);
        gemm_tc<<<g, 256, GT_SMEM>>>(h16, hlo16, wih1hi, wih1lo,
                                     b_ih1, b_hh1, xg, 4096, 1024);
    }
    // #6: layer-1 recurrence
    lstm_mma<<<LSTM_NBLK, 256, LS_SMEM>>>(xg, h, c, whh1hi, whh1lo, h16, hlo16);
    // #7: FC
    dim3 gf(1, 512);
    gemm_bias<<<gf, 256>>>(h, W_fc, b_fc, nullptr, out, 64, 1024);
}

// round 12
// speedup vs baseline: 1.1212x; 1.1212x over previous
#include <cuda_runtime.h>
#include <cuda_fp16.h>

typedef unsigned long long u64;
typedef unsigned int u32;

// ===========================================================================
// PTX helpers — family-portable only (.target sm_103): mma.sync fp16 (HMMA),
// ldmatrix, cp.async. No tcgen05/TMEM (rejected by compute_103 virtual arch).
// ===========================================================================
__device__ __forceinline__ u64 ffma2(u64 a, u64 b, u64 c) {
    asm("fma.rn.f32x2 %0, %1, %2, %0;" : "+l"(c) : "l"(a), "l"(b));
    return c;
}
__device__ __forceinline__ u64 dup2(float x) {
    u64 r; unsigned xi = __float_as_uint(x);
    asm("mov.b64 %0, {%1, %1};" : "=l"(r) : "r"(xi));
    return r;
}
__device__ __forceinline__ float2 unpk(u64 v) {
    unsigned lo, hi;
    asm("mov.b64 {%0, %1}, %2;" : "=r"(lo), "=r"(hi) : "l"(v));
    return make_float2(__uint_as_float(lo), __uint_as_float(hi));
}
__device__ __forceinline__ u32 smem_u32(const void* p) {
    u32 a;
    asm("{ .reg .u64 t; cvta.to.shared.u64 t, %1; cvt.u32.u64 %0, t; }" : "=r"(a) : "l"(p));
    return a;
}
__device__ __forceinline__ void ldsm4(u32 addr, u32 r[4]) {
    asm volatile("ldmatrix.sync.aligned.m8n8.x4.shared.b16 {%0,%1,%2,%3}, [%4];"
                 : "=r"(r[0]), "=r"(r[1]), "=r"(r[2]), "=r"(r[3]) : "r"(addr));
}
__device__ __forceinline__ void mma16816h(float d[4], const u32 a[4], u32 b0, u32 b1) {
    asm volatile(
        "mma.sync.aligned.m16n8k16.row.col.f32.f16.f16.f32 "
        "{%0,%1,%2,%3}, {%4,%5,%6,%7}, {%8,%9}, {%0,%1,%2,%3};"
        : "+f"(d[0]), "+f"(d[1]), "+f"(d[2]), "+f"(d[3])
        : "r"(a[0]), "r"(a[1]), "r"(a[2]), "r"(a[3]), "r"(b0), "r"(b1));
}
#define CPASYNC(s, g) \
    asm volatile("cp.async.ca.shared.global [%0], [%1], 16;" :: "r"(s), "l"(g))
#define CPCOMMIT() asm volatile("cp.async.commit_group;" ::: "memory")
#define CPWAIT(n)  asm volatile("cp.async.wait_group %0;" :: "n"(n) : "memory")

// ===========================================================================
// Scratch (__device__ globals) — all low-precision planes are fp16
// ===========================================================================
__device__ float g_xg[268435456ULL];              // [65536][4096] fp32
__device__ float g_h [67108864ULL];               // [65536][1024] fp32 (exact h)
__device__ float g_c [131072];                    // [128][1024]
__device__ __half g_whh0_hi[4194304];             // permuted W_hh0 hi [4096][1024]
__device__ __half g_whh0_lo[4194304];
__device__ __half g_whh1_hi[4194304];
__device__ __half g_whh1_lo[4194304];
__device__ __half g_wih0_hi[4194304];             // W_ih0 [4096][64]
__device__ __half g_wih0_lo[4194304];
__device__ __half g_wih1_hi[4194304];             // W_ih1 [4096][1024]
__device__ __half g_wih1_lo[4194304];
__device__ __half g_in_hi[4194304];               // input planes [65536][64]
__device__ __half g_in_lo[4194304];
__device__ __half g_h16 [67108864ULL];            // h quantized fp16 (recurrence B)
__device__ __half g_hlo16[67108864ULL];           // h residual (for xg1 3-pass)

__device__ unsigned g_bar_count = 0;
__device__ volatile unsigned g_bar_gen = 0;

__device__ __forceinline__ void grid_barrier(int nblocks) {
    __syncthreads();
    if (threadIdx.x == 0) {
        __threadfence();
        unsigned my_gen = g_bar_gen;
        if (atomicAdd(&g_bar_count, 1) == (unsigned)(nblocks - 1)) {
            g_bar_count = 0;
            __threadfence();
            g_bar_gen = my_gen + 1;
        } else {
            while (g_bar_gen == my_gen) { }
            __threadfence();
        }
    }
    __syncthreads();
}

// ===========================================================================
// split_all: ONE prep launch.
//   blocks [0,4096)      : input split       (65536*64 elems)
//   blocks [4096,4352)   : W_ih0 split       (4096*64)
//   blocks [4352,8448)   : W_hh0 split+permute
//   blocks [8448,12544)  : W_hh1 split+permute
// ===========================================================================
__device__ __forceinline__ void plane_body(const float* __restrict__ src,
                                           __half* __restrict__ hi,
                                           __half* __restrict__ lo, size_t blk)
{
    size_t i4 = blk * 256 + threadIdx.x;
    float4 v = ((const float4*)src)[i4];
    float xs[4] = {v.x, v.y, v.z, v.w};
    __half h[4], l[4];
#pragma unroll
    for (int e = 0; e < 4; e++) {
        h[e] = __float2half_rn(xs[e]);
        l[e] = __float2half_rn(xs[e] - __half2float(h[e]));
    }
    __half2* hp = (__half2*)(hi + i4 * 4);
    __half2* lp = (__half2*)(lo + i4 * 4);
    hp[0] = __halves2half2(h[0], h[1]); hp[1] = __halves2half2(h[2], h[3]);
    lp[0] = __halves2half2(l[0], l[1]); lp[1] = __halves2half2(l[2], l[3]);
}

__device__ __forceinline__ void splitw_body(const float* __restrict__ W,
                                            __half* __restrict__ hi,
                                            __half* __restrict__ lo, int orow)
{
    int cta = orow >> 5, cc = orow & 31;
    int q = cc >> 3, r = cc & 7;
    int wrow = cta * 8 + r + q * 1024;
    float4 v = ((const float4*)(W + (size_t)wrow * 1024))[threadIdx.x];
    size_t o = (size_t)orow * 1024 + threadIdx.x * 4;
    float xs[4] = {v.x, v.y, v.z, v.w};
#pragma unroll
    for (int e = 0; e < 4; e++) {
        __half h = __float2half_rn(xs[e]);
        hi[o + e] = h;
        lo[o + e] = __float2half_rn(xs[e] - __half2float(h));
    }
}

__global__ void __launch_bounds__(256)
split_all(const float* __restrict__ input, const float* __restrict__ W_ih0,
          const float* __restrict__ W_hh0, const float* __restrict__ W_hh1,
          __half* inhi, __half* inlo, __half* wih0hi, __half* wih0lo,
          __half* whh0hi, __half* whh0lo, __half* whh1hi, __half* whh1lo)
{
    int b = blockIdx.x;
    if (b < 4096)       plane_body(input, inhi, inlo, (size_t)b);
    else if (b < 4352)  plane_body(W_ih0, wih0hi, wih0lo, (size_t)(b - 4096));
    else if (b < 8448)  splitw_body(W_hh0, whh0hi, whh0lo, b - 4352);
    else                splitw_body(W_hh1, whh1hi, whh1lo, b - 8448);
}

__global__ void __launch_bounds__(256)
split_plane_h(const float* __restrict__ src, __half* __restrict__ hi,
              __half* __restrict__ lo)
{
    plane_body(src, hi, lo, (size_t)blockIdx.x);
}

// ===========================================================================
// SIMT f32x2 GEMM (small FC only): C[M,N] = A[M,K]@W[N,K]^T + b1(+b2)
// ===========================================================================
__global__ void __launch_bounds__(256)
gemm_bias(const float* __restrict__ A, const float* __restrict__ W,
          const float* __restrict__ b1, const float* __restrict__ b2,
          float* __restrict__ C, int N, int K)
{
    __shared__ float As[16 * 128];
    __shared__ float Ws[16 * 64];

    const int tid = threadIdx.x;
    const size_t m0 = (size_t)blockIdx.y * 128;
    const int n0 = blockIdx.x * 64;
    const int tm0 = (tid >> 4) * 8;
    const int tn0 = (tid & 15) * 4;

    u64 acc[4][4];
#pragma unroll
    for (int i = 0; i < 4; i++)
#pragma unroll
        for (int j = 0; j < 4; j++) acc[i][j] = 0ULL;

    const int lm  = tid >> 2;
    const int lkq = (tid & 3) * 4;

    for (int k0 = 0; k0 < K; k0 += 16) {
#pragma unroll
        for (int p = 0; p < 2; p++) {
            int m = lm + p * 64;
            float4 v = *(const float4*)(A + (m0 + m) * (size_t)K + k0 + lkq);
            As[(lkq + 0) * 128 + m] = v.x;
            As[(lkq + 1) * 128 + m] = v.y;
            As[(lkq + 2) * 128 + m] = v.z;
            As[(lkq + 3) * 128 + m] = v.w;
        }
        {
            float4 v = *(const float4*)(W + (size_t)(n0 + lm) * K + k0 + lkq);
            Ws[(lkq + 0) * 64 + lm] = v.x;
            Ws[(lkq + 1) * 64 + lm] = v.y;
            Ws[(lkq + 2) * 64 + lm] = v.z;
            Ws[(lkq + 3) * 64 + lm] = v.w;
        }
        __syncthreads();

#pragma unroll
        for (int k = 0; k < 16; k++) {
            u64 a0 = *(const u64*)(As + k * 128 + tm0 + 0);
            u64 a1 = *(const u64*)(As + k * 128 + tm0 + 2);
            u64 a2 = *(const u64*)(As + k * 128 + tm0 + 4);
            u64 a3 = *(const u64*)(As + k * 128 + tm0 + 6);
            float4 w = *(const float4*)(Ws + k * 64 + tn0);
            u64 w0 = dup2(w.x), w1 = dup2(w.y), w2 = dup2(w.z), w3 = dup2(w.w);
            acc[0][0] = ffma2(a0, w0, acc[0][0]); acc[0][1] = ffma2(a0, w1, acc[0][1]);
            acc[0][2] = ffma2(a0, w2, acc[0][2]); acc[0][3] = ffma2(a0, w3, acc[0][3]);
            acc[1][0] = ffma2(a1, w0, acc[1][0]); acc[1][1] = ffma2(a1, w1, acc[1][1]);
            acc[1][2] = ffma2(a1, w2, acc[1][2]); acc[1][3] = ffma2(a1, w3, acc[1][3]);
            acc[2][0] = ffma2(a2, w0, acc[2][0]); acc[2][1] = ffma2(a2, w1, acc[2][1]);
            acc[2][2] = ffma2(a2, w2, acc[2][2]); acc[2][3] = ffma2(a2, w3, acc[2][3]);
            acc[3][0] = ffma2(a3, w0, acc[3][0]); acc[3][1] = ffma2(a3, w1, acc[3][1]);
            acc[3][2] = ffma2(a3, w2, acc[3][2]); acc[3][3] = ffma2(a3, w3, acc[3][3]);
        }
        __syncthreads();
    }

#pragma unroll
    for (int j = 0; j < 4; j++) {
        int col = n0 + tn0 + j;
        float bias = b1[col] + (b2 ? b2[col] : 0.0f);
#pragma unroll
        for (int i = 0; i < 4; i++) {
            float2 v = unpk(acc[i][j]);
            size_t r = m0 + tm0 + 2 * i;
            C[r * (size_t)N + col]       = v.x + bias;
            C[(r + 1) * (size_t)N + col] = v.y + bias;
        }
    }
}

// ===========================================================================
// gemm_tc: C[M,N] = A[M,K]@W[N,K]^T + b1 + b2, fp16 hi/lo 3-pass via mma.sync
// ===========================================================================
#define GT_PITCH 144
#define GT_PL    (128 * GT_PITCH)
#define GT_BUF   (4 * GT_PL)
#define GT_SMEM  (2 * GT_BUF)

__device__ __forceinline__ void gt_fill(u32 sb, const __half* Ahi,
                                        const __half* Alo,
                                        const __half* Whi,
                                        const __half* Wlo,
                                        size_t m0, int n0, int K, int k0, int tid)
{
#pragma unroll
    for (int i = 0; i < 8; i++) {
        int idx = tid + i * 256;
        int pl = idx >> 10, r2 = idx & 1023;
        int rr = r2 >> 3, ks = r2 & 7;
        const __half* src = (pl ? Alo : Ahi) + (m0 + rr) * (size_t)K + k0 + ks * 8;
        CPASYNC(sb + pl * GT_PL + rr * GT_PITCH + ks * 16, src);
    }
#pragma unroll
    for (int i = 0; i < 8; i++) {
        int idx = tid + i * 256;
        int pl = idx >> 10, r2 = idx & 1023;
        int rr = r2 >> 3, ks = r2 & 7;
        const __half* src = (pl ? Wlo : Whi) + (size_t)(n0 + rr) * K + k0 + ks * 8;
        CPASYNC(sb + 2 * GT_PL + pl * GT_PL + rr * GT_PITCH + ks * 16, src);
    }
}

__global__ void __launch_bounds__(256, 1)
gemm_tc(const __half* __restrict__ Ahi, const __half* __restrict__ Alo,
        const __half* __restrict__ Whi, const __half* __restrict__ Wlo,
        const float* __restrict__ b1, const float* __restrict__ b2,
        float* __restrict__ C, int N, int K)
{
    extern __shared__ char smem[];
    const u32 sbase = smem_u32(smem);
    const int tid = threadIdx.x;
    const int wid = tid >> 5, lane = tid & 31;
    const int wr = wid >> 2, wc = wid & 3;
    const size_t m0 = (size_t)blockIdx.y * 128;
    const int n0 = blockIdx.x * 128;
    const int NC = K / 64;

    float acc[4][4][4];
#pragma unroll
    for (int a = 0; a < 4; a++)
#pragma unroll
        for (int b = 0; b < 4; b++)
#pragma unroll
            for (int e = 0; e < 4; e++) acc[a][b][e] = 0.0f;

    const u32 a_r  = (u32)(lane & 15);
    const u32 a_c8 = (u32)((lane >> 4) << 3);
    const u32 b_r  = (u32)(((lane >> 4) << 3) + (lane & 7));
    const u32 b_c8 = (u32)(((lane >> 3) & 1) << 3);

    gt_fill(sbase, Ahi, Alo, Whi, Wlo, m0, n0, K, 0, tid);
    CPCOMMIT();

    for (int c = 0; c < NC; c++) {
        if (c + 1 < NC) {
            gt_fill(sbase + ((c + 1) & 1) * GT_BUF, Ahi, Alo, Whi, Wlo,
                    m0, n0, K, (c + 1) * 64, tid);
            CPCOMMIT();
            CPWAIT(1);
        } else {
            CPWAIT(0);
        }
        __syncthreads();

        const u32 ab = sbase + (c & 1) * GT_BUF;
#pragma unroll
        for (int kk = 0; kk < 4; kk++) {
            const u32 kc = (u32)(kk * 16);
            u32 baddr = ab + 2 * GT_PL + (wc * 32 + b_r) * GT_PITCH + (kc + b_c8) * 2;
            u32 bh0[4], bh1[4], bl0[4], bl1[4];
            ldsm4(baddr, bh0);
            ldsm4(baddr + 16 * GT_PITCH, bh1);
            ldsm4(baddr + GT_PL, bl0);
            ldsm4(baddr + GT_PL + 16 * GT_PITCH, bl1);
#pragma unroll
            for (int mb = 0; mb < 4; mb++) {
                u32 aaddr = ab + (wr * 64 + mb * 16 + a_r) * GT_PITCH + (kc + a_c8) * 2;
                u32 ah[4], al[4];
                ldsm4(aaddr, ah);
                ldsm4(aaddr + GT_PL, al);
                mma16816h(acc[mb][0], ah, bh0[0], bh0[1]);
                mma16816h(acc[mb][1], ah, bh0[2], bh0[3]);
                mma16816h(acc[mb][2], ah, bh1[0], bh1[1]);
                mma16816h(acc[mb][3], ah, bh1[2], bh1[3]);
                mma16816h(acc[mb][0], ah, bl0[0], bl0[1]);
                mma16816h(acc[mb][1], ah, bl0[2], bl0[3]);
                mma16816h(acc[mb][2], ah, bl1[0], bl1[1]);
                mma16816h(acc[mb][3], ah, bl1[2], bl1[3]);
                mma16816h(acc[mb][0], al, bh0[0], bh0[1]);
                mma16816h(acc[mb][1], al, bh0[2], bh0[3]);
                mma16816h(acc[mb][2], al, bh1[0], bh1[1]);
                mma16816h(acc[mb][3], al, bh1[2], bh1[3]);
            }
        }
        __syncthreads();
    }

#pragma unroll
    for (int nb = 0; nb < 4; nb++) {
        int col = n0 + wc * 32 + nb * 8 + (lane & 3) * 2;
        float bs0 = b1[col]     + b2[col];
        float bs1 = b1[col + 1] + b2[col + 1];
#pragma unroll
        for (int mb = 0; mb < 4; mb++) {
            size_t row = m0 + wr * 64 + mb * 16 + (lane >> 2);
            float2 v0 = make_float2(acc[mb][nb][0] + bs0, acc[mb][nb][1] + bs1);
            float2 v1 = make_float2(acc[mb][nb][2] + bs0, acc[mb][nb][3] + bs1);
            *(float2*)(C + row * (size_t)N + col)       = v0;
            *(float2*)(C + (row + 8) * (size_t)N + col) = v1;
        }
    }
}

// ===========================================================================
// Persistent recurrence — 2-pass fp16, K-SPLIT WARPS:
// 128 CTAs x 512 threads (16 warps = 2 M-halves x 2 N-halves(64) x 4 K-slices
// of 16 within each 64-chunk). CTA: M=32 permuted gate rows, N=128 batch,
// K=1024 in 16 chunks of 64. Partials accumulate in registers across chunks,
// spill to 4 Gs planes, summed in the gate pass (exact fp32 reassociation).
// Per-SM ldsm bytes/chunk: 48KB (vs 64KB in R10) with 4 warps/SMSP.
// smem: 2 x 27648 ring | Gs 4 x [32][132] f32 = 67584  -> 122880
// ===========================================================================
#define LS_PITCH 144
#define LS_APL   (32 * LS_PITCH)              // 4608
#define LS_BPL   (128 * LS_PITCH)             // 18432
#define LS_BUF   (2 * LS_APL + LS_BPL)        // 27648
#define LS_GS    (2 * LS_BUF)                 // 55296
#define GS_PITCH 132
#define GS_PLANE (32 * GS_PITCH)              // floats per k-plane
#define LS_SMEM  (LS_GS + 4 * GS_PLANE * 4)   // 122880
#define LSTM_NBLK 128

__device__ __forceinline__ void ls_fill(u32 sb, const __half* Whi,
                                        const __half* Wlo,
                                        const __half* h16,
                                        int cta, int tp, int k0, int tid)
{
    {   // A (Wperm slice): 2 planes x 32 rows x 8 segs = 512 cp.async
        int pl = tid >> 8, r2 = tid & 255;
        int rr = r2 >> 3, ks = r2 & 7;
        const __half* src = (pl ? Wlo : Whi) +
            (size_t)(cta * 32 + rr) * 1024 + k0 + ks * 8;
        CPASYNC(sb + pl * LS_APL + rr * LS_PITCH + ks * 16, src);
    }
#pragma unroll
    for (int i = 0; i < 2; i++) {        // B (h16): 128 batch x 8 segs = 1024
        int idx = tid + i * 512;
        int rb = idx >> 3, ks = idx & 7;
        const __half* src = h16 + ((size_t)rb * 512 + tp) * 1024 + k0 + ks * 8;
        CPASYNC(sb + 2 * LS_APL + rb * LS_PITCH + ks * 16, src);
    }
}

__global__ void __launch_bounds__(512, 1)
lstm_mma(const float* __restrict__ xg,          // [65536][4096]
         float* __restrict__ hseq,              // [65536][1024] fp32 exact
         float* __restrict__ cst,               // [128][1024]
         const __half* __restrict__ Whi,        // permuted [4096][1024]
         const __half* __restrict__ Wlo,
         __half* __restrict__ h16,              // [65536][1024]
         __half* __restrict__ hlo16)            // residual (for xg1)
{
    extern __shared__ char smem[];
    const u32 sbase = smem_u32(smem);
    float* Gs = (float*)(smem + LS_GS);
    const int tid = threadIdx.x;
    const int lane = tid & 31;
    const int wid = tid >> 5;                // 0..15
    const int wr = wid & 1;                  // M half (16 rows)
    const int wn = (wid >> 1) & 1;           // N half (64 batch)
    const int kq = wid >> 2;                 // K slice (16 of each 64-chunk)
    const u32 kc = (u32)(kq * 16);
    const int cta = blockIdx.x;
    const int j0 = cta * 8;

    const u32 a_r  = (u32)(lane & 15);
    const u32 a_c8 = (u32)((lane >> 4) << 3);
    const u32 b_r  = (u32)(((lane >> 4) << 3) + (lane & 7));
    const u32 b_c8 = (u32)(((lane >> 3) & 1) << 3);

    const int bB = tid >> 2;             // gate-pass batch 0..127
    const int up = tid & 3;              // unit pair (2 units)

    for (int t = 0; t < 512; t++) {
        if (t > 0) {
            float acc[8][4];
#pragma unroll
            for (int b = 0; b < 8; b++)
#pragma unroll
                for (int e = 0; e < 4; e++) acc[b][e] = 0.0f;

            ls_fill(sbase, Whi, Wlo, h16, cta, t - 1, 0, tid);
            CPCOMMIT();

            for (int c = 0; c < 16; c++) {
                if (c < 15) {
                    ls_fill(sbase + ((c + 1) & 1) * LS_BUF, Whi, Wlo, h16,
                            cta, t - 1, (c + 1) * 64, tid);
                    CPCOMMIT();
                    CPWAIT(1);
                } else {
                    CPWAIT(0);
                }
                __syncthreads();

                const u32 ab = sbase + (c & 1) * LS_BUF;
                u32 aaddr = ab + (wr * 16 + a_r) * LS_PITCH + (kc + a_c8) * 2;
                u32 ah[4], al[4];
                ldsm4(aaddr, ah);
                ldsm4(aaddr + LS_APL, al);
#pragma unroll
                for (int j = 0; j < 4; j++) {
                    u32 baddr = ab + 2 * LS_APL +
                        (wn * 64 + j * 16 + b_r) * LS_PITCH + (kc + b_c8) * 2;
                    u32 bb[4];
                    ldsm4(baddr, bb);
                    mma16816h(acc[j * 2 + 0], ah, bb[0], bb[1]);
                    mma16816h(acc[j * 2 + 1], ah, bb[2], bb[3]);
                    mma16816h(acc[j * 2 + 0], al, bb[0], bb[1]);
                    mma16816h(acc[j * 2 + 1], al, bb[2], bb[3]);
                }
                __syncthreads();
            }

            // spill partial accum to Gs plane kq: [32 gate rows][128 batch]
            float* G = Gs + kq * GS_PLANE;
#pragma unroll
            for (int nb = 0; nb < 8; nb++) {
                int n = wn * 64 + nb * 8 + (lane & 3) * 2;
                int mm = wr * 16 + (lane >> 2);
                G[mm * GS_PITCH + n]           = acc[nb][0];
                G[mm * GS_PITCH + n + 1]       = acc[nb][1];
                G[(mm + 8) * GS_PITCH + n]     = acc[nb][2];
                G[(mm + 8) * GS_PITCH + n + 1] = acc[nb][3];
            }
            __syncthreads();
        }

        // fused gate pass: thread = (batch bB, unit pair up), 2 units each
        {
            size_t row = (size_t)bB * 512 + t;
            const float* xr = xg + row * 4096 + j0 + up * 2;
            float2 xi = *(const float2*)(xr);
            float2 xf = *(const float2*)(xr + 1024);
            float2 xq = *(const float2*)(xr + 2048);
            float2 xo = *(const float2*)(xr + 3072);
            float xia[2] = {xi.x, xi.y};
            float xfa[2] = {xf.x, xf.y};
            float xqa[2] = {xq.x, xq.y};
            float xoa[2] = {xo.x, xo.y};
            float cpa[2] = {0.f, 0.f};
            float ria[2] = {0.f, 0.f}, rfa[2] = {0.f, 0.f};
            float rqa[2] = {0.f, 0.f}, roa[2] = {0.f, 0.f};
            if (t > 0) {
                float2 cv = *(const float2*)(cst + bB * 1024 + j0 + up * 2);
                cpa[0] = cv.x; cpa[1] = cv.y;
#pragma unroll
                for (int r = 0; r < 2; r++) {
                    int u = up * 2 + r;
#pragma unroll
                    for (int k = 0; k < 4; k++) {
                        const float* G = Gs + k * GS_PLANE;
                        ria[r] += G[(0  + u) * GS_PITCH + bB];
                        rfa[r] += G[(8  + u) * GS_PITCH + bB];
                        rqa[r] += G[(16 + u) * GS_PITCH + bB];
                        roa[r] += G[(24 + u) * GS_PITCH + bB];
                    }
                }
            }
            float hva[2], cna[2];
#pragma unroll
            for (int r = 0; r < 2; r++) {
                float ig = 1.0f / (1.0f + expf(-(ria[r] + xia[r])));
                float fg = 1.0f / (1.0f + expf(-(rfa[r] + xfa[r])));
                float gv = tanhf(rqa[r] + xqa[r]);
                float og = 1.0f / (1.0f + expf(-(roa[r] + xoa[r])));
                cna[r] = fg * cpa[r] + ig * gv;
                hva[r] = og * tanhf(cna[r]);
            }
            *(float2*)(cst + bB * 1024 + j0 + up * 2) = make_float2(cna[0], cna[1]);
            *(float2*)(hseq + row * 1024 + j0 + up * 2) = make_float2(hva[0], hva[1]);
            __half hb0 = __float2half_rn(hva[0]);
            __half hb1 = __float2half_rn(hva[1]);
            *(__half2*)(h16 + row * 1024 + j0 + up * 2) = __halves2half2(hb0, hb1);
            *(__half2*)(hlo16 + row * 1024 + j0 + up * 2) = __halves2half2(
                __float2half_rn(hva[0] - __half2float(hb0)),
                __float2half_rn(hva[1] - __half2float(hb1)));
        }

        grid_barrier(LSTM_NBLK);
    }
}

// ===========================================================================
// Launch sequence (7 launches), graph-capturable, allocation-free.
// ===========================================================================
extern "C" void kernel_launch(void* const* d_in, const int* in_sizes, int n_in,
                              void* d_out, int out_size)
{
    const float* input = (const float*)d_in[0];
    const float* W_ih0 = (const float*)d_in[1];
    const float* W_hh0 = (const float*)d_in[2];
    const float* b_ih0 = (const float*)d_in[3];
    const float* b_hh0 = (const float*)d_in[4];
    const float* W_ih1 = (const float*)d_in[5];
    const float* W_hh1 = (const float*)d_in[6];
    const float* b_ih1 = (const float*)d_in[7];
    const float* b_hh1 = (const float*)d_in[8];
    const float* W_fc  = (const float*)d_in[9];
    const float* b_fc  = (const float*)d_in[10];
    float* out = (float*)d_out;

    float *xg, *h, *c;
    __half *whh0hi, *whh0lo, *whh1hi, *whh1lo;
    __half *wih0hi, *wih0lo, *wih1hi, *wih1lo, *inhi, *inlo, *h16, *hlo16;
    cudaGetSymbolAddress((void**)&xg,     g_xg);
    cudaGetSymbolAddress((void**)&h,      g_h);
    cudaGetSymbolAddress((void**)&c,      g_c);
    cudaGetSymbolAddress((void**)&whh0hi, g_whh0_hi);
    cudaGetSymbolAddress((void**)&whh0lo, g_whh0_lo);
    cudaGetSymbolAddress((void**)&whh1hi, g_whh1_hi);
    cudaGetSymbolAddress((void**)&whh1lo, g_whh1_lo);
    cudaGetSymbolAddress((void**)&wih0hi, g_wih0_hi);
    cudaGetSymbolAddress((void**)&wih0lo, g_wih0_lo);
    cudaGetSymbolAddress((void**)&wih1hi, g_wih1_hi);
    cudaGetSymbolAddress((void**)&wih1lo, g_wih1_lo);
    cudaGetSymbolAddress((void**)&inhi,   g_in_hi);
    cudaGetSymbolAddress((void**)&inlo,   g_in_lo);
    cudaGetSymbolAddress((void**)&h16,    g_h16);
    cudaGetSymbolAddress((void**)&hlo16,  g_hlo16);

    cudaFuncSetAttribute(gemm_tc,  cudaFuncAttributeMaxDynamicSharedMemorySize, GT_SMEM);
    cudaFuncSetAttribute(lstm_mma, cudaFuncAttributeMaxDynamicSharedMemorySize, LS_SMEM);

    // #1: all prep splits fused
    split_all<<<12544, 256>>>(input, W_ih0, W_hh0, W_hh1,
                              inhi, inlo, wih0hi, wih0lo,
                              whh0hi, whh0lo, whh1hi, whh1lo);
    // #2: xg0 = x @ W_ih0^T + biases (K=64)
    {
        dim3 g(4096 / 128, 65536 / 128);
        gemm_tc<<<g, 256, GT_SMEM>>>(inhi, inlo, wih0hi, wih0lo,
                                     b_ih0, b_hh0, xg, 4096, 64);
    }
    // #3: W_ih1 split
    split_plane_h<<<4096, 256>>>(W_ih1, wih1hi, wih1lo);
    // #4: layer-0 recurrence (absolute launch #6 -> ncu window)
    lstm_mma<<<LSTM_NBLK, 512, LS_SMEM>>>(xg, h, c, whh0hi, whh0lo, h16, hlo16);
    // #5: xg1 = h1 @ W_ih1^T + biases (K=1024, 3-pass fp16)
    {
        dim3 g(4096 / 128, 65536 / 128);
        gemm_tc<<<g, 256, GT_SMEM>>>(h16, hlo16, wih1hi, wih1lo,
                                     b_ih1, b_hh1, xg, 4096, 1024);
    }
    // #6: layer-1 recurrence
    lstm_mma<<<LSTM_NBLK, 512, LS_SMEM>>>(xg, h, c, whh1hi, whh1lo, h16, hlo16);
    // #7: FC
    dim3 gf(1, 512);
    gemm_bias<<<gf, 256>>>(h, W_fc, b_fc, nullptr, out, 64, 1024);
}

// round 13
// speedup vs baseline: 1.1643x; 1.0384x over previous
#include <cuda_runtime.h>
#include <cuda_fp16.h>

typedef unsigned long long u64;
typedef unsigned int u32;

// ===========================================================================
// PTX helpers — family-portable only (.target sm_103): mma.sync fp16 (HMMA),
// ldmatrix, cp.async. No tcgen05/TMEM (rejected by compute_103 virtual arch).
// ===========================================================================
__device__ __forceinline__ u64 ffma2(u64 a, u64 b, u64 c) {
    asm("fma.rn.f32x2 %0, %1, %2, %0;" : "+l"(c) : "l"(a), "l"(b));
    return c;
}
__device__ __forceinline__ u64 dup2(float x) {
    u64 r; unsigned xi = __float_as_uint(x);
    asm("mov.b64 %0, {%1, %1};" : "=l"(r) : "r"(xi));
    return r;
}
__device__ __forceinline__ float2 unpk(u64 v) {
    unsigned lo, hi;
    asm("mov.b64 {%0, %1}, %2;" : "=r"(lo), "=r"(hi) : "l"(v));
    return make_float2(__uint_as_float(lo), __uint_as_float(hi));
}
__device__ __forceinline__ u32 smem_u32(const void* p) {
    u32 a;
    asm("{ .reg .u64 t; cvta.to.shared.u64 t, %1; cvt.u32.u64 %0, t; }" : "=r"(a) : "l"(p));
    return a;
}
__device__ __forceinline__ void ldsm4(u32 addr, u32 r[4]) {
    asm volatile("ldmatrix.sync.aligned.m8n8.x4.shared.b16 {%0,%1,%2,%3}, [%4];"
                 : "=r"(r[0]), "=r"(r[1]), "=r"(r[2]), "=r"(r[3]) : "r"(addr));
}
__device__ __forceinline__ void mma16816h(float d[4], const u32 a[4], u32 b0, u32 b1) {
    asm volatile(
        "mma.sync.aligned.m16n8k16.row.col.f32.f16.f16.f32 "
        "{%0,%1,%2,%3}, {%4,%5,%6,%7}, {%8,%9}, {%0,%1,%2,%3};"
        : "+f"(d[0]), "+f"(d[1]), "+f"(d[2]), "+f"(d[3])
        : "r"(a[0]), "r"(a[1]), "r"(a[2]), "r"(a[3]), "r"(b0), "r"(b1));
}
#define CPASYNC(s, g) \
    asm volatile("cp.async.ca.shared.global [%0], [%1], 16;" :: "r"(s), "l"(g))
#define CPCOMMIT() asm volatile("cp.async.commit_group;" ::: "memory")
#define CPWAIT(n)  asm volatile("cp.async.wait_group %0;" :: "n"(n) : "memory")

// ===========================================================================
// Scratch (__device__ globals) — all low-precision planes are fp16
// ===========================================================================
__device__ float g_xg[268435456ULL];              // [65536][4096] fp32
__device__ float g_h [67108864ULL];               // [65536][1024] fp32 (exact h)
__device__ float g_c [131072];                    // [128][1024]
__device__ __half g_whh0_hi[4194304];             // permuted W_hh0 hi [4096][1024]
__device__ __half g_whh0_lo[4194304];
__device__ __half g_whh1_hi[4194304];
__device__ __half g_whh1_lo[4194304];
__device__ __half g_wih0_hi[4194304];             // W_ih0 [4096][64]
__device__ __half g_wih0_lo[4194304];
__device__ __half g_wih1_hi[4194304];             // W_ih1 [4096][1024]
__device__ __half g_wih1_lo[4194304];
__device__ __half g_in_hi[4194304];               // input planes [65536][64]
__device__ __half g_in_lo[4194304];
__device__ __half g_h16 [67108864ULL];            // h quantized fp16 (recurrence B)
__device__ __half g_hlo16[67108864ULL];           // h residual (for xg1 3-pass)

__device__ unsigned g_bar_count = 0;
__device__ volatile unsigned g_bar_gen = 0;

__device__ __forceinline__ void grid_barrier(int nblocks) {
    __syncthreads();
    if (threadIdx.x == 0) {
        __threadfence();
        unsigned my_gen = g_bar_gen;
        if (atomicAdd(&g_bar_count, 1) == (unsigned)(nblocks - 1)) {
            g_bar_count = 0;
            __threadfence();
            g_bar_gen = my_gen + 1;
        } else {
            while (g_bar_gen == my_gen) { }
            __threadfence();
        }
    }
    __syncthreads();
}

// ===========================================================================
// split_all: ONE prep launch.
//   blocks [0,4096)      : input split       (65536*64 elems)
//   blocks [4096,4352)   : W_ih0 split       (4096*64)
//   blocks [4352,8448)   : W_hh0 split+permute
//   blocks [8448,12544)  : W_hh1 split+permute
// ===========================================================================
__device__ __forceinline__ void plane_body(const float* __restrict__ src,
                                           __half* __restrict__ hi,
                                           __half* __restrict__ lo, size_t blk)
{
    size_t i4 = blk * 256 + threadIdx.x;
    float4 v = ((const float4*)src)[i4];
    float xs[4] = {v.x, v.y, v.z, v.w};
    __half h[4], l[4];
#pragma unroll
    for (int e = 0; e < 4; e++) {
        h[e] = __float2half_rn(xs[e]);
        l[e] = __float2half_rn(xs[e] - __half2float(h[e]));
    }
    __half2* hp = (__half2*)(hi + i4 * 4);
    __half2* lp = (__half2*)(lo + i4 * 4);
    hp[0] = __halves2half2(h[0], h[1]); hp[1] = __halves2half2(h[2], h[3]);
    lp[0] = __halves2half2(l[0], l[1]); lp[1] = __halves2half2(l[2], l[3]);
}

__device__ __forceinline__ void splitw_body(const float* __restrict__ W,
                                            __half* __restrict__ hi,
                                            __half* __restrict__ lo, int orow)
{
    int cta = orow >> 5, cc = orow & 31;
    int q = cc >> 3, r = cc & 7;
    int wrow = cta * 8 + r + q * 1024;
    float4 v = ((const float4*)(W + (size_t)wrow * 1024))[threadIdx.x];
    size_t o = (size_t)orow * 1024 + threadIdx.x * 4;
    float xs[4] = {v.x, v.y, v.z, v.w};
#pragma unroll
    for (int e = 0; e < 4; e++) {
        __half h = __float2half_rn(xs[e]);
        hi[o + e] = h;
        lo[o + e] = __float2half_rn(xs[e] - __half2float(h));
    }
}

__global__ void __launch_bounds__(256)
split_all(const float* __restrict__ input, const float* __restrict__ W_ih0,
          const float* __restrict__ W_hh0, const float* __restrict__ W_hh1,
          __half* inhi, __half* inlo, __half* wih0hi, __half* wih0lo,
          __half* whh0hi, __half* whh0lo, __half* whh1hi, __half* whh1lo)
{
    int b = blockIdx.x;
    if (b < 4096)       plane_body(input, inhi, inlo, (size_t)b);
    else if (b < 4352)  plane_body(W_ih0, wih0hi, wih0lo, (size_t)(b - 4096));
    else if (b < 8448)  splitw_body(W_hh0, whh0hi, whh0lo, b - 4352);
    else                splitw_body(W_hh1, whh1hi, whh1lo, b - 8448);
}

__global__ void __launch_bounds__(256)
split_plane_h(const float* __restrict__ src, __half* __restrict__ hi,
              __half* __restrict__ lo)
{
    plane_body(src, hi, lo, (size_t)blockIdx.x);
}

// ===========================================================================
// SIMT f32x2 GEMM (small FC only): C[M,N] = A[M,K]@W[N,K]^T + b1(+b2)
// ===========================================================================
__global__ void __launch_bounds__(256)
gemm_bias(const float* __restrict__ A, const float* __restrict__ W,
          const float* __restrict__ b1, const float* __restrict__ b2,
          float* __restrict__ C, int N, int K)
{
    __shared__ float As[16 * 128];
    __shared__ float Ws[16 * 64];

    const int tid = threadIdx.x;
    const size_t m0 = (size_t)blockIdx.y * 128;
    const int n0 = blockIdx.x * 64;
    const int tm0 = (tid >> 4) * 8;
    const int tn0 = (tid & 15) * 4;

    u64 acc[4][4];
#pragma unroll
    for (int i = 0; i < 4; i++)
#pragma unroll
        for (int j = 0; j < 4; j++) acc[i][j] = 0ULL;

    const int lm  = tid >> 2;
    const int lkq = (tid & 3) * 4;

    for (int k0 = 0; k0 < K; k0 += 16) {
#pragma unroll
        for (int p = 0; p < 2; p++) {
            int m = lm + p * 64;
            float4 v = *(const float4*)(A + (m0 + m) * (size_t)K + k0 + lkq);
            As[(lkq + 0) * 128 + m] = v.x;
            As[(lkq + 1) * 128 + m] = v.y;
            As[(lkq + 2) * 128 + m] = v.z;
            As[(lkq + 3) * 128 + m] = v.w;
        }
        {
            float4 v = *(const float4*)(W + (size_t)(n0 + lm) * K + k0 + lkq);
            Ws[(lkq + 0) * 64 + lm] = v.x;
            Ws[(lkq + 1) * 64 + lm] = v.y;
            Ws[(lkq + 2) * 64 + lm] = v.z;
            Ws[(lkq + 3) * 64 + lm] = v.w;
        }
        __syncthreads();

#pragma unroll
        for (int k = 0; k < 16; k++) {
            u64 a0 = *(const u64*)(As + k * 128 + tm0 + 0);
            u64 a1 = *(const u64*)(As + k * 128 + tm0 + 2);
            u64 a2 = *(const u64*)(As + k * 128 + tm0 + 4);
            u64 a3 = *(const u64*)(As + k * 128 + tm0 + 6);
            float4 w = *(const float4*)(Ws + k * 64 + tn0);
            u64 w0 = dup2(w.x), w1 = dup2(w.y), w2 = dup2(w.z), w3 = dup2(w.w);
            acc[0][0] = ffma2(a0, w0, acc[0][0]); acc[0][1] = ffma2(a0, w1, acc[0][1]);
            acc[0][2] = ffma2(a0, w2, acc[0][2]); acc[0][3] = ffma2(a0, w3, acc[0][3]);
            acc[1][0] = ffma2(a1, w0, acc[1][0]); acc[1][1] = ffma2(a1, w1, acc[1][1]);
            acc[1][2] = ffma2(a1, w2, acc[1][2]); acc[1][3] = ffma2(a1, w3, acc[1][3]);
            acc[2][0] = ffma2(a2, w0, acc[2][0]); acc[2][1] = ffma2(a2, w1, acc[2][1]);
            acc[2][2] = ffma2(a2, w2, acc[2][2]); acc[2][3] = ffma2(a2, w3, acc[2][3]);
            acc[3][0] = ffma2(a3, w0, acc[3][0]); acc[3][1] = ffma2(a3, w1, acc[3][1]);
            acc[3][2] = ffma2(a3, w2, acc[3][2]); acc[3][3] = ffma2(a3, w3, acc[3][3]);
        }
        __syncthreads();
    }

#pragma unroll
    for (int j = 0; j < 4; j++) {
        int col = n0 + tn0 + j;
        float bias = b1[col] + (b2 ? b2[col] : 0.0f);
#pragma unroll
        for (int i = 0; i < 4; i++) {
            float2 v = unpk(acc[i][j]);
            size_t r = m0 + tm0 + 2 * i;
            C[r * (size_t)N + col]       = v.x + bias;
            C[(r + 1) * (size_t)N + col] = v.y + bias;
        }
    }
}

// ===========================================================================
// gemm_tc: C[M,N] = A[M,K]@W[N,K]^T + b1 + b2, fp16 hi/lo 3-pass via mma.sync
// ===========================================================================
#define GT_PITCH 144
#define GT_PL    (128 * GT_PITCH)
#define GT_BUF   (4 * GT_PL)
#define GT_SMEM  (2 * GT_BUF)

__device__ __forceinline__ void gt_fill(u32 sb, const __half* Ahi,
                                        const __half* Alo,
                                        const __half* Whi,
                                        const __half* Wlo,
                                        size_t m0, int n0, int K, int k0, int tid)
{
#pragma unroll
    for (int i = 0; i < 8; i++) {
        int idx = tid + i * 256;
        int pl = idx >> 10, r2 = idx & 1023;
        int rr = r2 >> 3, ks = r2 & 7;
        const __half* src = (pl ? Alo : Ahi) + (m0 + rr) * (size_t)K + k0 + ks * 8;
        CPASYNC(sb + pl * GT_PL + rr * GT_PITCH + ks * 16, src);
    }
#pragma unroll
    for (int i = 0; i < 8; i++) {
        int idx = tid + i * 256;
        int pl = idx >> 10, r2 = idx & 1023;
        int rr = r2 >> 3, ks = r2 & 7;
        const __half* src = (pl ? Wlo : Whi) + (size_t)(n0 + rr) * K + k0 + ks * 8;
        CPASYNC(sb + 2 * GT_PL + pl * GT_PL + rr * GT_PITCH + ks * 16, src);
    }
}

__global__ void __launch_bounds__(256, 1)
gemm_tc(const __half* __restrict__ Ahi, const __half* __restrict__ Alo,
        const __half* __restrict__ Whi, const __half* __restrict__ Wlo,
        const float* __restrict__ b1, const float* __restrict__ b2,
        float* __restrict__ C, int N, int K)
{
    extern __shared__ char smem[];
    const u32 sbase = smem_u32(smem);
    const int tid = threadIdx.x;
    const int wid = tid >> 5, lane = tid & 31;
    const int wr = wid >> 2, wc = wid & 3;
    const size_t m0 = (size_t)blockIdx.y * 128;
    const int n0 = blockIdx.x * 128;
    const int NC = K / 64;

    float acc[4][4][4];
#pragma unroll
    for (int a = 0; a < 4; a++)
#pragma unroll
        for (int b = 0; b < 4; b++)
#pragma unroll
            for (int e = 0; e < 4; e++) acc[a][b][e] = 0.0f;

    const u32 a_r  = (u32)(lane & 15);
    const u32 a_c8 = (u32)((lane >> 4) << 3);
    const u32 b_r  = (u32)(((lane >> 4) << 3) + (lane & 7));
    const u32 b_c8 = (u32)(((lane >> 3) & 1) << 3);

    gt_fill(sbase, Ahi, Alo, Whi, Wlo, m0, n0, K, 0, tid);
    CPCOMMIT();

    for (int c = 0; c < NC; c++) {
        if (c + 1 < NC) {
            gt_fill(sbase + ((c + 1) & 1) * GT_BUF, Ahi, Alo, Whi, Wlo,
                    m0, n0, K, (c + 1) * 64, tid);
            CPCOMMIT();
            CPWAIT(1);
        } else {
            CPWAIT(0);
        }
        __syncthreads();

        const u32 ab = sbase + (c & 1) * GT_BUF;
#pragma unroll
        for (int kk = 0; kk < 4; kk++) {
            const u32 kc = (u32)(kk * 16);
            u32 baddr = ab + 2 * GT_PL + (wc * 32 + b_r) * GT_PITCH + (kc + b_c8) * 2;
            u32 bh0[4], bh1[4], bl0[4], bl1[4];
            ldsm4(baddr, bh0);
            ldsm4(baddr + 16 * GT_PITCH, bh1);
            ldsm4(baddr + GT_PL, bl0);
            ldsm4(baddr + GT_PL + 16 * GT_PITCH, bl1);
#pragma unroll
            for (int mb = 0; mb < 4; mb++) {
                u32 aaddr = ab + (wr * 64 + mb * 16 + a_r) * GT_PITCH + (kc + a_c8) * 2;
                u32 ah[4], al[4];
                ldsm4(aaddr, ah);
                ldsm4(aaddr + GT_PL, al);
                mma16816h(acc[mb][0], ah, bh0[0], bh0[1]);
                mma16816h(acc[mb][1], ah, bh0[2], bh0[3]);
                mma16816h(acc[mb][2], ah, bh1[0], bh1[1]);
                mma16816h(acc[mb][3], ah, bh1[2], bh1[3]);
                mma16816h(acc[mb][0], ah, bl0[0], bl0[1]);
                mma16816h(acc[mb][1], ah, bl0[2], bl0[3]);
                mma16816h(acc[mb][2], ah, bl1[0], bl1[1]);
                mma16816h(acc[mb][3], ah, bl1[2], bl1[3]);
                mma16816h(acc[mb][0], al, bh0[0], bh0[1]);
                mma16816h(acc[mb][1], al, bh0[2], bh0[3]);
                mma16816h(acc[mb][2], al, bh1[0], bh1[1]);
                mma16816h(acc[mb][3], al, bh1[2], bh1[3]);
            }
        }
        __syncthreads();
    }

#pragma unroll
    for (int nb = 0; nb < 4; nb++) {
        int col = n0 + wc * 32 + nb * 8 + (lane & 3) * 2;
        float bs0 = b1[col]     + b2[col];
        float bs1 = b1[col + 1] + b2[col + 1];
#pragma unroll
        for (int mb = 0; mb < 4; mb++) {
            size_t row = m0 + wr * 64 + mb * 16 + (lane >> 2);
            float2 v0 = make_float2(acc[mb][nb][0] + bs0, acc[mb][nb][1] + bs1);
            float2 v1 = make_float2(acc[mb][nb][2] + bs0, acc[mb][nb][3] + bs1);
            *(float2*)(C + row * (size_t)N + col)       = v0;
            *(float2*)(C + (row + 8) * (size_t)N + col) = v1;
        }
    }
}

// ===========================================================================
// Persistent recurrence — 2-pass fp16, K-split warps (R12) + 3-DEEP RING
// with ONE __syncthreads per chunk (R13 change).
// 128 CTAs x 512 threads (16 warps = 2M x 2N(64) x 4K(16-slices)).
// Ring safety: sync at top of chunk c proves all warps finished mma(c-1) on
// buffer (c-1)%3 == (c+2)%3, so fill(c+2) cannot race a reader. CPWAIT(1)
// leaves fill(c) complete.
// smem: 3 x 27648 ring | Gs 4 x [32][132] f32 = 67584  -> 150528
// ===========================================================================
#define LS_PITCH 144
#define LS_APL   (32 * LS_PITCH)              // 4608
#define LS_BPL   (128 * LS_PITCH)             // 18432
#define LS_BUF   (2 * LS_APL + LS_BPL)        // 27648
#define LS_GS    (3 * LS_BUF)                 // 82944
#define GS_PITCH 132
#define GS_PLANE (32 * GS_PITCH)
#define LS_SMEM  (LS_GS + 4 * GS_PLANE * 4)   // 150528
#define LSTM_NBLK 128

__device__ __forceinline__ void ls_fill(u32 sb, const __half* Whi,
                                        const __half* Wlo,
                                        const __half* h16,
                                        int cta, int tp, int k0, int tid)
{
    {   // A (Wperm slice): 2 planes x 32 rows x 8 segs = 512 cp.async
        int pl = tid >> 8, r2 = tid & 255;
        int rr = r2 >> 3, ks = r2 & 7;
        const __half* src = (pl ? Wlo : Whi) +
            (size_t)(cta * 32 + rr) * 1024 + k0 + ks * 8;
        CPASYNC(sb + pl * LS_APL + rr * LS_PITCH + ks * 16, src);
    }
#pragma unroll
    for (int i = 0; i < 2; i++) {        // B (h16): 128 batch x 8 segs = 1024
        int idx = tid + i * 512;
        int rb = idx >> 3, ks = idx & 7;
        const __half* src = h16 + ((size_t)rb * 512 + tp) * 1024 + k0 + ks * 8;
        CPASYNC(sb + 2 * LS_APL + rb * LS_PITCH + ks * 16, src);
    }
}

__global__ void __launch_bounds__(512, 1)
lstm_mma(const float* __restrict__ xg,          // [65536][4096]
         float* __restrict__ hseq,              // [65536][1024] fp32 exact
         float* __restrict__ cst,               // [128][1024]
         const __half* __restrict__ Whi,        // permuted [4096][1024]
         const __half* __restrict__ Wlo,
         __half* __restrict__ h16,              // [65536][1024]
         __half* __restrict__ hlo16)            // residual (for xg1)
{
    extern __shared__ char smem[];
    const u32 sbase = smem_u32(smem);
    float* Gs = (float*)(smem + LS_GS);
    const int tid = threadIdx.x;
    const int lane = tid & 31;
    const int wid = tid >> 5;                // 0..15
    const int wr = wid & 1;                  // M half (16 rows)
    const int wn = (wid >> 1) & 1;           // N half (64 batch)
    const int kq = wid >> 2;                 // K slice (16 of each 64-chunk)
    const u32 kc = (u32)(kq * 16);
    const int cta = blockIdx.x;
    const int j0 = cta * 8;

    const u32 a_r  = (u32)(lane & 15);
    const u32 a_c8 = (u32)((lane >> 4) << 3);
    const u32 b_r  = (u32)(((lane >> 4) << 3) + (lane & 7));
    const u32 b_c8 = (u32)(((lane >> 3) & 1) << 3);

    const int bB = tid >> 2;             // gate-pass batch 0..127
    const int up = tid & 3;              // unit pair (2 units)

    for (int t = 0; t < 512; t++) {
        if (t > 0) {
            float acc[8][4];
#pragma unroll
            for (int b = 0; b < 8; b++)
#pragma unroll
                for (int e = 0; e < 4; e++) acc[b][e] = 0.0f;

            ls_fill(sbase + 0 * LS_BUF, Whi, Wlo, h16, cta, t - 1, 0, tid);
            CPCOMMIT();
            ls_fill(sbase + 1 * LS_BUF, Whi, Wlo, h16, cta, t - 1, 64, tid);
            CPCOMMIT();

            int bidx = 0;                 // c % 3
            for (int c = 0; c < 16; c++) {
                if (c < 15) CPWAIT(1); else CPWAIT(0);
                __syncthreads();
                if (c < 14) {
                    int nb = bidx + 2; if (nb >= 3) nb -= 3;
                    ls_fill(sbase + nb * LS_BUF, Whi, Wlo, h16,
                            cta, t - 1, (c + 2) * 64, tid);
                    CPCOMMIT();
                }

                const u32 ab = sbase + bidx * LS_BUF;
                u32 aaddr = ab + (wr * 16 + a_r) * LS_PITCH + (kc + a_c8) * 2;
                u32 ah[4], al[4];
                ldsm4(aaddr, ah);
                ldsm4(aaddr + LS_APL, al);
#pragma unroll
                for (int j = 0; j < 4; j++) {
                    u32 baddr = ab + 2 * LS_APL +
                        (wn * 64 + j * 16 + b_r) * LS_PITCH + (kc + b_c8) * 2;
                    u32 bb[4];
                    ldsm4(baddr, bb);
                    mma16816h(acc[j * 2 + 0], ah, bb[0], bb[1]);
                    mma16816h(acc[j * 2 + 1], ah, bb[2], bb[3]);
                    mma16816h(acc[j * 2 + 0], al, bb[0], bb[1]);
                    mma16816h(acc[j * 2 + 1], al, bb[2], bb[3]);
                }
                if (++bidx == 3) bidx = 0;
            }

            // spill partial accum (warp-private) to Gs plane kq
            float* G = Gs + kq * GS_PLANE;
#pragma unroll
            for (int nb = 0; nb < 8; nb++) {
                int n = wn * 64 + nb * 8 + (lane & 3) * 2;
                int mm = wr * 16 + (lane >> 2);
                G[mm * GS_PITCH + n]           = acc[nb][0];
                G[mm * GS_PITCH + n + 1]       = acc[nb][1];
                G[(mm + 8) * GS_PITCH + n]     = acc[nb][2];
                G[(mm + 8) * GS_PITCH + n + 1] = acc[nb][3];
            }
            __syncthreads();
        }

        // fused gate pass: thread = (batch bB, unit pair up), 2 units each
        {
            size_t row = (size_t)bB * 512 + t;
            const float* xr = xg + row * 4096 + j0 + up * 2;
            float2 xi = *(const float2*)(xr);
            float2 xf = *(const float2*)(xr + 1024);
            float2 xq = *(const float2*)(xr + 2048);
            float2 xo = *(const float2*)(xr + 3072);
            float xia[2] = {xi.x, xi.y};
            float xfa[2] = {xf.x, xf.y};
            float xqa[2] = {xq.x, xq.y};
            float xoa[2] = {xo.x, xo.y};
            float cpa[2] = {0.f, 0.f};
            float ria[2] = {0.f, 0.f}, rfa[2] = {0.f, 0.f};
            float rqa[2] = {0.f, 0.f}, roa[2] = {0.f, 0.f};
            if (t > 0) {
                float2 cv = *(const float2*)(cst + bB * 1024 + j0 + up * 2);
                cpa[0] = cv.x; cpa[1] = cv.y;
#pragma unroll
                for (int r = 0; r < 2; r++) {
                    int u = up * 2 + r;
#pragma unroll
                    for (int k = 0; k < 4; k++) {
                        const float* G = Gs + k * GS_PLANE;
                        ria[r] += G[(0  + u) * GS_PITCH + bB];
                        rfa[r] += G[(8  + u) * GS_PITCH + bB];
                        rqa[r] += G[(16 + u) * GS_PITCH + bB];
                        roa[r] += G[(24 + u) * GS_PITCH + bB];
                    }
                }
            }
            float hva[2], cna[2];
#pragma unroll
            for (int r = 0; r < 2; r++) {
                float ig = 1.0f / (1.0f + expf(-(ria[r] + xia[r])));
                float fg = 1.0f / (1.0f + expf(-(rfa[r] + xfa[r])));
                float gv = tanhf(rqa[r] + xqa[r]);
                float og = 1.0f / (1.0f + expf(-(roa[r] + xoa[r])));
                cna[r] = fg * cpa[r] + ig * gv;
                hva[r] = og * tanhf(cna[r]);
            }
            *(float2*)(cst + bB * 1024 + j0 + up * 2) = make_float2(cna[0], cna[1]);
            *(float2*)(hseq + row * 1024 + j0 + up * 2) = make_float2(hva[0], hva[1]);
            __half hb0 = __float2half_rn(hva[0]);
            __half hb1 = __float2half_rn(hva[1]);
            *(__half2*)(h16 + row * 1024 + j0 + up * 2) = __halves2half2(hb0, hb1);
            *(__half2*)(hlo16 + row * 1024 + j0 + up * 2) = __halves2half2(
                __float2half_rn(hva[0] - __half2float(hb0)),
                __float2half_rn(hva[1] - __half2float(hb1)));
        }

        grid_barrier(LSTM_NBLK);
    }
}

// ===========================================================================
// Launch sequence (7 launches), graph-capturable, allocation-free.
// ===========================================================================
extern "C" void kernel_launch(void* const* d_in, const int* in_sizes, int n_in,
                              void* d_out, int out_size)
{
    const float* input = (const float*)d_in[0];
    const float* W_ih0 = (const float*)d_in[1];
    const float* W_hh0 = (const float*)d_in[2];
    const float* b_ih0 = (const float*)d_in[3];
    const float* b_hh0 = (const float*)d_in[4];
    const float* W_ih1 = (const float*)d_in[5];
    const float* W_hh1 = (const float*)d_in[6];
    const float* b_ih1 = (const float*)d_in[7];
    const float* b_hh1 = (const float*)d_in[8];
    const float* W_fc  = (const float*)d_in[9];
    const float* b_fc  = (const float*)d_in[10];
    float* out = (float*)d_out;

    float *xg, *h, *c;
    __half *whh0hi, *whh0lo, *whh1hi, *whh1lo;
    __half *wih0hi, *wih0lo, *wih1hi, *wih1lo, *inhi, *inlo, *h16, *hlo16;
    cudaGetSymbolAddress((void**)&xg,     g_xg);
    cudaGetSymbolAddress((void**)&h,      g_h);
    cudaGetSymbolAddress((void**)&c,      g_c);
    cudaGetSymbolAddress((void**)&whh0hi, g_whh0_hi);
    cudaGetSymbolAddress((void**)&whh0lo, g_whh0_lo);
    cudaGetSymbolAddress((void**)&whh1hi, g_whh1_hi);
    cudaGetSymbolAddress((void**)&whh1lo, g_whh1_lo);
    cudaGetSymbolAddress((void**)&wih0hi, g_wih0_hi);
    cudaGetSymbolAddress((void**)&wih0lo, g_wih0_lo);
    cudaGetSymbolAddress((void**)&wih1hi, g_wih1_hi);
    cudaGetSymbolAddress((void**)&wih1lo, g_wih1_lo);
    cudaGetSymbolAddress((void**)&inhi,   g_in_hi);
    cudaGetSymbolAddress((void**)&inlo,   g_in_lo);
    cudaGetSymbolAddress((void**)&h16,    g_h16);
    cudaGetSymbolAddress((void**)&hlo16,  g_hlo16);

    cudaFuncSetAttribute(gemm_tc,  cudaFuncAttributeMaxDynamicSharedMemorySize, GT_SMEM);
    cudaFuncSetAttribute(lstm_mma, cudaFuncAttributeMaxDynamicSharedMemorySize, LS_SMEM);

    // #1: all prep splits fused
    split_all<<<12544, 256>>>(input, W_ih0, W_hh0, W_hh1,
                              inhi, inlo, wih0hi, wih0lo,
                              whh0hi, whh0lo, whh1hi, whh1lo);
    // #2: xg0 = x @ W_ih0^T + biases (K=64)
    {
        dim3 g(4096 / 128, 65536 / 128);
        gemm_tc<<<g, 256, GT_SMEM>>>(inhi, inlo, wih0hi, wih0lo,
                                     b_ih0, b_hh0, xg, 4096, 64);
    }
    // #3: W_ih1 split
    split_plane_h<<<4096, 256>>>(W_ih1, wih1hi, wih1lo);
    // #4: layer-0 recurrence (absolute launch #6 -> ncu window)
    lstm_mma<<<LSTM_NBLK, 512, LS_SMEM>>>(xg, h, c, whh0hi, whh0lo, h16, hlo16);
    // #5: xg1 = h1 @ W_ih1^T + biases (K=1024, 3-pass fp16)
    {
        dim3 g(4096 / 128, 65536 / 128);
        gemm_tc<<<g, 256, GT_SMEM>>>(h16, hlo16, wih1hi, wih1lo,
                                     b_ih1, b_hh1, xg, 4096, 1024);
    }
    // #6: layer-1 recurrence
    lstm_mma<<<LSTM_NBLK, 512, LS_SMEM>>>(xg, h, c, whh1hi, whh1lo, h16, hlo16);
    // #7: FC
    dim3 gf(1, 512);
    gemm_bias<<<gf, 256>>>(h, W_fc, b_fc, nullptr, out, 64, 1024);
}

// round 14
// speedup vs baseline: 1.2927x; 1.1103x over previous
#include <cuda_runtime.h>
#include <cuda_fp16.h>

typedef unsigned long long u64;
typedef unsigned int u32;

// ===========================================================================
// PTX helpers — family-portable only (.target sm_103): mma.sync fp16 (HMMA),
// ldmatrix, cp.async. No tcgen05/TMEM (rejected by compute_103 virtual arch).
// ===========================================================================
__device__ __forceinline__ u64 ffma2(u64 a, u64 b, u64 c) {
    asm("fma.rn.f32x2 %0, %1, %2, %0;" : "+l"(c) : "l"(a), "l"(b));
    return c;
}
__device__ __forceinline__ u64 dup2(float x) {
    u64 r; unsigned xi = __float_as_uint(x);
    asm("mov.b64 %0, {%1, %1};" : "=l"(r) : "r"(xi));
    return r;
}
__device__ __forceinline__ float2 unpk(u64 v) {
    unsigned lo, hi;
    asm("mov.b64 {%0, %1}, %2;" : "=r"(lo), "=r"(hi) : "l"(v));
    return make_float2(__uint_as_float(lo), __uint_as_float(hi));
}
__device__ __forceinline__ u32 smem_u32(const void* p) {
    u32 a;
    asm("{ .reg .u64 t; cvta.to.shared.u64 t, %1; cvt.u32.u64 %0, t; }" : "=r"(a) : "l"(p));
    return a;
}
__device__ __forceinline__ void ldsm4(u32 addr, u32 r[4]) {
    asm volatile("ldmatrix.sync.aligned.m8n8.x4.shared.b16 {%0,%1,%2,%3}, [%4];"
                 : "=r"(r[0]), "=r"(r[1]), "=r"(r[2]), "=r"(r[3]) : "r"(addr));
}
__device__ __forceinline__ void mma16816h(float d[4], const u32 a[4], u32 b0, u32 b1) {
    asm volatile(
        "mma.sync.aligned.m16n8k16.row.col.f32.f16.f16.f32 "
        "{%0,%1,%2,%3}, {%4,%5,%6,%7}, {%8,%9}, {%0,%1,%2,%3};"
        : "+f"(d[0]), "+f"(d[1]), "+f"(d[2]), "+f"(d[3])
        : "r"(a[0]), "r"(a[1]), "r"(a[2]), "r"(a[3]), "r"(b0), "r"(b1));
}
#define CPASYNC(s, g) \
    asm volatile("cp.async.ca.shared.global [%0], [%1], 16;" :: "r"(s), "l"(g))
#define CPCOMMIT() asm volatile("cp.async.commit_group;" ::: "memory")
#define CPWAIT(n)  asm volatile("cp.async.wait_group %0;" :: "n"(n) : "memory")

// ===========================================================================
// Scratch (__device__ globals) — all low-precision planes are fp16
// ===========================================================================
__device__ float g_xg[268435456ULL];              // [65536][4096] fp32
__device__ float g_h [67108864ULL];               // [65536][1024] fp32 (exact h)
__device__ float g_c [131072];                    // [128][1024]
__device__ __half g_whh0_hi[4194304];             // permuted W_hh0 hi [4096][1024]
__device__ __half g_whh0_lo[4194304];
__device__ __half g_whh1_hi[4194304];
__device__ __half g_whh1_lo[4194304];
__device__ __half g_wih0_hi[4194304];             // W_ih0 [4096][64]
__device__ __half g_wih0_lo[4194304];
__device__ __half g_wih1_hi[4194304];             // W_ih1 [4096][1024]
__device__ __half g_wih1_lo[4194304];
__device__ __half g_in_hi[4194304];               // input fp16 [65536][64]
__device__ __half g_in_lo[4194304];               // (unused by 2-pass, kept)
__device__ __half g_h16 [67108864ULL];            // h quantized fp16

__device__ unsigned g_bar_count = 0;
__device__ volatile unsigned g_bar_gen = 0;

__device__ __forceinline__ void grid_barrier(int nblocks) {
    __syncthreads();
    if (threadIdx.x == 0) {
        __threadfence();
        unsigned my_gen = g_bar_gen;
        if (atomicAdd(&g_bar_count, 1) == (unsigned)(nblocks - 1)) {
            g_bar_count = 0;
            __threadfence();
            g_bar_gen = my_gen + 1;
        } else {
            while (g_bar_gen == my_gen) { }
            __threadfence();
        }
    }
    __syncthreads();
}

// ===========================================================================
// split_all: ONE prep launch.
// ===========================================================================
__device__ __forceinline__ void plane_body(const float* __restrict__ src,
                                           __half* __restrict__ hi,
                                           __half* __restrict__ lo, size_t blk)
{
    size_t i4 = blk * 256 + threadIdx.x;
    float4 v = ((const float4*)src)[i4];
    float xs[4] = {v.x, v.y, v.z, v.w};
    __half h[4], l[4];
#pragma unroll
    for (int e = 0; e < 4; e++) {
        h[e] = __float2half_rn(xs[e]);
        l[e] = __float2half_rn(xs[e] - __half2float(h[e]));
    }
    __half2* hp = (__half2*)(hi + i4 * 4);
    __half2* lp = (__half2*)(lo + i4 * 4);
    hp[0] = __halves2half2(h[0], h[1]); hp[1] = __halves2half2(h[2], h[3]);
    lp[0] = __halves2half2(l[0], l[1]); lp[1] = __halves2half2(l[2], l[3]);
}

__device__ __forceinline__ void splitw_body(const float* __restrict__ W,
                                            __half* __restrict__ hi,
                                            __half* __restrict__ lo, int orow)
{
    int cta = orow >> 5, cc = orow & 31;
    int q = cc >> 3, r = cc & 7;
    int wrow = cta * 8 + r + q * 1024;
    float4 v = ((const float4*)(W + (size_t)wrow * 1024))[threadIdx.x];
    size_t o = (size_t)orow * 1024 + threadIdx.x * 4;
    float xs[4] = {v.x, v.y, v.z, v.w};
#pragma unroll
    for (int e = 0; e < 4; e++) {
        __half h = __float2half_rn(xs[e]);
        hi[o + e] = h;
        lo[o + e] = __float2half_rn(xs[e] - __half2float(h));
    }
}

__global__ void __launch_bounds__(256)
split_all(const float* __restrict__ input, const float* __restrict__ W_ih0,
          const float* __restrict__ W_hh0, const float* __restrict__ W_hh1,
          __half* inhi, __half* inlo, __half* wih0hi, __half* wih0lo,
          __half* whh0hi, __half* whh0lo, __half* whh1hi, __half* whh1lo)
{
    int b = blockIdx.x;
    if (b < 4096)       plane_body(input, inhi, inlo, (size_t)b);
    else if (b < 4352)  plane_body(W_ih0, wih0hi, wih0lo, (size_t)(b - 4096));
    else if (b < 8448)  splitw_body(W_hh0, whh0hi, whh0lo, b - 4352);
    else                splitw_body(W_hh1, whh1hi, whh1lo, b - 8448);
}

__global__ void __launch_bounds__(256)
split_plane_h(const float* __restrict__ src, __half* __restrict__ hi,
              __half* __restrict__ lo)
{
    plane_body(src, hi, lo, (size_t)blockIdx.x);
}

// ===========================================================================
// SIMT f32x2 GEMM (small FC only): C[M,N] = A[M,K]@W[N,K]^T + b1(+b2)
// ===========================================================================
__global__ void __launch_bounds__(256)
gemm_bias(const float* __restrict__ A, const float* __restrict__ W,
          const float* __restrict__ b1, const float* __restrict__ b2,
          float* __restrict__ C, int N, int K)
{
    __shared__ float As[16 * 128];
    __shared__ float Ws[16 * 64];

    const int tid = threadIdx.x;
    const size_t m0 = (size_t)blockIdx.y * 128;
    const int n0 = blockIdx.x * 64;
    const int tm0 = (tid >> 4) * 8;
    const int tn0 = (tid & 15) * 4;

    u64 acc[4][4];
#pragma unroll
    for (int i = 0; i < 4; i++)
#pragma unroll
        for (int j = 0; j < 4; j++) acc[i][j] = 0ULL;

    const int lm  = tid >> 2;
    const int lkq = (tid & 3) * 4;

    for (int k0 = 0; k0 < K; k0 += 16) {
#pragma unroll
        for (int p = 0; p < 2; p++) {
            int m = lm + p * 64;
            float4 v = *(const float4*)(A + (m0 + m) * (size_t)K + k0 + lkq);
            As[(lkq + 0) * 128 + m] = v.x;
            As[(lkq + 1) * 128 + m] = v.y;
            As[(lkq + 2) * 128 + m] = v.z;
            As[(lkq + 3) * 128 + m] = v.w;
        }
        {
            float4 v = *(const float4*)(W + (size_t)(n0 + lm) * K + k0 + lkq);
            Ws[(lkq + 0) * 64 + lm] = v.x;
            Ws[(lkq + 1) * 64 + lm] = v.y;
            Ws[(lkq + 2) * 64 + lm] = v.z;
            Ws[(lkq + 3) * 64 + lm] = v.w;
        }
        __syncthreads();

#pragma unroll
        for (int k = 0; k < 16; k++) {
            u64 a0 = *(const u64*)(As + k * 128 + tm0 + 0);
            u64 a1 = *(const u64*)(As + k * 128 + tm0 + 2);
            u64 a2 = *(const u64*)(As + k * 128 + tm0 + 4);
            u64 a3 = *(const u64*)(As + k * 128 + tm0 + 6);
            float4 w = *(const float4*)(Ws + k * 64 + tn0);
            u64 w0 = dup2(w.x), w1 = dup2(w.y), w2 = dup2(w.z), w3 = dup2(w.w);
            acc[0][0] = ffma2(a0, w0, acc[0][0]); acc[0][1] = ffma2(a0, w1, acc[0][1]);
            acc[0][2] = ffma2(a0, w2, acc[0][2]); acc[0][3] = ffma2(a0, w3, acc[0][3]);
            acc[1][0] = ffma2(a1, w0, acc[1][0]); acc[1][1] = ffma2(a1, w1, acc[1][1]);
            acc[1][2] = ffma2(a1, w2, acc[1][2]); acc[1][3] = ffma2(a1, w3, acc[1][3]);
            acc[2][0] = ffma2(a2, w0, acc[2][0]); acc[2][1] = ffma2(a2, w1, acc[2][1]);
            acc[2][2] = ffma2(a2, w2, acc[2][2]); acc[2][3] = ffma2(a2, w3, acc[2][3]);
            acc[3][0] = ffma2(a3, w0, acc[3][0]); acc[3][1] = ffma2(a3, w1, acc[3][1]);
            acc[3][2] = ffma2(a3, w2, acc[3][2]); acc[3][3] = ffma2(a3, w3, acc[3][3]);
        }
        __syncthreads();
    }

#pragma unroll
    for (int j = 0; j < 4; j++) {
        int col = n0 + tn0 + j;
        float bias = b1[col] + (b2 ? b2[col] : 0.0f);
#pragma unroll
        for (int i = 0; i < 4; i++) {
            float2 v = unpk(acc[i][j]);
            size_t r = m0 + tm0 + 2 * i;
            C[r * (size_t)N + col]       = v.x + bias;
            C[(r + 1) * (size_t)N + col] = v.y + bias;
        }
    }
}

// ===========================================================================
// gemm_tc — 2-PASS fp16: C = A@(Whi+Wlo)^T + b1 + b2.
// A = single fp16 plane (x or h16); W exact as hi+lo.
// Buffer: A(18432) + Whi(18432) + Wlo(18432) = 55296; x2 = 110592
// -> 2 CTAs/SM (4 warps/SMSP).
// ===========================================================================
#define GT_PITCH 144
#define GT_PL    (128 * GT_PITCH)
#define GT_BUF   (3 * GT_PL)                  // 55296
#define GT_SMEM  (2 * GT_BUF)                 // 110592

__device__ __forceinline__ void gt_fill(u32 sb, const __half* A,
                                        const __half* Whi,
                                        const __half* Wlo,
                                        size_t m0, int n0, int K, int k0, int tid)
{
#pragma unroll
    for (int i = 0; i < 4; i++) {        // A: 128 rows x 8 segs
        int idx = tid + i * 256;
        int rr = idx >> 3, ks = idx & 7;
        const __half* src = A + (m0 + rr) * (size_t)K + k0 + ks * 8;
        CPASYNC(sb + rr * GT_PITCH + ks * 16, src);
    }
#pragma unroll
    for (int i = 0; i < 8; i++) {        // W: 2 planes x 128 x 8
        int idx = tid + i * 256;
        int pl = idx >> 10, r2 = idx & 1023;
        int rr = r2 >> 3, ks = r2 & 7;
        const __half* src = (pl ? Wlo : Whi) + (size_t)(n0 + rr) * K + k0 + ks * 8;
        CPASYNC(sb + GT_PL + pl * GT_PL + rr * GT_PITCH + ks * 16, src);
    }
}

__global__ void __launch_bounds__(256, 2)
gemm_tc(const __half* __restrict__ A,
        const __half* __restrict__ Whi, const __half* __restrict__ Wlo,
        const float* __restrict__ b1, const float* __restrict__ b2,
        float* __restrict__ C, int N, int K)
{
    extern __shared__ char smem[];
    const u32 sbase = smem_u32(smem);
    const int tid = threadIdx.x;
    const int wid = tid >> 5, lane = tid & 31;
    const int wr = wid >> 2, wc = wid & 3;
    const size_t m0 = (size_t)blockIdx.y * 128;
    const int n0 = blockIdx.x * 128;
    const int NC = K / 64;

    float acc[4][4][4];
#pragma unroll
    for (int a = 0; a < 4; a++)
#pragma unroll
        for (int b = 0; b < 4; b++)
#pragma unroll
            for (int e = 0; e < 4; e++) acc[a][b][e] = 0.0f;

    const u32 a_r  = (u32)(lane & 15);
    const u32 a_c8 = (u32)((lane >> 4) << 3);
    const u32 b_r  = (u32)(((lane >> 4) << 3) + (lane & 7));
    const u32 b_c8 = (u32)(((lane >> 3) & 1) << 3);

    gt_fill(sbase, A, Whi, Wlo, m0, n0, K, 0, tid);
    CPCOMMIT();

    for (int c = 0; c < NC; c++) {
        if (c + 1 < NC) {
            gt_fill(sbase + ((c + 1) & 1) * GT_BUF, A, Whi, Wlo,
                    m0, n0, K, (c + 1) * 64, tid);
            CPCOMMIT();
            CPWAIT(1);
        } else {
            CPWAIT(0);
        }
        __syncthreads();

        const u32 ab = sbase + (c & 1) * GT_BUF;
#pragma unroll
        for (int kk = 0; kk < 4; kk++) {
            const u32 kc = (u32)(kk * 16);
            u32 baddr = ab + GT_PL + (wc * 32 + b_r) * GT_PITCH + (kc + b_c8) * 2;
            u32 bh0[4], bh1[4], bl0[4], bl1[4];
            ldsm4(baddr, bh0);
            ldsm4(baddr + 16 * GT_PITCH, bh1);
            ldsm4(baddr + GT_PL, bl0);
            ldsm4(baddr + GT_PL + 16 * GT_PITCH, bl1);
#pragma unroll
            for (int mb = 0; mb < 4; mb++) {
                u32 aaddr = ab + (wr * 64 + mb * 16 + a_r) * GT_PITCH + (kc + a_c8) * 2;
                u32 ah[4];
                ldsm4(aaddr, ah);
                mma16816h(acc[mb][0], ah, bh0[0], bh0[1]);
                mma16816h(acc[mb][1], ah, bh0[2], bh0[3]);
                mma16816h(acc[mb][2], ah, bh1[0], bh1[1]);
                mma16816h(acc[mb][3], ah, bh1[2], bh1[3]);
                mma16816h(acc[mb][0], ah, bl0[0], bl0[1]);
                mma16816h(acc[mb][1], ah, bl0[2], bl0[3]);
                mma16816h(acc[mb][2], ah, bl1[0], bl1[1]);
                mma16816h(acc[mb][3], ah, bl1[2], bl1[3]);
            }
        }
        __syncthreads();
    }

#pragma unroll
    for (int nb = 0; nb < 4; nb++) {
        int col = n0 + wc * 32 + nb * 8 + (lane & 3) * 2;
        float bs0 = b1[col]     + b2[col];
        float bs1 = b1[col + 1] + b2[col + 1];
#pragma unroll
        for (int mb = 0; mb < 4; mb++) {
            size_t row = m0 + wr * 64 + mb * 16 + (lane >> 2);
            float2 v0 = make_float2(acc[mb][nb][0] + bs0, acc[mb][nb][1] + bs1);
            float2 v1 = make_float2(acc[mb][nb][2] + bs0, acc[mb][nb][3] + bs1);
            *(float2*)(C + row * (size_t)N + col)       = v0;
            *(float2*)(C + (row + 8) * (size_t)N + col) = v1;
        }
    }
}

// ===========================================================================
// Persistent recurrence — R13 config (2-pass fp16, K-split warps, 3-deep
// ring, one sync/chunk). hlo16 writes removed (no longer consumed).
// ===========================================================================
#define LS_PITCH 144
#define LS_APL   (32 * LS_PITCH)              // 4608
#define LS_BPL   (128 * LS_PITCH)             // 18432
#define LS_BUF   (2 * LS_APL + LS_BPL)        // 27648
#define LS_GS    (3 * LS_BUF)                 // 82944
#define GS_PITCH 132
#define GS_PLANE (32 * GS_PITCH)
#define LS_SMEM  (LS_GS + 4 * GS_PLANE * 4)   // 150528
#define LSTM_NBLK 128

__device__ __forceinline__ void ls_fill(u32 sb, const __half* Whi,
                                        const __half* Wlo,
                                        const __half* h16,
                                        int cta, int tp, int k0, int tid)
{
    {   // A (Wperm slice): 2 planes x 32 rows x 8 segs = 512 cp.async
        int pl = tid >> 8, r2 = tid & 255;
        int rr = r2 >> 3, ks = r2 & 7;
        const __half* src = (pl ? Wlo : Whi) +
            (size_t)(cta * 32 + rr) * 1024 + k0 + ks * 8;
        CPASYNC(sb + pl * LS_APL + rr * LS_PITCH + ks * 16, src);
    }
#pragma unroll
    for (int i = 0; i < 2; i++) {        // B (h16): 128 batch x 8 segs = 1024
        int idx = tid + i * 512;
        int rb = idx >> 3, ks = idx & 7;
        const __half* src = h16 + ((size_t)rb * 512 + tp) * 1024 + k0 + ks * 8;
        CPASYNC(sb + 2 * LS_APL + rb * LS_PITCH + ks * 16, src);
    }
}

__global__ void __launch_bounds__(512, 1)
lstm_mma(const float* __restrict__ xg,          // [65536][4096]
         float* __restrict__ hseq,              // [65536][1024] fp32 exact
         float* __restrict__ cst,               // [128][1024]
         const __half* __restrict__ Whi,        // permuted [4096][1024]
         const __half* __restrict__ Wlo,
         __half* __restrict__ h16)              // [65536][1024]
{
    extern __shared__ char smem[];
    const u32 sbase = smem_u32(smem);
    float* Gs = (float*)(smem + LS_GS);
    const int tid = threadIdx.x;
    const int lane = tid & 31;
    const int wid = tid >> 5;                // 0..15
    const int wr = wid & 1;                  // M half (16 rows)
    const int wn = (wid >> 1) & 1;           // N half (64 batch)
    const int kq = wid >> 2;                 // K slice (16 of each 64-chunk)
    const u32 kc = (u32)(kq * 16);
    const int cta = blockIdx.x;
    const int j0 = cta * 8;

    const u32 a_r  = (u32)(lane & 15);
    const u32 a_c8 = (u32)((lane >> 4) << 3);
    const u32 b_r  = (u32)(((lane >> 4) << 3) + (lane & 7));
    const u32 b_c8 = (u32)(((lane >> 3) & 1) << 3);

    const int bB = tid >> 2;             // gate-pass batch 0..127
    const int up = tid & 3;              // unit pair (2 units)

    for (int t = 0; t < 512; t++) {
        if (t > 0) {
            float acc[8][4];
#pragma unroll
            for (int b = 0; b < 8; b++)
#pragma unroll
                for (int e = 0; e < 4; e++) acc[b][e] = 0.0f;

            ls_fill(sbase + 0 * LS_BUF, Whi, Wlo, h16, cta, t - 1, 0, tid);
            CPCOMMIT();
            ls_fill(sbase + 1 * LS_BUF, Whi, Wlo, h16, cta, t - 1, 64, tid);
            CPCOMMIT();

            int bidx = 0;                 // c % 3
            for (int c = 0; c < 16; c++) {
                if (c < 15) CPWAIT(1); else CPWAIT(0);
                __syncthreads();
                if (c < 14) {
                    int nb = bidx + 2; if (nb >= 3) nb -= 3;
                    ls_fill(sbase + nb * LS_BUF, Whi, Wlo, h16,
                            cta, t - 1, (c + 2) * 64, tid);
                    CPCOMMIT();
                }

                const u32 ab = sbase + bidx * LS_BUF;
                u32 aaddr = ab + (wr * 16 + a_r) * LS_PITCH + (kc + a_c8) * 2;
                u32 ah[4], al[4];
                ldsm4(aaddr, ah);
                ldsm4(aaddr + LS_APL, al);
#pragma unroll
                for (int j = 0; j < 4; j++) {
                    u32 baddr = ab + 2 * LS_APL +
                        (wn * 64 + j * 16 + b_r) * LS_PITCH + (kc + b_c8) * 2;
                    u32 bb[4];
                    ldsm4(baddr, bb);
                    mma16816h(acc[j * 2 + 0], ah, bb[0], bb[1]);
                    mma16816h(acc[j * 2 + 1], ah, bb[2], bb[3]);
                    mma16816h(acc[j * 2 + 0], al, bb[0], bb[1]);
                    mma16816h(acc[j * 2 + 1], al, bb[2], bb[3]);
                }
                if (++bidx == 3) bidx = 0;
            }

            // spill partial accum (warp-private) to Gs plane kq
            float* G = Gs + kq * GS_PLANE;
#pragma unroll
            for (int nb = 0; nb < 8; nb++) {
                int n = wn * 64 + nb * 8 + (lane & 3) * 2;
                int mm = wr * 16 + (lane >> 2);
                G[mm * GS_PITCH + n]           = acc[nb][0];
                G[mm * GS_PITCH + n + 1]       = acc[nb][1];
                G[(mm + 8) * GS_PITCH + n]     = acc[nb][2];
                G[(mm + 8) * GS_PITCH + n + 1] = acc[nb][3];
            }
            __syncthreads();
        }

        // fused gate pass: thread = (batch bB, unit pair up), 2 units each
        {
            size_t row = (size_t)bB * 512 + t;
            const float* xr = xg + row * 4096 + j0 + up * 2;
            float2 xi = *(const float2*)(xr);
            float2 xf = *(const float2*)(xr + 1024);
            float2 xq = *(const float2*)(xr + 2048);
            float2 xo = *(const float2*)(xr + 3072);
            float xia[2] = {xi.x, xi.y};
            float xfa[2] = {xf.x, xf.y};
            float xqa[2] = {xq.x, xq.y};
            float xoa[2] = {xo.x, xo.y};
            float cpa[2] = {0.f, 0.f};
            float ria[2] = {0.f, 0.f}, rfa[2] = {0.f, 0.f};
            float rqa[2] = {0.f, 0.f}, roa[2] = {0.f, 0.f};
            if (t > 0) {
                float2 cv = *(const float2*)(cst + bB * 1024 + j0 + up * 2);
                cpa[0] = cv.x; cpa[1] = cv.y;
#pragma unroll
                for (int r = 0; r < 2; r++) {
                    int u = up * 2 + r;
#pragma unroll
                    for (int k = 0; k < 4; k++) {
                        const float* G = Gs + k * GS_PLANE;
                        ria[r] += G[(0  + u) * GS_PITCH + bB];
                        rfa[r] += G[(8  + u) * GS_PITCH + bB];
                        rqa[r] += G[(16 + u) * GS_PITCH + bB];
                        roa[r] += G[(24 + u) * GS_PITCH + bB];
                    }
                }
            }
            float hva[2], cna[2];
#pragma unroll
            for (int r = 0; r < 2; r++) {
                float ig = 1.0f / (1.0f + expf(-(ria[r] + xia[r])));
                float fg = 1.0f / (1.0f + expf(-(rfa[r] + xfa[r])));
                float gv = tanhf(rqa[r] + xqa[r]);
                float og = 1.0f / (1.0f + expf(-(roa[r] + xoa[r])));
                cna[r] = fg * cpa[r] + ig * gv;
                hva[r] = og * tanhf(cna[r]);
            }
            *(float2*)(cst + bB * 1024 + j0 + up * 2) = make_float2(cna[0], cna[1]);
            *(float2*)(hseq + row * 1024 + j0 + up * 2) = make_float2(hva[0], hva[1]);
            *(__half2*)(h16 + row * 1024 + j0 + up * 2) = __halves2half2(
                __float2half_rn(hva[0]), __float2half_rn(hva[1]));
        }

        grid_barrier(LSTM_NBLK);
    }
}

// ===========================================================================
// Launch sequence (7 launches), graph-capturable, allocation-free.
// ===========================================================================
extern "C" void kernel_launch(void* const* d_in, const int* in_sizes, int n_in,
                              void* d_out, int out_size)
{
    const float* input = (const float*)d_in[0];
    const float* W_ih0 = (const float*)d_in[1];
    const float* W_hh0 = (const float*)d_in[2];
    const float* b_ih0 = (const float*)d_in[3];
    const float* b_hh0 = (const float*)d_in[4];
    const float* W_ih1 = (const float*)d_in[5];
    const float* W_hh1 = (const float*)d_in[6];
    const float* b_ih1 = (const float*)d_in[7];
    const float* b_hh1 = (const float*)d_in[8];
    const float* W_fc  = (const float*)d_in[9];
    const float* b_fc  = (const float*)d_in[10];
    float* out = (float*)d_out;

    float *xg, *h, *c;
    __half *whh0hi, *whh0lo, *whh1hi, *whh1lo;
    __half *wih0hi, *wih0lo, *wih1hi, *wih1lo, *inhi, *inlo, *h16;
    cudaGetSymbolAddress((void**)&xg,     g_xg);
    cudaGetSymbolAddress((void**)&h,      g_h);
    cudaGetSymbolAddress((void**)&c,      g_c);
    cudaGetSymbolAddress((void**)&whh0hi, g_whh0_hi);
    cudaGetSymbolAddress((void**)&whh0lo, g_whh0_lo);
    cudaGetSymbolAddress((void**)&whh1hi, g_whh1_hi);
    cudaGetSymbolAddress((void**)&whh1lo, g_whh1_lo);
    cudaGetSymbolAddress((void**)&wih0hi, g_wih0_hi);
    cudaGetSymbolAddress((void**)&wih0lo, g_wih0_lo);
    cudaGetSymbolAddress((void**)&wih1hi, g_wih1_hi);
    cudaGetSymbolAddress((void**)&wih1lo, g_wih1_lo);
    cudaGetSymbolAddress((void**)&inhi,   g_in_hi);
    cudaGetSymbolAddress((void**)&inlo,   g_in_lo);
    cudaGetSymbolAddress((void**)&h16,    g_h16);

    cudaFuncSetAttribute(gemm_tc,  cudaFuncAttributeMaxDynamicSharedMemorySize, GT_SMEM);
    cudaFuncSetAttribute(lstm_mma, cudaFuncAttributeMaxDynamicSharedMemorySize, LS_SMEM);

    // #1: all prep splits fused
    split_all<<<12544, 256>>>(input, W_ih0, W_hh0, W_hh1,
                              inhi, inlo, wih0hi, wih0lo,
                              whh0hi, whh0lo, whh1hi, whh1lo);
    // #2: xg0 = x16 @ (W_ih0 hi+lo)^T + biases (K=64, 2-pass)
    {
        dim3 g(4096 / 128, 65536 / 128);
        gemm_tc<<<g, 256, GT_SMEM>>>(inhi, wih0hi, wih0lo,
                                     b_ih0, b_hh0, xg, 4096, 64);
    }
    // #3: W_ih1 split
    split_plane_h<<<4096, 256>>>(W_ih1, wih1hi, wih1lo);
    // #4: layer-0 recurrence (absolute launch #6 -> ncu window)
    lstm_mma<<<LSTM_NBLK, 512, LS_SMEM>>>(xg, h, c, whh0hi, whh0lo, h16);
    // #5: xg1 = h16 @ (W_ih1 hi+lo)^T + biases (K=1024, 2-pass)
    {
        dim3 g(4096 / 128, 65536 / 128);
        gemm_tc<<<g, 256, GT_SMEM>>>(h16, wih1hi, wih1lo,
                                     b_ih1, b_hh1, xg, 4096, 1024);
    }
    // #6: layer-1 recurrence
    lstm_mma<<<LSTM_NBLK, 512, LS_SMEM>>>(xg, h, c, whh1hi, whh1lo, h16);
    // #7: FC
    dim3 gf(1, 512);
    gemm_bias<<<gf, 256>>>(h, W_fc, b_fc, nullptr, out, 64, 1024);
}

// round 15
// speedup vs baseline: 1.3565x; 1.0493x over previous
#include <cuda_runtime.h>
#include <cuda_fp16.h>

typedef unsigned long long u64;
typedef unsigned int u32;

// ===========================================================================
// PTX helpers — family-portable only (.target sm_103): mma.sync fp16 (HMMA),
// ldmatrix, cp.async. No tcgen05/TMEM (rejected by compute_103 virtual arch).
// ===========================================================================
__device__ __forceinline__ u64 ffma2(u64 a, u64 b, u64 c) {
    asm("fma.rn.f32x2 %0, %1, %2, %0;" : "+l"(c) : "l"(a), "l"(b));
    return c;
}
__device__ __forceinline__ u64 dup2(float x) {
    u64 r; unsigned xi = __float_as_uint(x);
    asm("mov.b64 %0, {%1, %1};" : "=l"(r) : "r"(xi));
    return r;
}
__device__ __forceinline__ float2 unpk(u64 v) {
    unsigned lo, hi;
    asm("mov.b64 {%0, %1}, %2;" : "=r"(lo), "=r"(hi) : "l"(v));
    return make_float2(__uint_as_float(lo), __uint_as_float(hi));
}
__device__ __forceinline__ u32 smem_u32(const void* p) {
    u32 a;
    asm("{ .reg .u64 t; cvta.to.shared.u64 t, %1; cvt.u32.u64 %0, t; }" : "=r"(a) : "l"(p));
    return a;
}
__device__ __forceinline__ void ldsm4(u32 addr, u32 r[4]) {
    asm volatile("ldmatrix.sync.aligned.m8n8.x4.shared.b16 {%0,%1,%2,%3}, [%4];"
                 : "=r"(r[0]), "=r"(r[1]), "=r"(r[2]), "=r"(r[3]) : "r"(addr));
}
__device__ __forceinline__ void mma16816h(float d[4], const u32 a[4], u32 b0, u32 b1) {
    asm volatile(
        "mma.sync.aligned.m16n8k16.row.col.f32.f16.f16.f32 "
        "{%0,%1,%2,%3}, {%4,%5,%6,%7}, {%8,%9}, {%0,%1,%2,%3};"
        : "+f"(d[0]), "+f"(d[1]), "+f"(d[2]), "+f"(d[3])
        : "r"(a[0]), "r"(a[1]), "r"(a[2]), "r"(a[3]), "r"(b0), "r"(b1));
}
#define CPASYNC(s, g) \
    asm volatile("cp.async.ca.shared.global [%0], [%1], 16;" :: "r"(s), "l"(g))
#define CPCOMMIT() asm volatile("cp.async.commit_group;" ::: "memory")
#define CPWAIT(n)  asm volatile("cp.async.wait_group %0;" :: "n"(n) : "memory")

// fast activations: ex2.approx (rel err 2^-22), rcp.approx (2^-23)
__device__ __forceinline__ float ex2a(float x) {
    float r; asm("ex2.approx.f32 %0, %1;" : "=f"(r) : "f"(x)); return r;
}
__device__ __forceinline__ float rcpa(float x) {
    float r; asm("rcp.approx.f32 %0, %1;" : "=f"(r) : "f"(x)); return r;
}

// ===========================================================================
// Scratch (__device__ globals) — all low-precision planes are fp16
// ===========================================================================
__device__ float g_xg[268435456ULL];              // [65536][4096] fp32
__device__ float g_h [67108864ULL];               // [65536][1024] fp32 (layer-1 h)
__device__ __half g_whh0_hi[4194304];             // permuted W_hh0 hi [4096][1024]
__device__ __half g_whh0_lo[4194304];
__device__ __half g_whh1_hi[4194304];
__device__ __half g_whh1_lo[4194304];
__device__ __half g_wih0_hi[4194304];             // W_ih0 [4096][64]
__device__ __half g_wih0_lo[4194304];
__device__ __half g_wih1_hi[4194304];             // W_ih1 [4096][1024]
__device__ __half g_wih1_lo[4194304];
__device__ __half g_in_hi[4194304];               // input fp16 [65536][64]
__device__ __half g_in_lo[4194304];               // (kept for layout stability)
__device__ __half g_h16 [67108864ULL];            // h quantized fp16

__device__ unsigned g_bar_count = 0;
__device__ volatile unsigned g_bar_gen = 0;

__device__ __forceinline__ void grid_barrier(int nblocks) {
    __syncthreads();
    if (threadIdx.x == 0) {
        __threadfence();
        unsigned my_gen = g_bar_gen;
        if (atomicAdd(&g_bar_count, 1) == (unsigned)(nblocks - 1)) {
            g_bar_count = 0;
            __threadfence();
            g_bar_gen = my_gen + 1;
        } else {
            while (g_bar_gen == my_gen) { }
            __threadfence();
        }
    }
    __syncthreads();
}

// ===========================================================================
// split_all: ONE prep launch.
// ===========================================================================
__device__ __forceinline__ void plane_body(const float* __restrict__ src,
                                           __half* __restrict__ hi,
                                           __half* __restrict__ lo, size_t blk)
{
    size_t i4 = blk * 256 + threadIdx.x;
    float4 v = ((const float4*)src)[i4];
    float xs[4] = {v.x, v.y, v.z, v.w};
    __half h[4], l[4];
#pragma unroll
    for (int e = 0; e < 4; e++) {
        h[e] = __float2half_rn(xs[e]);
        l[e] = __float2half_rn(xs[e] - __half2float(h[e]));
    }
    __half2* hp = (__half2*)(hi + i4 * 4);
    __half2* lp = (__half2*)(lo + i4 * 4);
    hp[0] = __halves2half2(h[0], h[1]); hp[1] = __halves2half2(h[2], h[3]);
    lp[0] = __halves2half2(l[0], l[1]); lp[1] = __halves2half2(l[2], l[3]);
}

__device__ __forceinline__ void splitw_body(const float* __restrict__ W,
                                            __half* __restrict__ hi,
                                            __half* __restrict__ lo, int orow)
{
    int cta = orow >> 5, cc = orow & 31;
    int q = cc >> 3, r = cc & 7;
    int wrow = cta * 8 + r + q * 1024;
    float4 v = ((const float4*)(W + (size_t)wrow * 1024))[threadIdx.x];
    size_t o = (size_t)orow * 1024 + threadIdx.x * 4;
    float xs[4] = {v.x, v.y, v.z, v.w};
#pragma unroll
    for (int e = 0; e < 4; e++) {
        __half h = __float2half_rn(xs[e]);
        hi[o + e] = h;
        lo[o + e] = __float2half_rn(xs[e] - __half2float(h));
    }
}

__global__ void __launch_bounds__(256)
split_all(const float* __restrict__ input, const float* __restrict__ W_ih0,
          const float* __restrict__ W_hh0, const float* __restrict__ W_hh1,
          __half* inhi, __half* inlo, __half* wih0hi, __half* wih0lo,
          __half* whh0hi, __half* whh0lo, __half* whh1hi, __half* whh1lo)
{
    int b = blockIdx.x;
    if (b < 4096)       plane_body(input, inhi, inlo, (size_t)b);
    else if (b < 4352)  plane_body(W_ih0, wih0hi, wih0lo, (size_t)(b - 4096));
    else if (b < 8448)  splitw_body(W_hh0, whh0hi, whh0lo, b - 4352);
    else                splitw_body(W_hh1, whh1hi, whh1lo, b - 8448);
}

__global__ void __launch_bounds__(256)
split_plane_h(const float* __restrict__ src, __half* __restrict__ hi,
              __half* __restrict__ lo)
{
    plane_body(src, hi, lo, (size_t)blockIdx.x);
}

// ===========================================================================
// SIMT f32x2 GEMM (small FC only): C[M,N] = A[M,K]@W[N,K]^T + b1(+b2)
// ===========================================================================
__global__ void __launch_bounds__(256)
gemm_bias(const float* __restrict__ A, const float* __restrict__ W,
          const float* __restrict__ b1, const float* __restrict__ b2,
          float* __restrict__ C, int N, int K)
{
    __shared__ float As[16 * 128];
    __shared__ float Ws[16 * 64];

    const int tid = threadIdx.x;
    const size_t m0 = (size_t)blockIdx.y * 128;
    const int n0 = blockIdx.x * 64;
    const int tm0 = (tid >> 4) * 8;
    const int tn0 = (tid & 15) * 4;

    u64 acc[4][4];
#pragma unroll
    for (int i = 0; i < 4; i++)
#pragma unroll
        for (int j = 0; j < 4; j++) acc[i][j] = 0ULL;

    const int lm  = tid >> 2;
    const int lkq = (tid & 3) * 4;

    for (int k0 = 0; k0 < K; k0 += 16) {
#pragma unroll
        for (int p = 0; p < 2; p++) {
            int m = lm + p * 64;
            float4 v = *(const float4*)(A + (m0 + m) * (size_t)K + k0 + lkq);
            As[(lkq + 0) * 128 + m] = v.x;
            As[(lkq + 1) * 128 + m] = v.y;
            As[(lkq + 2) * 128 + m] = v.z;
            As[(lkq + 3) * 128 + m] = v.w;
        }
        {
            float4 v = *(const float4*)(W + (size_t)(n0 + lm) * K + k0 + lkq);
            Ws[(lkq + 0) * 64 + lm] = v.x;
            Ws[(lkq + 1) * 64 + lm] = v.y;
            Ws[(lkq + 2) * 64 + lm] = v.z;
            Ws[(lkq + 3) * 64 + lm] = v.w;
        }
        __syncthreads();

#pragma unroll
        for (int k = 0; k < 16; k++) {
            u64 a0 = *(const u64*)(As + k * 128 + tm0 + 0);
            u64 a1 = *(const u64*)(As + k * 128 + tm0 + 2);
            u64 a2 = *(const u64*)(As + k * 128 + tm0 + 4);
            u64 a3 = *(const u64*)(As + k * 128 + tm0 + 6);
            float4 w = *(const float4*)(Ws + k * 64 + tn0);
            u64 w0 = dup2(w.x), w1 = dup2(w.y), w2 = dup2(w.z), w3 = dup2(w.w);
            acc[0][0] = ffma2(a0, w0, acc[0][0]); acc[0][1] = ffma2(a0, w1, acc[0][1]);
            acc[0][2] = ffma2(a0, w2, acc[0][2]); acc[0][3] = ffma2(a0, w3, acc[0][3]);
            acc[1][0] = ffma2(a1, w0, acc[1][0]); acc[1][1] = ffma2(a1, w1, acc[1][1]);
            acc[1][2] = ffma2(a1, w2, acc[1][2]); acc[1][3] = ffma2(a1, w3, acc[1][3]);
            acc[2][0] = ffma2(a2, w0, acc[2][0]); acc[2][1] = ffma2(a2, w1, acc[2][1]);
            acc[2][2] = ffma2(a2, w2, acc[2][2]); acc[2][3] = ffma2(a2, w3, acc[2][3]);
            acc[3][0] = ffma2(a3, w0, acc[3][0]); acc[3][1] = ffma2(a3, w1, acc[3][1]);
            acc[3][2] = ffma2(a3, w2, acc[3][2]); acc[3][3] = ffma2(a3, w3, acc[3][3]);
        }
        __syncthreads();
    }

#pragma unroll
    for (int j = 0; j < 4; j++) {
        int col = n0 + tn0 + j;
        float bias = b1[col] + (b2 ? b2[col] : 0.0f);
#pragma unroll
        for (int i = 0; i < 4; i++) {
            float2 v = unpk(acc[i][j]);
            size_t r = m0 + tm0 + 2 * i;
            C[r * (size_t)N + col]       = v.x + bias;
            C[(r + 1) * (size_t)N + col] = v.y + bias;
        }
    }
}

// ===========================================================================
// gemm_tc — 2-PASS fp16 (R14): C = A@(Whi+Wlo)^T + b1 + b2. 2 CTAs/SM.
// ===========================================================================
#define GT_PITCH 144
#define GT_PL    (128 * GT_PITCH)
#define GT_BUF   (3 * GT_PL)                  // 55296
#define GT_SMEM  (2 * GT_BUF)                 // 110592

__device__ __forceinline__ void gt_fill(u32 sb, const __half* A,
                                        const __half* Whi,
                                        const __half* Wlo,
                                        size_t m0, int n0, int K, int k0, int tid)
{
#pragma unroll
    for (int i = 0; i < 4; i++) {
        int idx = tid + i * 256;
        int rr = idx >> 3, ks = idx & 7;
        const __half* src = A + (m0 + rr) * (size_t)K + k0 + ks * 8;
        CPASYNC(sb + rr * GT_PITCH + ks * 16, src);
    }
#pragma unroll
    for (int i = 0; i < 8; i++) {
        int idx = tid + i * 256;
        int pl = idx >> 10, r2 = idx & 1023;
        int rr = r2 >> 3, ks = r2 & 7;
        const __half* src = (pl ? Wlo : Whi) + (size_t)(n0 + rr) * K + k0 + ks * 8;
        CPASYNC(sb + GT_PL + pl * GT_PL + rr * GT_PITCH + ks * 16, src);
    }
}

__global__ void __launch_bounds__(256, 2)
gemm_tc(const __half* __restrict__ A,
        const __half* __restrict__ Whi, const __half* __restrict__ Wlo,
        const float* __restrict__ b1, const float* __restrict__ b2,
        float* __restrict__ C, int N, int K)
{
    extern __shared__ char smem[];
    const u32 sbase = smem_u32(smem);
    const int tid = threadIdx.x;
    const int wid = tid >> 5, lane = tid & 31;
    const int wr = wid >> 2, wc = wid & 3;
    const size_t m0 = (size_t)blockIdx.y * 128;
    const int n0 = blockIdx.x * 128;
    const int NC = K / 64;

    float acc[4][4][4];
#pragma unroll
    for (int a = 0; a < 4; a++)
#pragma unroll
        for (int b = 0; b < 4; b++)
#pragma unroll
            for (int e = 0; e < 4; e++) acc[a][b][e] = 0.0f;

    const u32 a_r  = (u32)(lane & 15);
    const u32 a_c8 = (u32)((lane >> 4) << 3);
    const u32 b_r  = (u32)(((lane >> 4) << 3) + (lane & 7));
    const u32 b_c8 = (u32)(((lane >> 3) & 1) << 3);

    gt_fill(sbase, A, Whi, Wlo, m0, n0, K, 0, tid);
    CPCOMMIT();

    for (int c = 0; c < NC; c++) {
        if (c + 1 < NC) {
            gt_fill(sbase + ((c + 1) & 1) * GT_BUF, A, Whi, Wlo,
                    m0, n0, K, (c + 1) * 64, tid);
            CPCOMMIT();
            CPWAIT(1);
        } else {
            CPWAIT(0);
        }
        __syncthreads();

        const u32 ab = sbase + (c & 1) * GT_BUF;
#pragma unroll
        for (int kk = 0; kk < 4; kk++) {
            const u32 kc = (u32)(kk * 16);
            u32 baddr = ab + GT_PL + (wc * 32 + b_r) * GT_PITCH + (kc + b_c8) * 2;
            u32 bh0[4], bh1[4], bl0[4], bl1[4];
            ldsm4(baddr, bh0);
            ldsm4(baddr + 16 * GT_PITCH, bh1);
            ldsm4(baddr + GT_PL, bl0);
            ldsm4(baddr + GT_PL + 16 * GT_PITCH, bl1);
#pragma unroll
            for (int mb = 0; mb < 4; mb++) {
                u32 aaddr = ab + (wr * 64 + mb * 16 + a_r) * GT_PITCH + (kc + a_c8) * 2;
                u32 ah[4];
                ldsm4(aaddr, ah);
                mma16816h(acc[mb][0], ah, bh0[0], bh0[1]);
                mma16816h(acc[mb][1], ah, bh0[2], bh0[3]);
                mma16816h(acc[mb][2], ah, bh1[0], bh1[1]);
                mma16816h(acc[mb][3], ah, bh1[2], bh1[3]);
                mma16816h(acc[mb][0], ah, bl0[0], bl0[1]);
                mma16816h(acc[mb][1], ah, bl0[2], bl0[3]);
                mma16816h(acc[mb][2], ah, bl1[0], bl1[1]);
                mma16816h(acc[mb][3], ah, bl1[2], bl1[3]);
            }
        }
        __syncthreads();
    }

#pragma unroll
    for (int nb = 0; nb < 4; nb++) {
        int col = n0 + wc * 32 + nb * 8 + (lane & 3) * 2;
        float bs0 = b1[col]     + b2[col];
        float bs1 = b1[col + 1] + b2[col + 1];
#pragma unroll
        for (int mb = 0; mb < 4; mb++) {
            size_t row = m0 + wr * 64 + mb * 16 + (lane >> 2);
            float2 v0 = make_float2(acc[mb][nb][0] + bs0, acc[mb][nb][1] + bs1);
            float2 v1 = make_float2(acc[mb][nb][2] + bs0, acc[mb][nb][3] + bs1);
            *(float2*)(C + row * (size_t)N + col)       = v0;
            *(float2*)(C + (row + 8) * (size_t)N + col) = v1;
        }
    }
}

// ===========================================================================
// Persistent recurrence — R14 mma config + R15 tail cuts:
//  - xg staged to smem via cp.async (folded into first fill group)
//  - c-state in registers (static thread ownership)
//  - activations via ex2.approx + batched rcp.approx
//  - hseq stores only when write_h != 0 (layer 1)
// smem: 3 x 27648 ring | Gs 4x[32][132]f32 | XGs [128][36]f32 -> 168960
// ===========================================================================
#define LS_PITCH 144
#define LS_APL   (32 * LS_PITCH)              // 4608
#define LS_BPL   (128 * LS_PITCH)             // 18432
#define LS_BUF   (2 * LS_APL + LS_BPL)        // 27648
#define LS_GS    (3 * LS_BUF)                 // 82944
#define GS_PITCH 132
#define GS_PLANE (32 * GS_PITCH)
#define XG_OFF   (LS_GS + 4 * GS_PLANE * 4)   // 150528
#define LS_SMEM  (XG_OFF + 128 * 36 * 4)      // 168960
#define LSTM_NBLK 128

__device__ __forceinline__ void ls_fill(u32 sb, const __half* Whi,
                                        const __half* Wlo,
                                        const __half* h16,
                                        int cta, int tp, int k0, int tid)
{
    {   // A (Wperm slice): 2 planes x 32 rows x 8 segs = 512 cp.async
        int pl = tid >> 8, r2 = tid & 255;
        int rr = r2 >> 3, ks = r2 & 7;
        const __half* src = (pl ? Wlo : Whi) +
            (size_t)(cta * 32 + rr) * 1024 + k0 + ks * 8;
        CPASYNC(sb + pl * LS_APL + rr * LS_PITCH + ks * 16, src);
    }
#pragma unroll
    for (int i = 0; i < 2; i++) {        // B (h16): 128 batch x 8 segs = 1024
        int idx = tid + i * 512;
        int rb = idx >> 3, ks = idx & 7;
        const __half* src = h16 + ((size_t)rb * 512 + tp) * 1024 + k0 + ks * 8;
        CPASYNC(sb + 2 * LS_APL + rb * LS_PITCH + ks * 16, src);
    }
}

// stage this step's xg gate inputs: XGs[b][q*8+u] (pitch 36 words)
__device__ __forceinline__ void ls_stage_xg(u32 sbase, const float* xg,
                                            int j0, int t, int tid)
{
#pragma unroll
    for (int i = 0; i < 2; i++) {
        int idx = tid + i * 512;             // 0..1023
        int b = idx >> 3;
        int q = (idx >> 1) & 3;
        int seg = idx & 1;
        const float* src = xg + ((size_t)b * 512 + t) * 4096 +
                           q * 1024 + j0 + seg * 4;
        CPASYNC(sbase + XG_OFF + (b * 36 + q * 8 + seg * 4) * 4, src);
    }
}

__global__ void __launch_bounds__(512, 1)
lstm_mma(const float* __restrict__ xg,          // [65536][4096]
         float* __restrict__ hseq,              // [65536][1024] fp32
         const __half* __restrict__ Whi,        // permuted [4096][1024]
         const __half* __restrict__ Wlo,
         __half* __restrict__ h16,              // [65536][1024]
         int write_h)
{
    extern __shared__ char smem[];
    const u32 sbase = smem_u32(smem);
    float* Gs  = (float*)(smem + LS_GS);
    float* XGs = (float*)(smem + XG_OFF);
    const int tid = threadIdx.x;
    const int lane = tid & 31;
    const int wid = tid >> 5;                // 0..15
    const int wr = wid & 1;                  // M half (16 rows)
    const int wn = (wid >> 1) & 1;           // N half (64 batch)
    const int kq = wid >> 2;                 // K slice (16 of each 64-chunk)
    const u32 kc = (u32)(kq * 16);
    const int cta = blockIdx.x;
    const int j0 = cta * 8;

    const u32 a_r  = (u32)(lane & 15);
    const u32 a_c8 = (u32)((lane >> 4) << 3);
    const u32 b_r  = (u32)(((lane >> 4) << 3) + (lane & 7));
    const u32 b_c8 = (u32)(((lane >> 3) & 1) << 3);

    const int bB = tid >> 2;             // gate-pass batch 0..127
    const int up = tid & 3;              // unit pair (2 units)

    float creg[2] = {0.0f, 0.0f};        // c-state lives in registers
    const float L1 = 1.4426950408889634f;

    for (int t = 0; t < 512; t++) {
        if (t > 0) {
            float acc[8][4];
#pragma unroll
            for (int b = 0; b < 8; b++)
#pragma unroll
                for (int e = 0; e < 4; e++) acc[b][e] = 0.0f;

            ls_fill(sbase + 0 * LS_BUF, Whi, Wlo, h16, cta, t - 1, 0, tid);
            ls_stage_xg(sbase, xg, j0, t, tid);   // same group as fill 0
            CPCOMMIT();
            ls_fill(sbase + 1 * LS_BUF, Whi, Wlo, h16, cta, t - 1, 64, tid);
            CPCOMMIT();

            int bidx = 0;                 // c % 3
            for (int c = 0; c < 16; c++) {
                if (c < 15) CPWAIT(1); else CPWAIT(0);
                __syncthreads();
                if (c < 14) {
                    int nb = bidx + 2; if (nb >= 3) nb -= 3;
                    ls_fill(sbase + nb * LS_BUF, Whi, Wlo, h16,
                            cta, t - 1, (c + 2) * 64, tid);
                    CPCOMMIT();
                }

                const u32 ab = sbase + bidx * LS_BUF;
                u32 aaddr = ab + (wr * 16 + a_r) * LS_PITCH + (kc + a_c8) * 2;
                u32 ah[4], al[4];
                ldsm4(aaddr, ah);
                ldsm4(aaddr + LS_APL, al);
#pragma unroll
                for (int j = 0; j < 4; j++) {
                    u32 baddr = ab + 2 * LS_APL +
                        (wn * 64 + j * 16 + b_r) * LS_PITCH + (kc + b_c8) * 2;
                    u32 bb[4];
                    ldsm4(baddr, bb);
                    mma16816h(acc[j * 2 + 0], ah, bb[0], bb[1]);
                    mma16816h(acc[j * 2 + 1], ah, bb[2], bb[3]);
                    mma16816h(acc[j * 2 + 0], al, bb[0], bb[1]);
                    mma16816h(acc[j * 2 + 1], al, bb[2], bb[3]);
                }
                if (++bidx == 3) bidx = 0;
            }

            // spill partial accum (warp-private) to Gs plane kq
            float* G = Gs + kq * GS_PLANE;
#pragma unroll
            for (int nb = 0; nb < 8; nb++) {
                int n = wn * 64 + nb * 8 + (lane & 3) * 2;
                int mm = wr * 16 + (lane >> 2);
                G[mm * GS_PITCH + n]           = acc[nb][0];
                G[mm * GS_PITCH + n + 1]       = acc[nb][1];
                G[(mm + 8) * GS_PITCH + n]     = acc[nb][2];
                G[(mm + 8) * GS_PITCH + n + 1] = acc[nb][3];
            }
            __syncthreads();
        }

        // fused gate pass: thread = (batch bB, unit pair up), 2 units each
        {
            size_t row = (size_t)bB * 512 + t;
            float pa[2][4];              // [item r][gate]
            if (t > 0) {
#pragma unroll
                for (int r = 0; r < 2; r++) {
                    int u = up * 2 + r;
#pragma unroll
                    for (int q = 0; q < 4; q++) {
                        float s = XGs[bB * 36 + q * 8 + u];
#pragma unroll
                        for (int k = 0; k < 4; k++)
                            s += Gs[k * GS_PLANE + (q * 8 + u) * GS_PITCH + bB];
                        pa[r][q] = s;
                    }
                }
            } else {
                const float* xr = xg + row * 4096 + j0 + up * 2;
#pragma unroll
                for (int r = 0; r < 2; r++) {
                    pa[r][0] = xr[r];
                    pa[r][1] = xr[1024 + r];
                    pa[r][2] = xr[2048 + r];
                    pa[r][3] = xr[3072 + r];
                }
            }

            float cna[2], soa[2];
#pragma unroll
            for (int r = 0; r < 2; r++) {
                float d0 = 1.0f + ex2a(fminf(-L1 * pa[r][0], 24.0f));
                float d1 = 1.0f + ex2a(fminf(-L1 * pa[r][1], 24.0f));
                float d2 = 1.0f + ex2a(fminf(-2.0f * L1 * pa[r][2], 24.0f));
                float d3 = 1.0f + ex2a(fminf(-L1 * pa[r][3], 24.0f));
                float p1 = d0 * d1, p2 = p1 * d2, p3 = p2 * d3;
                float inv = rcpa(p3);
                float invd3 = inv * p2;
                float invp2 = inv * d3;
                float invd2 = invp2 * p1;
                float invp1 = invp2 * d2;
                float invd1 = invp1 * d0;
                float invd0 = invp1 * d1;
                float si = invd0, sf = invd1, so = invd3;
                float tg = __fmaf_rn(2.0f, invd2, -1.0f);
                cna[r] = __fmaf_rn(sf, creg[r], si * tg);
                soa[r] = so;
            }
            // tanh(c): 2 denominators, 1 rcp
            float q0 = 1.0f + ex2a(fminf(-2.0f * L1 * cna[0], 24.0f));
            float q1 = 1.0f + ex2a(fminf(-2.0f * L1 * cna[1], 24.0f));
            float qq = q0 * q1;
            float iq = rcpa(qq);
            float ic0 = iq * q1;
            float ic1 = iq * q0;
            float hv0 = soa[0] * __fmaf_rn(2.0f, ic0, -1.0f);
            float hv1 = soa[1] * __fmaf_rn(2.0f, ic1, -1.0f);
            creg[0] = cna[0];
            creg[1] = cna[1];

            if (write_h)
                *(float2*)(hseq + row * 1024 + j0 + up * 2) = make_float2(hv0, hv1);
            *(__half2*)(h16 + row * 1024 + j0 + up * 2) = __halves2half2(
                __float2half_rn(hv0), __float2half_rn(hv1));
        }

        grid_barrier(LSTM_NBLK);
    }
}

// ===========================================================================
// Launch sequence (7 launches), graph-capturable, allocation-free.
// ===========================================================================
extern "C" void kernel_launch(void* const* d_in, const int* in_sizes, int n_in,
                              void* d_out, int out_size)
{
    const float* input = (const float*)d_in[0];
    const float* W_ih0 = (const float*)d_in[1];
    const float* W_hh0 = (const float*)d_in[2];
    const float* b_ih0 = (const float*)d_in[3];
    const float* b_hh0 = (const float*)d_in[4];
    const float* W_ih1 = (const float*)d_in[5];
    const float* W_hh1 = (const float*)d_in[6];
    const float* b_ih1 = (const float*)d_in[7];
    const float* b_hh1 = (const float*)d_in[8];
    const float* W_fc  = (const float*)d_in[9];
    const float* b_fc  = (const float*)d_in[10];
    float* out = (float*)d_out;

    float *xg, *h;
    __half *whh0hi, *whh0lo, *whh1hi, *whh1lo;
    __half *wih0hi, *wih0lo, *wih1hi, *wih1lo, *inhi, *inlo, *h16;
    cudaGetSymbolAddress((void**)&xg,     g_xg);
    cudaGetSymbolAddress((void**)&h,      g_h);
    cudaGetSymbolAddress((void**)&whh0hi, g_whh0_hi);
    cudaGetSymbolAddress((void**)&whh0lo, g_whh0_lo);
    cudaGetSymbolAddress((void**)&whh1hi, g_whh1_hi);
    cudaGetSymbolAddress((void**)&whh1lo, g_whh1_lo);
    cudaGetSymbolAddress((void**)&wih0hi, g_wih0_hi);
    cudaGetSymbolAddress((void**)&wih0lo, g_wih0_lo);
    cudaGetSymbolAddress((void**)&wih1hi, g_wih1_hi);
    cudaGetSymbolAddress((void**)&wih1lo, g_wih1_lo);
    cudaGetSymbolAddress((void**)&inhi,   g_in_hi);
    cudaGetSymbolAddress((void**)&inlo,   g_in_lo);
    cudaGetSymbolAddress((void**)&h16,    g_h16);

    cudaFuncSetAttribute(gemm_tc,  cudaFuncAttributeMaxDynamicSharedMemorySize, GT_SMEM);
    cudaFuncSetAttribute(lstm_mma, cudaFuncAttributeMaxDynamicSharedMemorySize, LS_SMEM);

    // #1: all prep splits fused
    split_all<<<12544, 256>>>(input, W_ih0, W_hh0, W_hh1,
                              inhi, inlo, wih0hi, wih0lo,
                              whh0hi, whh0lo, whh1hi, whh1lo);
    // #2: xg0 = x16 @ (W_ih0 hi+lo)^T + biases (K=64, 2-pass)
    {
        dim3 g(4096 / 128, 65536 / 128);
        gemm_tc<<<g, 256, GT_SMEM>>>(inhi, wih0hi, wih0lo,
                                     b_ih0, b_hh0, xg, 4096, 64);
    }
    // #3: W_ih1 split
    split_plane_h<<<4096, 256>>>(W_ih1, wih1hi, wih1lo);
    // #4: layer-0 recurrence (no hseq stores; xg1 reads h16)
    lstm_mma<<<LSTM_NBLK, 512, LS_SMEM>>>(xg, h, whh0hi, whh0lo, h16, 0);
    // #5: xg1 = h16 @ (W_ih1 hi+lo)^T + biases (K=1024, 2-pass)
    {
        dim3 g(4096 / 128, 65536 / 128);
        gemm_tc<<<g, 256, GT_SMEM>>>(h16, wih1hi, wih1lo,
                                     b_ih1, b_hh1, xg, 4096, 1024);
    }
    // #6: layer-1 recurrence (writes hseq for FC)
    lstm_mma<<<LSTM_NBLK, 512, LS_SMEM>>>(xg, h, whh1hi, whh1lo, h16, 1);
    // #7: FC
    dim3 gf(1, 512);
    gemm_bias<<<gf, 256>>>(h, W_fc, b_fc, nullptr, out, 64, 1024);
}

// round 16
// speedup vs baseline: 1.4963x; 1.1031x over previous
#include <cuda_runtime.h>
#include <cuda_fp16.h>

typedef unsigned long long u64;
typedef unsigned int u32;

// ===========================================================================
// PTX helpers — family-portable only (.target sm_103): mma.sync fp16 (HMMA),
// ldmatrix, cp.async. No tcgen05/TMEM (rejected by compute_103 virtual arch).
// ===========================================================================
__device__ __forceinline__ u64 ffma2(u64 a, u64 b, u64 c) {
    asm("fma.rn.f32x2 %0, %1, %2, %0;" : "+l"(c) : "l"(a), "l"(b));
    return c;
}
__device__ __forceinline__ u64 dup2(float x) {
    u64 r; unsigned xi = __float_as_uint(x);
    asm("mov.b64 %0, {%1, %1};" : "=l"(r) : "r"(xi));
    return r;
}
__device__ __forceinline__ float2 unpk(u64 v) {
    unsigned lo, hi;
    asm("mov.b64 {%0, %1}, %2;" : "=r"(lo), "=r"(hi) : "l"(v));
    return make_float2(__uint_as_float(lo), __uint_as_float(hi));
}
__device__ __forceinline__ u32 smem_u32(const void* p) {
    u32 a;
    asm("{ .reg .u64 t; cvta.to.shared.u64 t, %1; cvt.u32.u64 %0, t; }" : "=r"(a) : "l"(p));
    return a;
}
__device__ __forceinline__ void ldsm4(u32 addr, u32 r[4]) {
    asm volatile("ldmatrix.sync.aligned.m8n8.x4.shared.b16 {%0,%1,%2,%3}, [%4];"
                 : "=r"(r[0]), "=r"(r[1]), "=r"(r[2]), "=r"(r[3]) : "r"(addr));
}
__device__ __forceinline__ void mma16816h(float d[4], const u32 a[4], u32 b0, u32 b1) {
    asm volatile(
        "mma.sync.aligned.m16n8k16.row.col.f32.f16.f16.f32 "
        "{%0,%1,%2,%3}, {%4,%5,%6,%7}, {%8,%9}, {%0,%1,%2,%3};"
        : "+f"(d[0]), "+f"(d[1]), "+f"(d[2]), "+f"(d[3])
        : "r"(a[0]), "r"(a[1]), "r"(a[2]), "r"(a[3]), "r"(b0), "r"(b1));
}
#define CPASYNC(s, g) \
    asm volatile("cp.async.ca.shared.global [%0], [%1], 16;" :: "r"(s), "l"(g))
#define CPCOMMIT() asm volatile("cp.async.commit_group;" ::: "memory")
#define CPWAIT(n)  asm volatile("cp.async.wait_group %0;" :: "n"(n) : "memory")

// fast activations: ex2.approx (rel err 2^-22), rcp.approx (2^-23)
__device__ __forceinline__ float ex2a(float x) {
    float r; asm("ex2.approx.f32 %0, %1;" : "=f"(r) : "f"(x)); return r;
}
__device__ __forceinline__ float rcpa(float x) {
    float r; asm("rcp.approx.f32 %0, %1;" : "=f"(r) : "f"(x)); return r;
}

// ===========================================================================
// Scratch (__device__ globals) — all low-precision planes are fp16
// ===========================================================================
__device__ float g_xg[268435456ULL];              // [65536][4096] fp32
__device__ float g_h [67108864ULL];               // [65536][1024] fp32 (layer-1 h)
__device__ __half g_whh0_hi[4194304];             // permuted W_hh0 [4096][1024]
__device__ __half g_whh0_lo[4194304];             // (unused by 1-pass; kept)
__device__ __half g_whh1_hi[4194304];
__device__ __half g_whh1_lo[4194304];
__device__ __half g_wih0_hi[4194304];             // W_ih0 [4096][64]
__device__ __half g_wih0_lo[4194304];
__device__ __half g_wih1_hi[4194304];             // W_ih1 [4096][1024]
__device__ __half g_wih1_lo[4194304];
__device__ __half g_in_hi[4194304];               // input fp16 [65536][64]
__device__ __half g_in_lo[4194304];
__device__ __half g_h16 [67108864ULL];            // h quantized fp16

__device__ unsigned g_bar_count = 0;
__device__ volatile unsigned g_bar_gen = 0;

__device__ __forceinline__ void grid_barrier(int nblocks) {
    __syncthreads();
    if (threadIdx.x == 0) {
        __threadfence();
        unsigned my_gen = g_bar_gen;
        if (atomicAdd(&g_bar_count, 1) == (unsigned)(nblocks - 1)) {
            g_bar_count = 0;
            __threadfence();
            g_bar_gen = my_gen + 1;
        } else {
            while (g_bar_gen == my_gen) { }
            __threadfence();
        }
    }
    __syncthreads();
}

// ===========================================================================
// split_all: ONE prep launch.
// ===========================================================================
__device__ __forceinline__ void plane_body(const float* __restrict__ src,
                                           __half* __restrict__ hi,
                                           __half* __restrict__ lo, size_t blk)
{
    size_t i4 = blk * 256 + threadIdx.x;
    float4 v = ((const float4*)src)[i4];
    float xs[4] = {v.x, v.y, v.z, v.w};
    __half h[4], l[4];
#pragma unroll
    for (int e = 0; e < 4; e++) {
        h[e] = __float2half_rn(xs[e]);
        l[e] = __float2half_rn(xs[e] - __half2float(h[e]));
    }
    __half2* hp = (__half2*)(hi + i4 * 4);
    __half2* lp = (__half2*)(lo + i4 * 4);
    hp[0] = __halves2half2(h[0], h[1]); hp[1] = __halves2half2(h[2], h[3]);
    lp[0] = __halves2half2(l[0], l[1]); lp[1] = __halves2half2(l[2], l[3]);
}

__device__ __forceinline__ void splitw_body(const float* __restrict__ W,
                                            __half* __restrict__ hi,
                                            __half* __restrict__ lo, int orow)
{
    int cta = orow >> 5, cc = orow & 31;
    int q = cc >> 3, r = cc & 7;
    int wrow = cta * 8 + r + q * 1024;
    float4 v = ((const float4*)(W + (size_t)wrow * 1024))[threadIdx.x];
    size_t o = (size_t)orow * 1024 + threadIdx.x * 4;
    float xs[4] = {v.x, v.y, v.z, v.w};
#pragma unroll
    for (int e = 0; e < 4; e++) {
        __half h = __float2half_rn(xs[e]);
        hi[o + e] = h;
        lo[o + e] = __float2half_rn(xs[e] - __half2float(h));
    }
}

__global__ void __launch_bounds__(256)
split_all(const float* __restrict__ input, const float* __restrict__ W_ih0,
          const float* __restrict__ W_hh0, const float* __restrict__ W_hh1,
          __half* inhi, __half* inlo, __half* wih0hi, __half* wih0lo,
          __half* whh0hi, __half* whh0lo, __half* whh1hi, __half* whh1lo)
{
    int b = blockIdx.x;
    if (b < 4096)       plane_body(input, inhi, inlo, (size_t)b);
    else if (b < 4352)  plane_body(W_ih0, wih0hi, wih0lo, (size_t)(b - 4096));
    else if (b < 8448)  splitw_body(W_hh0, whh0hi, whh0lo, b - 4352);
    else                splitw_body(W_hh1, whh1hi, whh1lo, b - 8448);
}

__global__ void __launch_bounds__(256)
split_plane_h(const float* __restrict__ src, __half* __restrict__ hi,
              __half* __restrict__ lo)
{
    plane_body(src, hi, lo, (size_t)blockIdx.x);
}

// ===========================================================================
// SIMT f32x2 GEMM (small FC only): C[M,N] = A[M,K]@W[N,K]^T + b1(+b2)
// ===========================================================================
__global__ void __launch_bounds__(256)
gemm_bias(const float* __restrict__ A, const float* __restrict__ W,
          const float* __restrict__ b1, const float* __restrict__ b2,
          float* __restrict__ C, int N, int K)
{
    __shared__ float As[16 * 128];
    __shared__ float Ws[16 * 64];

    const int tid = threadIdx.x;
    const size_t m0 = (size_t)blockIdx.y * 128;
    const int n0 = blockIdx.x * 64;
    const int tm0 = (tid >> 4) * 8;
    const int tn0 = (tid & 15) * 4;

    u64 acc[4][4];
#pragma unroll
    for (int i = 0; i < 4; i++)
#pragma unroll
        for (int j = 0; j < 4; j++) acc[i][j] = 0ULL;

    const int lm  = tid >> 2;
    const int lkq = (tid & 3) * 4;

    for (int k0 = 0; k0 < K; k0 += 16) {
#pragma unroll
        for (int p = 0; p < 2; p++) {
            int m = lm + p * 64;
            float4 v = *(const float4*)(A + (m0 + m) * (size_t)K + k0 + lkq);
            As[(lkq + 0) * 128 + m] = v.x;
            As[(lkq + 1) * 128 + m] = v.y;
            As[(lkq + 2) * 128 + m] = v.z;
            As[(lkq + 3) * 128 + m] = v.w;
        }
        {
            float4 v = *(const float4*)(W + (size_t)(n0 + lm) * K + k0 + lkq);
            Ws[(lkq + 0) * 64 + lm] = v.x;
            Ws[(lkq + 1) * 64 + lm] = v.y;
            Ws[(lkq + 2) * 64 + lm] = v.z;
            Ws[(lkq + 3) * 64 + lm] = v.w;
        }
        __syncthreads();

#pragma unroll
        for (int k = 0; k < 16; k++) {
            u64 a0 = *(const u64*)(As + k * 128 + tm0 + 0);
            u64 a1 = *(const u64*)(As + k * 128 + tm0 + 2);
            u64 a2 = *(const u64*)(As + k * 128 + tm0 + 4);
            u64 a3 = *(const u64*)(As + k * 128 + tm0 + 6);
            float4 w = *(const float4*)(Ws + k * 64 + tn0);
            u64 w0 = dup2(w.x), w1 = dup2(w.y), w2 = dup2(w.z), w3 = dup2(w.w);
            acc[0][0] = ffma2(a0, w0, acc[0][0]); acc[0][1] = ffma2(a0, w1, acc[0][1]);
            acc[0][2] = ffma2(a0, w2, acc[0][2]); acc[0][3] = ffma2(a0, w3, acc[0][3]);
            acc[1][0] = ffma2(a1, w0, acc[1][0]); acc[1][1] = ffma2(a1, w1, acc[1][1]);
            acc[1][2] = ffma2(a1, w2, acc[1][2]); acc[1][3] = ffma2(a1, w3, acc[1][3]);
            acc[2][0] = ffma2(a2, w0, acc[2][0]); acc[2][1] = ffma2(a2, w1, acc[2][1]);
            acc[2][2] = ffma2(a2, w2, acc[2][2]); acc[2][3] = ffma2(a2, w3, acc[2][3]);
            acc[3][0] = ffma2(a3, w0, acc[3][0]); acc[3][1] = ffma2(a3, w1, acc[3][1]);
            acc[3][2] = ffma2(a3, w2, acc[3][2]); acc[3][3] = ffma2(a3, w3, acc[3][3]);
        }
        __syncthreads();
    }

#pragma unroll
    for (int j = 0; j < 4; j++) {
        int col = n0 + tn0 + j;
        float bias = b1[col] + (b2 ? b2[col] : 0.0f);
#pragma unroll
        for (int i = 0; i < 4; i++) {
            float2 v = unpk(acc[i][j]);
            size_t r = m0 + tm0 + 2 * i;
            C[r * (size_t)N + col]       = v.x + bias;
            C[(r + 1) * (size_t)N + col] = v.y + bias;
        }
    }
}

// ===========================================================================
// gemm_tc — 2-PASS fp16 (unchanged from R14): C = A@(Whi+Wlo)^T + b1 + b2.
// ===========================================================================
#define GT_PITCH 144
#define GT_PL    (128 * GT_PITCH)
#define GT_BUF   (3 * GT_PL)                  // 55296
#define GT_SMEM  (2 * GT_BUF)                 // 110592

__device__ __forceinline__ void gt_fill(u32 sb, const __half* A,
                                        const __half* Whi,
                                        const __half* Wlo,
                                        size_t m0, int n0, int K, int k0, int tid)
{
#pragma unroll
    for (int i = 0; i < 4; i++) {
        int idx = tid + i * 256;
        int rr = idx >> 3, ks = idx & 7;
        const __half* src = A + (m0 + rr) * (size_t)K + k0 + ks * 8;
        CPASYNC(sb + rr * GT_PITCH + ks * 16, src);
    }
#pragma unroll
    for (int i = 0; i < 8; i++) {
        int idx = tid + i * 256;
        int pl = idx >> 10, r2 = idx & 1023;
        int rr = r2 >> 3, ks = r2 & 7;
        const __half* src = (pl ? Wlo : Whi) + (size_t)(n0 + rr) * K + k0 + ks * 8;
        CPASYNC(sb + GT_PL + pl * GT_PL + rr * GT_PITCH + ks * 16, src);
    }
}

__global__ void __launch_bounds__(256, 2)
gemm_tc(const __half* __restrict__ A,
        const __half* __restrict__ Whi, const __half* __restrict__ Wlo,
        const float* __restrict__ b1, const float* __restrict__ b2,
        float* __restrict__ C, int N, int K)
{
    extern __shared__ char smem[];
    const u32 sbase = smem_u32(smem);
    const int tid = threadIdx.x;
    const int wid = tid >> 5, lane = tid & 31;
    const int wr = wid >> 2, wc = wid & 3;
    const size_t m0 = (size_t)blockIdx.y * 128;
    const int n0 = blockIdx.x * 128;
    const int NC = K / 64;

    float acc[4][4][4];
#pragma unroll
    for (int a = 0; a < 4; a++)
#pragma unroll
        for (int b = 0; b < 4; b++)
#pragma unroll
            for (int e = 0; e < 4; e++) acc[a][b][e] = 0.0f;

    const u32 a_r  = (u32)(lane & 15);
    const u32 a_c8 = (u32)((lane >> 4) << 3);
    const u32 b_r  = (u32)(((lane >> 4) << 3) + (lane & 7));
    const u32 b_c8 = (u32)(((lane >> 3) & 1) << 3);

    gt_fill(sbase, A, Whi, Wlo, m0, n0, K, 0, tid);
    CPCOMMIT();

    for (int c = 0; c < NC; c++) {
        if (c + 1 < NC) {
            gt_fill(sbase + ((c + 1) & 1) * GT_BUF, A, Whi, Wlo,
                    m0, n0, K, (c + 1) * 64, tid);
            CPCOMMIT();
            CPWAIT(1);
        } else {
            CPWAIT(0);
        }
        __syncthreads();

        const u32 ab = sbase + (c & 1) * GT_BUF;
#pragma unroll
        for (int kk = 0; kk < 4; kk++) {
            const u32 kc = (u32)(kk * 16);
            u32 baddr = ab + GT_PL + (wc * 32 + b_r) * GT_PITCH + (kc + b_c8) * 2;
            u32 bh0[4], bh1[4], bl0[4], bl1[4];
            ldsm4(baddr, bh0);
            ldsm4(baddr + 16 * GT_PITCH, bh1);
            ldsm4(baddr + GT_PL, bl0);
            ldsm4(baddr + GT_PL + 16 * GT_PITCH, bl1);
#pragma unroll
            for (int mb = 0; mb < 4; mb++) {
                u32 aaddr = ab + (wr * 64 + mb * 16 + a_r) * GT_PITCH + (kc + a_c8) * 2;
                u32 ah[4];
                ldsm4(aaddr, ah);
                mma16816h(acc[mb][0], ah, bh0[0], bh0[1]);
                mma16816h(acc[mb][1], ah, bh0[2], bh0[3]);
                mma16816h(acc[mb][2], ah, bh1[0], bh1[1]);
                mma16816h(acc[mb][3], ah, bh1[2], bh1[3]);
                mma16816h(acc[mb][0], ah, bl0[0], bl0[1]);
                mma16816h(acc[mb][1], ah, bl0[2], bl0[3]);
                mma16816h(acc[mb][2], ah, bl1[0], bl1[1]);
                mma16816h(acc[mb][3], ah, bl1[2], bl1[3]);
            }
        }
        __syncthreads();
    }

#pragma unroll
    for (int nb = 0; nb < 4; nb++) {
        int col = n0 + wc * 32 + nb * 8 + (lane & 3) * 2;
        float bs0 = b1[col]     + b2[col];
        float bs1 = b1[col + 1] + b2[col + 1];
#pragma unroll
        for (int mb = 0; mb < 4; mb++) {
            size_t row = m0 + wr * 64 + mb * 16 + (lane >> 2);
            float2 v0 = make_float2(acc[mb][nb][0] + bs0, acc[mb][nb][1] + bs1);
            float2 v1 = make_float2(acc[mb][nb][2] + bs0, acc[mb][nb][3] + bs1);
            *(float2*)(C + row * (size_t)N + col)       = v0;
            *(float2*)(C + (row + 8) * (size_t)N + col) = v1;
        }
    }
}

// ===========================================================================
// Persistent recurrence — R15 structure, SINGLE-PASS fp16 W (R16 change):
//   D = Whh16 @ h16^T. mma/chunk/warp 16 -> 8; A-plane + A-ldsm halve.
// smem: 3 x 23040 ring | Gs 4x[32][132]f32 | XGs [128][36]f32 -> 155136
// ===========================================================================
#define LS_PITCH 144
#define LS_APL   (32 * LS_PITCH)              // 4608 (single W plane)
#define LS_BPL   (128 * LS_PITCH)             // 18432
#define LS_BUF   (LS_APL + LS_BPL)            // 23040
#define LS_GS    (3 * LS_BUF)                 // 69120
#define GS_PITCH 132
#define GS_PLANE (32 * GS_PITCH)
#define XG_OFF   (LS_GS + 4 * GS_PLANE * 4)   // 136704
#define LS_SMEM  (XG_OFF + 128 * 36 * 4)      // 155136
#define LSTM_NBLK 128

__device__ __forceinline__ void ls_fill(u32 sb, const __half* Whh,
                                        const __half* h16,
                                        int cta, int tp, int k0, int tid)
{
    if (tid < 256) {   // A (Wperm slice): 32 rows x 8 segs = 256 cp.async
        int rr = tid >> 3, ks = tid & 7;
        const __half* src = Whh + (size_t)(cta * 32 + rr) * 1024 + k0 + ks * 8;
        CPASYNC(sb + rr * LS_PITCH + ks * 16, src);
    }
#pragma unroll
    for (int i = 0; i < 2; i++) {        // B (h16): 128 batch x 8 segs = 1024
        int idx = tid + i * 512;
        int rb = idx >> 3, ks = idx & 7;
        const __half* src = h16 + ((size_t)rb * 512 + tp) * 1024 + k0 + ks * 8;
        CPASYNC(sb + LS_APL + rb * LS_PITCH + ks * 16, src);
    }
}

// stage this step's xg gate inputs: XGs[b][q*8+u] (pitch 36 words)
__device__ __forceinline__ void ls_stage_xg(u32 sbase, const float* xg,
                                            int j0, int t, int tid)
{
#pragma unroll
    for (int i = 0; i < 2; i++) {
        int idx = tid + i * 512;             // 0..1023
        int b = idx >> 3;
        int q = (idx >> 1) & 3;
        int seg = idx & 1;
        const float* src = xg + ((size_t)b * 512 + t) * 4096 +
                           q * 1024 + j0 + seg * 4;
        CPASYNC(sbase + XG_OFF + (b * 36 + q * 8 + seg * 4) * 4, src);
    }
}

__global__ void __launch_bounds__(512, 1)
lstm_mma(const float* __restrict__ xg,          // [65536][4096]
         float* __restrict__ hseq,              // [65536][1024] fp32
         const __half* __restrict__ Whh,        // permuted fp16 [4096][1024]
         __half* __restrict__ h16,              // [65536][1024]
         int write_h)
{
    extern __shared__ char smem[];
    const u32 sbase = smem_u32(smem);
    float* Gs  = (float*)(smem + LS_GS);
    float* XGs = (float*)(smem + XG_OFF);
    const int tid = threadIdx.x;
    const int lane = tid & 31;
    const int wid = tid >> 5;                // 0..15
    const int wr = wid & 1;                  // M half (16 rows)
    const int wn = (wid >> 1) & 1;           // N half (64 batch)
    const int kq = wid >> 2;                 // K slice (16 of each 64-chunk)
    const u32 kc = (u32)(kq * 16);
    const int cta = blockIdx.x;
    const int j0 = cta * 8;

    const u32 a_r  = (u32)(lane & 15);
    const u32 a_c8 = (u32)((lane >> 4) << 3);
    const u32 b_r  = (u32)(((lane >> 4) << 3) + (lane & 7));
    const u32 b_c8 = (u32)(((lane >> 3) & 1) << 3);

    const int bB = tid >> 2;             // gate-pass batch 0..127
    const int up = tid & 3;              // unit pair (2 units)

    float creg[2] = {0.0f, 0.0f};        // c-state lives in registers
    const float L1 = 1.4426950408889634f;

    for (int t = 0; t < 512; t++) {
        if (t > 0) {
            float acc[8][4];
#pragma unroll
            for (int b = 0; b < 8; b++)
#pragma unroll
                for (int e = 0; e < 4; e++) acc[b][e] = 0.0f;

            ls_fill(sbase + 0 * LS_BUF, Whh, h16, cta, t - 1, 0, tid);
            ls_stage_xg(sbase, xg, j0, t, tid);   // same group as fill 0
            CPCOMMIT();
            ls_fill(sbase + 1 * LS_BUF, Whh, h16, cta, t - 1, 64, tid);
            CPCOMMIT();

            int bidx = 0;                 // c % 3
            for (int c = 0; c < 16; c++) {
                if (c < 15) CPWAIT(1); else CPWAIT(0);
                __syncthreads();
                if (c < 14) {
                    int nb = bidx + 2; if (nb >= 3) nb -= 3;
                    ls_fill(sbase + nb * LS_BUF, Whh, h16,
                            cta, t - 1, (c + 2) * 64, tid);
                    CPCOMMIT();
                }

                const u32 ab = sbase + bidx * LS_BUF;
                u32 aaddr = ab + (wr * 16 + a_r) * LS_PITCH + (kc + a_c8) * 2;
                u32 ah[4];
                ldsm4(aaddr, ah);
#pragma unroll
                for (int j = 0; j < 4; j++) {
                    u32 baddr = ab + LS_APL +
                        (wn * 64 + j * 16 + b_r) * LS_PITCH + (kc + b_c8) * 2;
                    u32 bb[4];
                    ldsm4(baddr, bb);
                    mma16816h(acc[j * 2 + 0], ah, bb[0], bb[1]);
                    mma16816h(acc[j * 2 + 1], ah, bb[2], bb[3]);
                }
                if (++bidx == 3) bidx = 0;
            }

            // spill partial accum (warp-private) to Gs plane kq
            float* G = Gs + kq * GS_PLANE;
#pragma unroll
            for (int nb = 0; nb < 8; nb++) {
                int n = wn * 64 + nb * 8 + (lane & 3) * 2;
                int mm = wr * 16 + (lane >> 2);
                G[mm * GS_PITCH + n]           = acc[nb][0];
                G[mm * GS_PITCH + n + 1]       = acc[nb][1];
                G[(mm + 8) * GS_PITCH + n]     = acc[nb][2];
                G[(mm + 8) * GS_PITCH + n + 1] = acc[nb][3];
            }
            __syncthreads();
        }

        // fused gate pass: thread = (batch bB, unit pair up), 2 units each
        {
            size_t row = (size_t)bB * 512 + t;
            float pa[2][4];              // [item r][gate]
            if (t > 0) {
#pragma unroll
                for (int r = 0; r < 2; r++) {
                    int u = up * 2 + r;
#pragma unroll
                    for (int q = 0; q < 4; q++) {
                        float s = XGs[bB * 36 + q * 8 + u];
#pragma unroll
                        for (int k = 0; k < 4; k++)
                            s += Gs[k * GS_PLANE + (q * 8 + u) * GS_PITCH + bB];
                        pa[r][q] = s;
                    }
                }
            } else {
                const float* xr = xg + row * 4096 + j0 + up * 2;
#pragma unroll
                for (int r = 0; r < 2; r++) {
                    pa[r][0] = xr[r];
                    pa[r][1] = xr[1024 + r];
                    pa[r][2] = xr[2048 + r];
                    pa[r][3] = xr[3072 + r];
                }
            }

            float cna[2], soa[2];
#pragma unroll
            for (int r = 0; r < 2; r++) {
                float d0 = 1.0f + ex2a(fminf(-L1 * pa[r][0], 24.0f));
                float d1 = 1.0f + ex2a(fminf(-L1 * pa[r][1], 24.0f));
                float d2 = 1.0f + ex2a(fminf(-2.0f * L1 * pa[r][2], 24.0f));
                float d3 = 1.0f + ex2a(fminf(-L1 * pa[r][3], 24.0f));
                float p1 = d0 * d1, p2 = p1 * d2, p3 = p2 * d3;
                float inv = rcpa(p3);
                float invd3 = inv * p2;
                float invp2 = inv * d3;
                float invd2 = invp2 * p1;
                float invp1 = invp2 * d2;
                float invd1 = invp1 * d0;
                float invd0 = invp1 * d1;
                float si = invd0, sf = invd1, so = invd3;
                float tg = __fmaf_rn(2.0f, invd2, -1.0f);
                cna[r] = __fmaf_rn(sf, creg[r], si * tg);
                soa[r] = so;
            }
            float q0 = 1.0f + ex2a(fminf(-2.0f * L1 * cna[0], 24.0f));
            float q1 = 1.0f + ex2a(fminf(-2.0f * L1 * cna[1], 24.0f));
            float qq = q0 * q1;
            float iq = rcpa(qq);
            float ic0 = iq * q1;
            float ic1 = iq * q0;
            float hv0 = soa[0] * __fmaf_rn(2.0f, ic0, -1.0f);
            float hv1 = soa[1] * __fmaf_rn(2.0f, ic1, -1.0f);
            creg[0] = cna[0];
            creg[1] = cna[1];

            if (write_h)
                *(float2*)(hseq + row * 1024 + j0 + up * 2) = make_float2(hv0, hv1);
            *(__half2*)(h16 + row * 1024 + j0 + up * 2) = __halves2half2(
                __float2half_rn(hv0), __float2half_rn(hv1));
        }

        grid_barrier(LSTM_NBLK);
    }
}

// ===========================================================================
// Launch sequence (7 launches), graph-capturable, allocation-free.
// ===========================================================================
extern "C" void kernel_launch(void* const* d_in, const int* in_sizes, int n_in,
                              void* d_out, int out_size)
{
    const float* input = (const float*)d_in[0];
    const float* W_ih0 = (const float*)d_in[1];
    const float* W_hh0 = (const float*)d_in[2];
    const float* b_ih0 = (const float*)d_in[3];
    const float* b_hh0 = (const float*)d_in[4];
    const float* W_ih1 = (const float*)d_in[5];
    const float* W_hh1 = (const float*)d_in[6];
    const float* b_ih1 = (const float*)d_in[7];
    const float* b_hh1 = (const float*)d_in[8];
    const float* W_fc  = (const float*)d_in[9];
    const float* b_fc  = (const float*)d_in[10];
    float* out = (float*)d_out;

    float *xg, *h;
    __half *whh0hi, *whh0lo, *whh1hi, *whh1lo;
    __half *wih0hi, *wih0lo, *wih1hi, *wih1lo, *inhi, *inlo, *h16;
    cudaGetSymbolAddress((void**)&xg,     g_xg);
    cudaGetSymbolAddress((void**)&h,      g_h);
    cudaGetSymbolAddress((void**)&whh0hi, g_whh0_hi);
    cudaGetSymbolAddress((void**)&whh0lo, g_whh0_lo);
    cudaGetSymbolAddress((void**)&whh1hi, g_whh1_hi);
    cudaGetSymbolAddress((void**)&whh1lo, g_whh1_lo);
    cudaGetSymbolAddress((void**)&wih0hi, g_wih0_hi);
    cudaGetSymbolAddress((void**)&wih0lo, g_wih0_lo);
    cudaGetSymbolAddress((void**)&wih1hi, g_wih1_hi);
    cudaGetSymbolAddress((void**)&wih1lo, g_wih1_lo);
    cudaGetSymbolAddress((void**)&inhi,   g_in_hi);
    cudaGetSymbolAddress((void**)&inlo,   g_in_lo);
    cudaGetSymbolAddress((void**)&h16,    g_h16);

    cudaFuncSetAttribute(gemm_tc,  cudaFuncAttributeMaxDynamicSharedMemorySize, GT_SMEM);
    cudaFuncSetAttribute(lstm_mma, cudaFuncAttributeMaxDynamicSharedMemorySize, LS_SMEM);

    // #1: all prep splits fused
    split_all<<<12544, 256>>>(input, W_ih0, W_hh0, W_hh1,
                              inhi, inlo, wih0hi, wih0lo,
                              whh0hi, whh0lo, whh1hi, whh1lo);
    // #2: xg0 = x16 @ (W_ih0 hi+lo)^T + biases (K=64, 2-pass)
    {
        dim3 g(4096 / 128, 65536 / 128);
        gemm_tc<<<g, 256, GT_SMEM>>>(inhi, wih0hi, wih0lo,
                                     b_ih0, b_hh0, xg, 4096, 64);
    }
    // #3: W_ih1 split
    split_plane_h<<<4096, 256>>>(W_ih1, wih1hi, wih1lo);
    // #4: layer-0 recurrence (single-pass fp16 W; no hseq stores)
    lstm_mma<<<LSTM_NBLK, 512, LS_SMEM>>>(xg, h, whh0hi, h16, 0);
    // #5: xg1 = h16 @ (W_ih1 hi+lo)^T + biases (K=1024, 2-pass)
    {
        dim3 g(4096 / 128, 65536 / 128);
        gemm_tc<<<g, 256, GT_SMEM>>>(h16, wih1hi, wih1lo,
                                     b_ih1, b_hh1, xg, 4096, 1024);
    }
    // #6: layer-1 recurrence (writes hseq for FC)
    lstm_mma<<<LSTM_NBLK, 512, LS_SMEM>>>(xg, h, whh1hi, h16, 1);
    // #7: FC
    dim3 gf(1, 512);
    gemm_bias<<<gf, 256>>>(h, W_fc, b_fc, nullptr, out, 64, 1024);
}

// round 17
// speedup vs baseline: 1.7597x; 1.1760x over previous
#include <cuda_runtime.h>
#include <cuda_fp16.h>

typedef unsigned long long u64;
typedef unsigned int u32;

// ===========================================================================
// PTX helpers — family-portable only (.target sm_103): mma.sync fp16 (HMMA),
// ldmatrix, cp.async. No tcgen05/TMEM (rejected by compute_103 virtual arch).
// ===========================================================================
__device__ __forceinline__ u64 ffma2(u64 a, u64 b, u64 c) {
    asm("fma.rn.f32x2 %0, %1, %2, %0;" : "+l"(c) : "l"(a), "l"(b));
    return c;
}
__device__ __forceinline__ u64 dup2(float x) {
    u64 r; unsigned xi = __float_as_uint(x);
    asm("mov.b64 %0, {%1, %1};" : "=l"(r) : "r"(xi));
    return r;
}
__device__ __forceinline__ float2 unpk(u64 v) {
    unsigned lo, hi;
    asm("mov.b64 {%0, %1}, %2;" : "=r"(lo), "=r"(hi) : "l"(v));
    return make_float2(__uint_as_float(lo), __uint_as_float(hi));
}
__device__ __forceinline__ u32 smem_u32(const void* p) {
    u32 a;
    asm("{ .reg .u64 t; cvta.to.shared.u64 t, %1; cvt.u32.u64 %0, t; }" : "=r"(a) : "l"(p));
    return a;
}
__device__ __forceinline__ void ldsm4(u32 addr, u32 r[4]) {
    asm volatile("ldmatrix.sync.aligned.m8n8.x4.shared.b16 {%0,%1,%2,%3}, [%4];"
                 : "=r"(r[0]), "=r"(r[1]), "=r"(r[2]), "=r"(r[3]) : "r"(addr));
}
__device__ __forceinline__ void mma16816h(float d[4], const u32 a[4], u32 b0, u32 b1) {
    asm volatile(
        "mma.sync.aligned.m16n8k16.row.col.f32.f16.f16.f32 "
        "{%0,%1,%2,%3}, {%4,%5,%6,%7}, {%8,%9}, {%0,%1,%2,%3};"
        : "+f"(d[0]), "+f"(d[1]), "+f"(d[2]), "+f"(d[3])
        : "r"(a[0]), "r"(a[1]), "r"(a[2]), "r"(a[3]), "r"(b0), "r"(b1));
}
#define CPASYNC(s, g) \
    asm volatile("cp.async.ca.shared.global [%0], [%1], 16;" :: "r"(s), "l"(g))
#define CPCOMMIT() asm volatile("cp.async.commit_group;" ::: "memory")
#define CPWAIT(n)  asm volatile("cp.async.wait_group %0;" :: "n"(n) : "memory")

// fast activations: ex2.approx (rel err 2^-22), rcp.approx (2^-23)
__device__ __forceinline__ float ex2a(float x) {
    float r; asm("ex2.approx.f32 %0, %1;" : "=f"(r) : "f"(x)); return r;
}
__device__ __forceinline__ float rcpa(float x) {
    float r; asm("rcp.approx.f32 %0, %1;" : "=f"(r) : "f"(x)); return r;
}

// ===========================================================================
// Scratch (__device__ globals) — all low-precision planes are fp16
// ===========================================================================
__device__ float g_xg[268435456ULL];              // [65536][4096] fp32
__device__ float g_h [67108864ULL];               // [65536][1024] fp32 (layer-1 h)
__device__ __half g_whh0_hi[4194304];             // permuted W_hh0 [4096][1024]
__device__ __half g_whh0_lo[4194304];             // (unused; kept for layout)
__device__ __half g_whh1_hi[4194304];
__device__ __half g_whh1_lo[4194304];
__device__ __half g_wih0_hi[4194304];             // W_ih0 [4096][64]
__device__ __half g_wih0_lo[4194304];
__device__ __half g_wih1_hi[4194304];             // W_ih1 [4096][1024]
__device__ __half g_wih1_lo[4194304];
__device__ __half g_in_hi[4194304];               // input fp16 [65536][64]
__device__ __half g_in_lo[4194304];
__device__ __half g_h16 [67108864ULL];            // h quantized fp16

__device__ unsigned g_bar_count = 0;
__device__ volatile unsigned g_bar_gen = 0;

__device__ __forceinline__ void grid_barrier(int nblocks) {
    __syncthreads();
    if (threadIdx.x == 0) {
        __threadfence();
        unsigned my_gen = g_bar_gen;
        if (atomicAdd(&g_bar_count, 1) == (unsigned)(nblocks - 1)) {
            g_bar_count = 0;
            __threadfence();
            g_bar_gen = my_gen + 1;
        } else {
            while (g_bar_gen == my_gen) { }
            __threadfence();
        }
    }
    __syncthreads();
}

// ===========================================================================
// split_all: ONE prep launch.
// ===========================================================================
__device__ __forceinline__ void plane_body(const float* __restrict__ src,
                                           __half* __restrict__ hi,
                                           __half* __restrict__ lo, size_t blk)
{
    size_t i4 = blk * 256 + threadIdx.x;
    float4 v = ((const float4*)src)[i4];
    float xs[4] = {v.x, v.y, v.z, v.w};
    __half h[4], l[4];
#pragma unroll
    for (int e = 0; e < 4; e++) {
        h[e] = __float2half_rn(xs[e]);
        l[e] = __float2half_rn(xs[e] - __half2float(h[e]));
    }
    __half2* hp = (__half2*)(hi + i4 * 4);
    __half2* lp = (__half2*)(lo + i4 * 4);
    hp[0] = __halves2half2(h[0], h[1]); hp[1] = __halves2half2(h[2], h[3]);
    lp[0] = __halves2half2(l[0], l[1]); lp[1] = __halves2half2(l[2], l[3]);
}

__device__ __forceinline__ void splitw_body(const float* __restrict__ W,
                                            __half* __restrict__ hi,
                                            __half* __restrict__ lo, int orow)
{
    int cta = orow >> 5, cc = orow & 31;
    int q = cc >> 3, r = cc & 7;
    int wrow = cta * 8 + r + q * 1024;
    float4 v = ((const float4*)(W + (size_t)wrow * 1024))[threadIdx.x];
    size_t o = (size_t)orow * 1024 + threadIdx.x * 4;
    float xs[4] = {v.x, v.y, v.z, v.w};
#pragma unroll
    for (int e = 0; e < 4; e++) {
        __half h = __float2half_rn(xs[e]);
        hi[o + e] = h;
        lo[o + e] = __float2half_rn(xs[e] - __half2float(h));
    }
}

__global__ void __launch_bounds__(256)
split_all(const float* __restrict__ input, const float* __restrict__ W_ih0,
          const float* __restrict__ W_hh0, const float* __restrict__ W_hh1,
          __half* inhi, __half* inlo, __half* wih0hi, __half* wih0lo,
          __half* whh0hi, __half* whh0lo, __half* whh1hi, __half* whh1lo)
{
    int b = blockIdx.x;
    if (b < 4096)       plane_body(input, inhi, inlo, (size_t)b);
    else if (b < 4352)  plane_body(W_ih0, wih0hi, wih0lo, (size_t)(b - 4096));
    else if (b < 8448)  splitw_body(W_hh0, whh0hi, whh0lo, b - 4352);
    else                splitw_body(W_hh1, whh1hi, whh1lo, b - 8448);
}

__global__ void __launch_bounds__(256)
split_plane_h(const float* __restrict__ src, __half* __restrict__ hi,
              __half* __restrict__ lo)
{
    plane_body(src, hi, lo, (size_t)blockIdx.x);
}

// ===========================================================================
// SIMT f32x2 GEMM (small FC only): C[M,N] = A[M,K]@W[N,K]^T + b1(+b2)
// ===========================================================================
__global__ void __launch_bounds__(256)
gemm_bias(const float* __restrict__ A, const float* __restrict__ W,
          const float* __restrict__ b1, const float* __restrict__ b2,
          float* __restrict__ C, int N, int K)
{
    __shared__ float As[16 * 128];
    __shared__ float Ws[16 * 64];

    const int tid = threadIdx.x;
    const size_t m0 = (size_t)blockIdx.y * 128;
    const int n0 = blockIdx.x * 64;
    const int tm0 = (tid >> 4) * 8;
    const int tn0 = (tid & 15) * 4;

    u64 acc[4][4];
#pragma unroll
    for (int i = 0; i < 4; i++)
#pragma unroll
        for (int j = 0; j < 4; j++) acc[i][j] = 0ULL;

    const int lm  = tid >> 2;
    const int lkq = (tid & 3) * 4;

    for (int k0 = 0; k0 < K; k0 += 16) {
#pragma unroll
        for (int p = 0; p < 2; p++) {
            int m = lm + p * 64;
            float4 v = *(const float4*)(A + (m0 + m) * (size_t)K + k0 + lkq);
            As[(lkq + 0) * 128 + m] = v.x;
            As[(lkq + 1) * 128 + m] = v.y;
            As[(lkq + 2) * 128 + m] = v.z;
            As[(lkq + 3) * 128 + m] = v.w;
        }
        {
            float4 v = *(const float4*)(W + (size_t)(n0 + lm) * K + k0 + lkq);
            Ws[(lkq + 0) * 64 + lm] = v.x;
            Ws[(lkq + 1) * 64 + lm] = v.y;
            Ws[(lkq + 2) * 64 + lm] = v.z;
            Ws[(lkq + 3) * 64 + lm] = v.w;
        }
        __syncthreads();

#pragma unroll
        for (int k = 0; k < 16; k++) {
            u64 a0 = *(const u64*)(As + k * 128 + tm0 + 0);
            u64 a1 = *(const u64*)(As + k * 128 + tm0 + 2);
            u64 a2 = *(const u64*)(As + k * 128 + tm0 + 4);
            u64 a3 = *(const u64*)(As + k * 128 + tm0 + 6);
            float4 w = *(const float4*)(Ws + k * 64 + tn0);
            u64 w0 = dup2(w.x), w1 = dup2(w.y), w2 = dup2(w.z), w3 = dup2(w.w);
            acc[0][0] = ffma2(a0, w0, acc[0][0]); acc[0][1] = ffma2(a0, w1, acc[0][1]);
            acc[0][2] = ffma2(a0, w2, acc[0][2]); acc[0][3] = ffma2(a0, w3, acc[0][3]);
            acc[1][0] = ffma2(a1, w0, acc[1][0]); acc[1][1] = ffma2(a1, w1, acc[1][1]);
            acc[1][2] = ffma2(a1, w2, acc[1][2]); acc[1][3] = ffma2(a1, w3, acc[1][3]);
            acc[2][0] = ffma2(a2, w0, acc[2][0]); acc[2][1] = ffma2(a2, w1, acc[2][1]);
            acc[2][2] = ffma2(a2, w2, acc[2][2]); acc[2][3] = ffma2(a2, w3, acc[2][3]);
            acc[3][0] = ffma2(a3, w0, acc[3][0]); acc[3][1] = ffma2(a3, w1, acc[3][1]);
            acc[3][2] = ffma2(a3, w2, acc[3][2]); acc[3][3] = ffma2(a3, w3, acc[3][3]);
        }
        __syncthreads();
    }

#pragma unroll
    for (int j = 0; j < 4; j++) {
        int col = n0 + tn0 + j;
        float bias = b1[col] + (b2 ? b2[col] : 0.0f);
#pragma unroll
        for (int i = 0; i < 4; i++) {
            float2 v = unpk(acc[i][j]);
            size_t r = m0 + tm0 + 2 * i;
            C[r * (size_t)N + col]       = v.x + bias;
            C[(r + 1) * (size_t)N + col] = v.y + bias;
        }
    }
}

// ===========================================================================
// gemm_tc — SINGLE-PASS fp16 (R17): C = A@W16^T + b1 + b2.
// Buffer: A(18432) + W(18432) = 36864; x2 = 73728 -> 2+ CTAs/SM.
// ===========================================================================
#define GT_PITCH 144
#define GT_PL    (128 * GT_PITCH)
#define GT_BUF   (2 * GT_PL)                  // 36864
#define GT_SMEM  (2 * GT_BUF)                 // 73728

__device__ __forceinline__ void gt_fill(u32 sb, const __half* A,
                                        const __half* W,
                                        size_t m0, int n0, int K, int k0, int tid)
{
#pragma unroll
    for (int i = 0; i < 4; i++) {        // A: 128 rows x 8 segs
        int idx = tid + i * 256;
        int rr = idx >> 3, ks = idx & 7;
        const __half* src = A + (m0 + rr) * (size_t)K + k0 + ks * 8;
        CPASYNC(sb + rr * GT_PITCH + ks * 16, src);
    }
#pragma unroll
    for (int i = 0; i < 4; i++) {        // W: 128 rows x 8 segs
        int idx = tid + i * 256;
        int rr = idx >> 3, ks = idx & 7;
        const __half* src = W + (size_t)(n0 + rr) * K + k0 + ks * 8;
        CPASYNC(sb + GT_PL + rr * GT_PITCH + ks * 16, src);
    }
}

__global__ void __launch_bounds__(256, 2)
gemm_tc(const __half* __restrict__ A, const __half* __restrict__ W,
        const float* __restrict__ b1, const float* __restrict__ b2,
        float* __restrict__ C, int N, int K)
{
    extern __shared__ char smem[];
    const u32 sbase = smem_u32(smem);
    const int tid = threadIdx.x;
    const int wid = tid >> 5, lane = tid & 31;
    const int wr = wid >> 2, wc = wid & 3;
    const size_t m0 = (size_t)blockIdx.y * 128;
    const int n0 = blockIdx.x * 128;
    const int NC = K / 64;

    float acc[4][4][4];
#pragma unroll
    for (int a = 0; a < 4; a++)
#pragma unroll
        for (int b = 0; b < 4; b++)
#pragma unroll
            for (int e = 0; e < 4; e++) acc[a][b][e] = 0.0f;

    const u32 a_r  = (u32)(lane & 15);
    const u32 a_c8 = (u32)((lane >> 4) << 3);
    const u32 b_r  = (u32)(((lane >> 4) << 3) + (lane & 7));
    const u32 b_c8 = (u32)(((lane >> 3) & 1) << 3);

    gt_fill(sbase, A, W, m0, n0, K, 0, tid);
    CPCOMMIT();

    for (int c = 0; c < NC; c++) {
        if (c + 1 < NC) {
            gt_fill(sbase + ((c + 1) & 1) * GT_BUF, A, W, m0, n0, K,
                    (c + 1) * 64, tid);
            CPCOMMIT();
            CPWAIT(1);
        } else {
            CPWAIT(0);
        }
        __syncthreads();

        const u32 ab = sbase + (c & 1) * GT_BUF;
#pragma unroll
        for (int kk = 0; kk < 4; kk++) {
            const u32 kc = (u32)(kk * 16);
            u32 baddr = ab + GT_PL + (wc * 32 + b_r) * GT_PITCH + (kc + b_c8) * 2;
            u32 bh0[4], bh1[4];
            ldsm4(baddr, bh0);
            ldsm4(baddr + 16 * GT_PITCH, bh1);
#pragma unroll
            for (int mb = 0; mb < 4; mb++) {
                u32 aaddr = ab + (wr * 64 + mb * 16 + a_r) * GT_PITCH + (kc + a_c8) * 2;
                u32 ah[4];
                ldsm4(aaddr, ah);
                mma16816h(acc[mb][0], ah, bh0[0], bh0[1]);
                mma16816h(acc[mb][1], ah, bh0[2], bh0[3]);
                mma16816h(acc[mb][2], ah, bh1[0], bh1[1]);
                mma16816h(acc[mb][3], ah, bh1[2], bh1[3]);
            }
        }
        __syncthreads();
    }

#pragma unroll
    for (int nb = 0; nb < 4; nb++) {
        int col = n0 + wc * 32 + nb * 8 + (lane & 3) * 2;
        float bs0 = b1[col]     + b2[col];
        float bs1 = b1[col + 1] + b2[col + 1];
#pragma unroll
        for (int mb = 0; mb < 4; mb++) {
            size_t row = m0 + wr * 64 + mb * 16 + (lane >> 2);
            float2 v0 = make_float2(acc[mb][nb][0] + bs0, acc[mb][nb][1] + bs1);
            float2 v1 = make_float2(acc[mb][nb][2] + bs0, acc[mb][nb][3] + bs1);
            *(float2*)(C + row * (size_t)N + col)       = v0;
            *(float2*)(C + (row + 8) * (size_t)N + col) = v1;
        }
    }
}

// ===========================================================================
// Persistent recurrence — single-pass fp16 W, RETILED warps (R17):
// 16 warps = 4 N-quarters(32 batch) x 4 K-slices(16). Each warp covers the
// full M=32: 2 A-ldsm + 2 B-ldsm -> 8 mma (4 ldsm/chunk vs 5 before).
// smem: 3 x 23040 ring | Gs 4x[32][132]f32 | XGs [128][36]f32 -> 155136
// ===========================================================================
#define LS_PITCH 144
#define LS_APL   (32 * LS_PITCH)              // 4608 (single W plane)
#define LS_BPL   (128 * LS_PITCH)             // 18432
#define LS_BUF   (LS_APL + LS_BPL)            // 23040
#define LS_GS    (3 * LS_BUF)                 // 69120
#define GS_PITCH 132
#define GS_PLANE (32 * GS_PITCH)
#define XG_OFF   (LS_GS + 4 * GS_PLANE * 4)   // 136704
#define LS_SMEM  (XG_OFF + 128 * 36 * 4)      // 155136
#define LSTM_NBLK 128

__device__ __forceinline__ void ls_fill(u32 sb, const __half* Whh,
                                        const __half* h16,
                                        int cta, int tp, int k0, int tid)
{
    if (tid < 256) {   // A (Wperm slice): 32 rows x 8 segs = 256 cp.async
        int rr = tid >> 3, ks = tid & 7;
        const __half* src = Whh + (size_t)(cta * 32 + rr) * 1024 + k0 + ks * 8;
        CPASYNC(sb + rr * LS_PITCH + ks * 16, src);
    }
#pragma unroll
    for (int i = 0; i < 2; i++) {        // B (h16): 128 batch x 8 segs = 1024
        int idx = tid + i * 512;
        int rb = idx >> 3, ks = idx & 7;
        const __half* src = h16 + ((size_t)rb * 512 + tp) * 1024 + k0 + ks * 8;
        CPASYNC(sb + LS_APL + rb * LS_PITCH + ks * 16, src);
    }
}

// stage this step's xg gate inputs: XGs[b][q*8+u] (pitch 36 words)
__device__ __forceinline__ void ls_stage_xg(u32 sbase, const float* xg,
                                            int j0, int t, int tid)
{
#pragma unroll
    for (int i = 0; i < 2; i++) {
        int idx = tid + i * 512;             // 0..1023
        int b = idx >> 3;
        int q = (idx >> 1) & 3;
        int seg = idx & 1;
        const float* src = xg + ((size_t)b * 512 + t) * 4096 +
                           q * 1024 + j0 + seg * 4;
        CPASYNC(sbase + XG_OFF + (b * 36 + q * 8 + seg * 4) * 4, src);
    }
}

__global__ void __launch_bounds__(512, 1)
lstm_mma(const float* __restrict__ xg,          // [65536][4096]
         float* __restrict__ hseq,              // [65536][1024] fp32
         const __half* __restrict__ Whh,        // permuted fp16 [4096][1024]
         __half* __restrict__ h16,              // [65536][1024]
         int write_h)
{
    extern __shared__ char smem[];
    const u32 sbase = smem_u32(smem);
    float* Gs  = (float*)(smem + LS_GS);
    float* XGs = (float*)(smem + XG_OFF);
    const int tid = threadIdx.x;
    const int lane = tid & 31;
    const int wid = tid >> 5;                // 0..15
    const int wn = wid & 3;                  // N quarter (32 batch)
    const int kq = wid >> 2;                 // K slice (16 of each 64-chunk)
    const u32 kc = (u32)(kq * 16);
    const int cta = blockIdx.x;
    const int j0 = cta * 8;

    const u32 a_r  = (u32)(lane & 15);
    const u32 a_c8 = (u32)((lane >> 4) << 3);
    const u32 b_r  = (u32)(((lane >> 4) << 3) + (lane & 7));
    const u32 b_c8 = (u32)(((lane >> 3) & 1) << 3);

    const int bB = tid >> 2;             // gate-pass batch 0..127
    const int up = tid & 3;              // unit pair (2 units)

    float creg[2] = {0.0f, 0.0f};        // c-state lives in registers
    const float L1 = 1.4426950408889634f;

    for (int t = 0; t < 512; t++) {
        if (t > 0) {
            float acc[2][4][4];          // [m half][n block][frag]
#pragma unroll
            for (int m = 0; m < 2; m++)
#pragma unroll
                for (int b = 0; b < 4; b++)
#pragma unroll
                    for (int e = 0; e < 4; e++) acc[m][b][e] = 0.0f;

            ls_fill(sbase + 0 * LS_BUF, Whh, h16, cta, t - 1, 0, tid);
            ls_stage_xg(sbase, xg, j0, t, tid);   // same group as fill 0
            CPCOMMIT();
            ls_fill(sbase + 1 * LS_BUF, Whh, h16, cta, t - 1, 64, tid);
            CPCOMMIT();

            int bidx = 0;                 // c % 3
            for (int c = 0; c < 16; c++) {
                if (c < 15) CPWAIT(1); else CPWAIT(0);
                __syncthreads();
                if (c < 14) {
                    int nb = bidx + 2; if (nb >= 3) nb -= 3;
                    ls_fill(sbase + nb * LS_BUF, Whh, h16,
                            cta, t - 1, (c + 2) * 64, tid);
                    CPCOMMIT();
                }

                const u32 ab = sbase + bidx * LS_BUF;
                u32 ah0[4], ah1[4];
                {
                    u32 aaddr = ab + a_r * LS_PITCH + (kc + a_c8) * 2;
                    ldsm4(aaddr, ah0);
                    ldsm4(aaddr + 16 * LS_PITCH, ah1);
                }
                u32 bb0[4], bb1[4];
                {
                    u32 baddr = ab + LS_APL +
                        (wn * 32 + b_r) * LS_PITCH + (kc + b_c8) * 2;
                    ldsm4(baddr, bb0);
                    ldsm4(baddr + 16 * LS_PITCH, bb1);
                }
                mma16816h(acc[0][0], ah0, bb0[0], bb0[1]);
                mma16816h(acc[0][1], ah0, bb0[2], bb0[3]);
                mma16816h(acc[0][2], ah0, bb1[0], bb1[1]);
                mma16816h(acc[0][3], ah0, bb1[2], bb1[3]);
                mma16816h(acc[1][0], ah1, bb0[0], bb0[1]);
                mma16816h(acc[1][1], ah1, bb0[2], bb0[3]);
                mma16816h(acc[1][2], ah1, bb1[0], bb1[1]);
                mma16816h(acc[1][3], ah1, bb1[2], bb1[3]);
                if (++bidx == 3) bidx = 0;
            }

            // spill partial accum (warp-private) to Gs plane kq
            float* G = Gs + kq * GS_PLANE;
#pragma unroll
            for (int m = 0; m < 2; m++)
#pragma unroll
                for (int nb = 0; nb < 4; nb++) {
                    int n = wn * 32 + nb * 8 + (lane & 3) * 2;
                    int mm = m * 16 + (lane >> 2);
                    G[mm * GS_PITCH + n]           = acc[m][nb][0];
                    G[mm * GS_PITCH + n + 1]       = acc[m][nb][1];
                    G[(mm + 8) * GS_PITCH + n]     = acc[m][nb][2];
                    G[(mm + 8) * GS_PITCH + n + 1] = acc[m][nb][3];
                }
            __syncthreads();
        }

        // fused gate pass: thread = (batch bB, unit pair up), 2 units each
        {
            size_t row = (size_t)bB * 512 + t;
            float pa[2][4];              // [item r][gate]
            if (t > 0) {
#pragma unroll
                for (int r = 0; r < 2; r++) {
                    int u = up * 2 + r;
#pragma unroll
                    for (int q = 0; q < 4; q++) {
                        float s = XGs[bB * 36 + q * 8 + u];
#pragma unroll
                        for (int k = 0; k < 4; k++)
                            s += Gs[k * GS_PLANE + (q * 8 + u) * GS_PITCH + bB];
                        pa[r][q] = s;
                    }
                }
            } else {
                const float* xr = xg + row * 4096 + j0 + up * 2;
#pragma unroll
                for (int r = 0; r < 2; r++) {
                    pa[r][0] = xr[r];
                    pa[r][1] = xr[1024 + r];
                    pa[r][2] = xr[2048 + r];
                    pa[r][3] = xr[3072 + r];
                }
            }

            float cna[2], soa[2];
#pragma unroll
            for (int r = 0; r < 2; r++) {
                float d0 = 1.0f + ex2a(fminf(-L1 * pa[r][0], 24.0f));
                float d1 = 1.0f + ex2a(fminf(-L1 * pa[r][1], 24.0f));
                float d2 = 1.0f + ex2a(fminf(-2.0f * L1 * pa[r][2], 24.0f));
                float d3 = 1.0f + ex2a(fminf(-L1 * pa[r][3], 24.0f));
                float p1 = d0 * d1, p2 = p1 * d2, p3 = p2 * d3;
                float inv = rcpa(p3);
                float invd3 = inv * p2;
                float invp2 = inv * d3;
                float invd2 = invp2 * p1;
                float invp1 = invp2 * d2;
                float invd1 = invp1 * d0;
                float invd0 = invp1 * d1;
                float si = invd0, sf = invd1, so = invd3;
                float tg = __fmaf_rn(2.0f, invd2, -1.0f);
                cna[r] = __fmaf_rn(sf, creg[r], si * tg);
                soa[r] = so;
            }
            float q0 = 1.0f + ex2a(fminf(-2.0f * L1 * cna[0], 24.0f));
            float q1 = 1.0f + ex2a(fminf(-2.0f * L1 * cna[1], 24.0f));
            float qq = q0 * q1;
            float iq = rcpa(qq);
            float ic0 = iq * q1;
            float ic1 = iq * q0;
            float hv0 = soa[0] * __fmaf_rn(2.0f, ic0, -1.0f);
            float hv1 = soa[1] * __fmaf_rn(2.0f, ic1, -1.0f);
            creg[0] = cna[0];
            creg[1] = cna[1];

            if (write_h)
                *(float2*)(hseq + row * 1024 + j0 + up * 2) = make_float2(hv0, hv1);
            *(__half2*)(h16 + row * 1024 + j0 + up * 2) = __halves2half2(
                __float2half_rn(hv0), __float2half_rn(hv1));
        }

        grid_barrier(LSTM_NBLK);
    }
}

// ===========================================================================
// Launch sequence (7 launches), graph-capturable, allocation-free.
// ===========================================================================
extern "C" void kernel_launch(void* const* d_in, const int* in_sizes, int n_in,
                              void* d_out, int out_size)
{
    const float* input = (const float*)d_in[0];
    const float* W_ih0 = (const float*)d_in[1];
    const float* W_hh0 = (const float*)d_in[2];
    const float* b_ih0 = (const float*)d_in[3];
    const float* b_hh0 = (const float*)d_in[4];
    const float* W_ih1 = (const float*)d_in[5];
    const float* W_hh1 = (const float*)d_in[6];
    const float* b_ih1 = (const float*)d_in[7];
    const float* b_hh1 = (const float*)d_in[8];
    const float* W_fc  = (const float*)d_in[9];
    const float* b_fc  = (const float*)d_in[10];
    float* out = (float*)d_out;

    float *xg, *h;
    __half *whh0hi, *whh0lo, *whh1hi, *whh1lo;
    __half *wih0hi, *wih0lo, *wih1hi, *wih1lo, *inhi, *inlo, *h16;
    cudaGetSymbolAddress((void**)&xg,     g_xg);
    cudaGetSymbolAddress((void**)&h,      g_h);
    cudaGetSymbolAddress((void**)&whh0hi, g_whh0_hi);
    cudaGetSymbolAddress((void**)&whh0lo, g_whh0_lo);
    cudaGetSymbolAddress((void**)&whh1hi, g_whh1_hi);
    cudaGetSymbolAddress((void**)&whh1lo, g_whh1_lo);
    cudaGetSymbolAddress((void**)&wih0hi, g_wih0_hi);
    cudaGetSymbolAddress((void**)&wih0lo, g_wih0_lo);
    cudaGetSymbolAddress((void**)&wih1hi, g_wih1_hi);
    cudaGetSymbolAddress((void**)&wih1lo, g_wih1_lo);
    cudaGetSymbolAddress((void**)&inhi,   g_in_hi);
    cudaGetSymbolAddress((void**)&inlo,   g_in_lo);
    cudaGetSymbolAddress((void**)&h16,    g_h16);

    cudaFuncSetAttribute(gemm_tc,  cudaFuncAttributeMaxDynamicSharedMemorySize, GT_SMEM);
    cudaFuncSetAttribute(lstm_mma, cudaFuncAttributeMaxDynamicSharedMemorySize, LS_SMEM);

    // #1: all prep splits fused
    split_all<<<12544, 256>>>(input, W_ih0, W_hh0, W_hh1,
                              inhi, inlo, wih0hi, wih0lo,
                              whh0hi, whh0lo, whh1hi, whh1lo);
    // #2: xg0 = x16 @ W_ih0_16^T + biases (K=64, single-pass)
    {
        dim3 g(4096 / 128, 65536 / 128);
        gemm_tc<<<g, 256, GT_SMEM>>>(inhi, wih0hi, b_ih0, b_hh0, xg, 4096, 64);
    }
    // #3: W_ih1 split
    split_plane_h<<<4096, 256>>>(W_ih1, wih1hi, wih1lo);
    // #4: layer-0 recurrence (single-pass fp16 W; no hseq stores)
    lstm_mma<<<LSTM_NBLK, 512, LS_SMEM>>>(xg, h, whh0hi, h16, 0);
    // #5: xg1 = h16 @ W_ih1_16^T + biases (K=1024, single-pass)
    {
        dim3 g(4096 / 128, 65536 / 128);
        gemm_tc<<<g, 256, GT_SMEM>>>(h16, wih1hi, b_ih1, b_hh1, xg, 4096, 1024);
    }
    // #6: layer-1 recurrence (writes hseq for FC)
    lstm_mma<<<LSTM_NBLK, 512, LS_SMEM>>>(xg, h, whh1hi, h16, 1);
    // #7: FC
    dim3 gf(1, 512);
    gemm_bias<<<gf, 256>>>(h, W_fc, b_fc, nullptr, out, 64, 1024);
}